// round 1
// baseline (speedup 1.0000x reference)
#include <cuda_runtime.h>
#include <math.h>
#include <stddef.h>

// ---------------- problem constants ----------------
#define BATCH 4
#define SQL   1024
#define SKV   1024
#define DIM   1024
#define NH    16
#define DH    64
#define NEXP  8
#define HDIM  4096              // 4*DIM
#define NTOK  (BATCH*SQL)       // 4096
#define BH    (BATCH*NH)        // 64
#define OUT_MAIN (NTOK*DIM)     // 4194304
#define THRESH 0.05f
#define COEF   0.01f

// ---------------- static device scratch ----------------
__device__ float g_q [NTOK*DIM];
__device__ float g_k [NTOK*DIM];
__device__ float g_v [NTOK*DIM];
__device__ float g_qh[NTOK*DIM];
__device__ float g_kh[NTOK*DIM];
__device__ float g_vh[NTOK*DIM];
__device__ float g_qt[NTOK*DIM];
__device__ float g_kt[NTOK*DIM];
__device__ float g_vt[NTOK*DIM];
__device__ float g_sc[(size_t)BH*SQL*SKV];      // 256 MB
__device__ float g_ot[NTOK*DIM];
__device__ float g_o [NTOK*DIM];
__device__ float g_op[NTOK*DIM];
__device__ float g_a [NTOK*DIM];
__device__ float g_x [NTOK*DIM];
__device__ float g_y [NTOK*DIM];
__device__ float g_h [(size_t)NEXP*NTOK*HDIM];  // 512 MB
__device__ int   g_cnt[NEXP];
__device__ float g_sumP[NEXP];
__device__ int   g_tok[NEXP*NTOK];
__device__ float g_gate[NEXP*NTOK];

// ---------------- helpers ----------------
__device__ __forceinline__ float blk_reduce_sum(float v, float* sm) {
    int lane = threadIdx.x & 31, w = threadIdx.x >> 5;
    #pragma unroll
    for (int o = 16; o; o >>= 1) v += __shfl_down_sync(0xffffffffu, v, o);
    if (!lane) sm[w] = v;
    __syncthreads();
    if (threadIdx.x < 32) {
        v = (threadIdx.x < 8) ? sm[threadIdx.x] : 0.f;
        #pragma unroll
        for (int o = 4; o; o >>= 1) v += __shfl_down_sync(0xffffffffu, v, o);
        if (!threadIdx.x) sm[0] = v;
    }
    __syncthreads();
    float r = sm[0];
    __syncthreads();
    return r;
}

__device__ __forceinline__ float blk_reduce_max(float v, float* sm) {
    int lane = threadIdx.x & 31, w = threadIdx.x >> 5;
    #pragma unroll
    for (int o = 16; o; o >>= 1) v = fmaxf(v, __shfl_down_sync(0xffffffffu, v, o));
    if (!lane) sm[w] = v;
    __syncthreads();
    if (threadIdx.x < 32) {
        v = (threadIdx.x < 8) ? sm[threadIdx.x] : -1e30f;
        #pragma unroll
        for (int o = 4; o; o >>= 1) v = fmaxf(v, __shfl_down_sync(0xffffffffu, v, o));
        if (!threadIdx.x) sm[0] = v;
    }
    __syncthreads();
    float r = sm[0];
    __syncthreads();
    return r;
}

__device__ __forceinline__ float gelu_exact(float v) {
    return 0.5f * v * (1.0f + erff(v * 0.70710678118654752f));
}

// ---------------- generic 64x64x16 SGEMM ----------------
// C[z] = alpha * A[z] @ op(B[z]) + bias   (op = B^T if TRANSB)
// M, N multiples of 64; K multiple of 16. 256 threads, 4x4 per thread.
template<bool TRANSB>
__global__ void gemm64(const float* __restrict__ A, const float* __restrict__ B,
                       float* __restrict__ C, int K,
                       int lda, int ldb, int ldc,
                       long long As, long long Bs, long long Cs,
                       const float* __restrict__ bias, float alpha)
{
    A += (long long)blockIdx.z * As;
    B += (long long)blockIdx.z * Bs;
    C += (long long)blockIdx.z * Cs;
    const int m0 = blockIdx.y << 6, n0 = blockIdx.x << 6;
    __shared__ __align__(16) float Asm[16][64];
    __shared__ __align__(16) float Bsm[16][64];
    float acc[4][4] = {};
    const int t  = threadIdx.x;
    const int tx = t & 15, ty = t >> 4;
    const int ar = t >> 2, ac = (t & 3) << 2;

    for (int k0 = 0; k0 < K; k0 += 16) {
        float4 av = *(const float4*)(A + (size_t)(m0 + ar) * lda + k0 + ac);
        Asm[ac + 0][ar] = av.x; Asm[ac + 1][ar] = av.y;
        Asm[ac + 2][ar] = av.z; Asm[ac + 3][ar] = av.w;
        if (TRANSB) {
            float4 bv = *(const float4*)(B + (size_t)(n0 + ar) * ldb + k0 + ac);
            Bsm[ac + 0][ar] = bv.x; Bsm[ac + 1][ar] = bv.y;
            Bsm[ac + 2][ar] = bv.z; Bsm[ac + 3][ar] = bv.w;
        } else {
            int bk = t >> 4, bn = (t & 15) << 2;
            *(float4*)&Bsm[bk][bn] = *(const float4*)(B + (size_t)(k0 + bk) * ldb + n0 + bn);
        }
        __syncthreads();
        #pragma unroll
        for (int kk = 0; kk < 16; kk++) {
            float4 a4 = *(const float4*)&Asm[kk][ty << 2];
            float4 b4 = *(const float4*)&Bsm[kk][tx << 2];
            float aa[4] = {a4.x, a4.y, a4.z, a4.w};
            float bb[4] = {b4.x, b4.y, b4.z, b4.w};
            #pragma unroll
            for (int i = 0; i < 4; i++)
                #pragma unroll
                for (int j = 0; j < 4; j++)
                    acc[i][j] += aa[i] * bb[j];
        }
        __syncthreads();
    }
    #pragma unroll
    for (int i = 0; i < 4; i++) {
        int mm = m0 + (ty << 2) + i;
        #pragma unroll
        for (int j = 0; j < 4; j++) {
            int nn = n0 + (tx << 2) + j;
            float v = acc[i][j] * alpha;
            if (bias) v += bias[nn];
            C[(size_t)mm * ldc + nn] = v;
        }
    }
}

// ---------------- MoE expert GEMM 1: h = gelu(gather(x) @ ew1[e] + eb1[e]) ----------------
__global__ void moe_gemm1(const float* __restrict__ ew1, const float* __restrict__ eb1)
{
    const int e = blockIdx.z;
    const int cnt = g_cnt[e];
    const int m0 = blockIdx.y << 6;
    if (m0 >= cnt) return;
    const int n0 = blockIdx.x << 6;
    const float* B = ew1 + (size_t)e * DIM * HDIM;
    __shared__ __align__(16) float Asm[16][64];
    __shared__ __align__(16) float Bsm[16][64];
    float acc[4][4] = {};
    const int t  = threadIdx.x;
    const int tx = t & 15, ty = t >> 4;
    const int ar = t >> 2, ac = (t & 3) << 2;
    const int gm = m0 + ar;
    const int tok = (gm < cnt) ? g_tok[e * NTOK + gm] : g_tok[e * NTOK];
    const float* Arow = g_x + (size_t)tok * DIM;

    for (int k0 = 0; k0 < DIM; k0 += 16) {
        float4 av = *(const float4*)(Arow + k0 + ac);
        Asm[ac + 0][ar] = av.x; Asm[ac + 1][ar] = av.y;
        Asm[ac + 2][ar] = av.z; Asm[ac + 3][ar] = av.w;
        int bk = t >> 4, bn = (t & 15) << 2;
        *(float4*)&Bsm[bk][bn] = *(const float4*)(B + (size_t)(k0 + bk) * HDIM + n0 + bn);
        __syncthreads();
        #pragma unroll
        for (int kk = 0; kk < 16; kk++) {
            float4 a4 = *(const float4*)&Asm[kk][ty << 2];
            float4 b4 = *(const float4*)&Bsm[kk][tx << 2];
            float aa[4] = {a4.x, a4.y, a4.z, a4.w};
            float bb[4] = {b4.x, b4.y, b4.z, b4.w};
            #pragma unroll
            for (int i = 0; i < 4; i++)
                #pragma unroll
                for (int j = 0; j < 4; j++)
                    acc[i][j] += aa[i] * bb[j];
        }
        __syncthreads();
    }
    #pragma unroll
    for (int i = 0; i < 4; i++) {
        int mm = m0 + (ty << 2) + i;
        #pragma unroll
        for (int j = 0; j < 4; j++) {
            int nn = n0 + (tx << 2) + j;
            float v = acc[i][j] + eb1[e * HDIM + nn];
            g_h[((size_t)e * NTOK + mm) * HDIM + nn] = gelu_exact(v);
        }
    }
}

// ---------------- MoE expert GEMM 2: y[tok] += gate * (h @ ew2[e] + eb2[e]) ----------------
__global__ void moe_gemm2(const float* __restrict__ ew2, const float* __restrict__ eb2)
{
    const int e = blockIdx.z;
    const int cnt = g_cnt[e];
    const int m0 = blockIdx.y << 6;
    if (m0 >= cnt) return;
    const int n0 = blockIdx.x << 6;
    const float* A = g_h + (size_t)e * NTOK * HDIM;
    const float* B = ew2 + (size_t)e * HDIM * DIM;
    __shared__ __align__(16) float Asm[16][64];
    __shared__ __align__(16) float Bsm[16][64];
    float acc[4][4] = {};
    const int t  = threadIdx.x;
    const int tx = t & 15, ty = t >> 4;
    const int ar = t >> 2, ac = (t & 3) << 2;

    for (int k0 = 0; k0 < HDIM; k0 += 16) {
        float4 av = *(const float4*)(A + (size_t)(m0 + ar) * HDIM + k0 + ac);
        Asm[ac + 0][ar] = av.x; Asm[ac + 1][ar] = av.y;
        Asm[ac + 2][ar] = av.z; Asm[ac + 3][ar] = av.w;
        int bk = t >> 4, bn = (t & 15) << 2;
        *(float4*)&Bsm[bk][bn] = *(const float4*)(B + (size_t)(k0 + bk) * DIM + n0 + bn);
        __syncthreads();
        #pragma unroll
        for (int kk = 0; kk < 16; kk++) {
            float4 a4 = *(const float4*)&Asm[kk][ty << 2];
            float4 b4 = *(const float4*)&Bsm[kk][tx << 2];
            float aa[4] = {a4.x, a4.y, a4.z, a4.w};
            float bb[4] = {b4.x, b4.y, b4.z, b4.w};
            #pragma unroll
            for (int i = 0; i < 4; i++)
                #pragma unroll
                for (int j = 0; j < 4; j++)
                    acc[i][j] += aa[i] * bb[j];
        }
        __syncthreads();
    }
    #pragma unroll
    for (int i = 0; i < 4; i++) {
        int gm = m0 + (ty << 2) + i;
        if (gm < cnt) {
            int   tok = g_tok[e * NTOK + gm];
            float gte = g_gate[e * NTOK + gm];
            #pragma unroll
            for (int j = 0; j < 4; j++) {
                int nn = n0 + (tx << 2) + j;
                float v = acc[i][j] + eb2[e * DIM + nn];
                atomicAdd(&g_y[(size_t)tok * DIM + nn], gte * v);
            }
        }
    }
}

// ---------------- head split/merge ----------------
__global__ void head_split(const float* __restrict__ in, float* __restrict__ out) {
    for (int i = blockIdx.x * blockDim.x + threadIdx.x; i < NTOK * DIM;
         i += gridDim.x * blockDim.x) {
        int d = i & 63, s = (i >> 6) & 1023, h = (i >> 16) & 15, b = i >> 20;
        out[i] = in[(size_t)((b << 10) + s) * DIM + (h << 6) + d];
    }
}
__global__ void head_merge(const float* __restrict__ in, float* __restrict__ out) {
    for (int i = blockIdx.x * blockDim.x + threadIdx.x; i < NTOK * DIM;
         i += gridDim.x * blockDim.x) {
        int col = i & 1023, h = col >> 6, d = col & 63;
        int s = (i >> 10) & 1023, b = i >> 20;
        out[i] = in[(size_t)(((b << 4) + h) * 1024 + s) * 64 + d];
    }
}

// ---------------- softmax over score rows (in place) ----------------
__global__ void softmax_rows() {
    float* r = g_sc + ((size_t)blockIdx.y * SQL + blockIdx.x) * SKV;
    __shared__ float sm[32];
    int t = threadIdx.x;
    float v[4];
    float mx = -1e30f;
    #pragma unroll
    for (int j = 0; j < 4; j++) { v[j] = r[t + j * 256]; mx = fmaxf(mx, v[j]); }
    mx = blk_reduce_max(mx, sm);
    float s = 0.f;
    #pragma unroll
    for (int j = 0; j < 4; j++) { v[j] = __expf(v[j] - mx); s += v[j]; }
    s = blk_reduce_sum(s, sm);
    float inv = 1.f / s;
    #pragma unroll
    for (int j = 0; j < 4; j++) r[t + j * 256] = v[j] * inv;
}

// ---------------- LayerNorm (optional residual, optional second output) ----------------
__global__ void ln_res(const float* __restrict__ a, const float* __restrict__ res,
                       const float* __restrict__ g, const float* __restrict__ b,
                       float* __restrict__ out1, float* __restrict__ out2)
{
    __shared__ float sm[32];
    const size_t base = (size_t)blockIdx.x * DIM;
    int t = threadIdx.x;
    float v[4];
    float s = 0.f;
    #pragma unroll
    for (int j = 0; j < 4; j++) {
        int c = t + j * 256;
        v[j] = a[base + c] + (res ? res[base + c] : 0.f);
        s += v[j];
    }
    s = blk_reduce_sum(s, sm);
    float mean = s * (1.0f / DIM);
    float s2 = 0.f;
    #pragma unroll
    for (int j = 0; j < 4; j++) { float d = v[j] - mean; s2 += d * d; }
    s2 = blk_reduce_sum(s2, sm);
    float rs = rsqrtf(s2 * (1.0f / DIM) + 1e-5f);
    #pragma unroll
    for (int j = 0; j < 4; j++) {
        int c = t + j * 256;
        float o = (v[j] - mean) * rs * g[c] + b[c];
        out1[base + c] = o;
        if (out2) out2[base + c] = o;
    }
}

// ---------------- gating: softmax over 8 experts, top-3 + threshold ----------------
__global__ void gating(const float* __restrict__ Wg) {
    __shared__ float logits[NEXP];
    const int tok = blockIdx.x;
    const float* xr = g_x + (size_t)tok * DIM;
    int w = threadIdx.x >> 5, lane = threadIdx.x & 31;
    float s = 0.f;
    for (int i = lane; i < DIM; i += 32) s += xr[i] * Wg[i * NEXP + w];
    #pragma unroll
    for (int o = 16; o; o >>= 1) s += __shfl_down_sync(0xffffffffu, s, o);
    if (!lane) logits[w] = s;
    __syncthreads();
    if (threadIdx.x == 0) {
        float p[NEXP];
        float mx = -1e30f;
        for (int e = 0; e < NEXP; e++) mx = fmaxf(mx, logits[e]);
        float sum = 0.f;
        for (int e = 0; e < NEXP; e++) { p[e] = __expf(logits[e] - mx); sum += p[e]; }
        float inv = 1.f / sum;
        for (int e = 0; e < NEXP; e++) p[e] *= inv;
        // top-3 (ties -> lowest index, matching lax.top_k)
        int i0 = 0;
        for (int e = 1; e < NEXP; e++) if (p[e] > p[i0]) i0 = e;
        int i1 = -1;
        for (int e = 0; e < NEXP; e++) if (e != i0 && (i1 < 0 || p[e] > p[i1])) i1 = e;
        int i2 = -1;
        for (int e = 0; e < NEXP; e++) if (e != i0 && e != i1 && (i2 < 0 || p[e] > p[i2])) i2 = e;
        float gA = p[i0];
        float gB = (p[i1] >= THRESH) ? p[i1] : 0.f;
        float gC = (p[i2] >= THRESH) ? p[i2] : 0.f;
        int   ids[3] = { i0, i1, i2 };
        float gts[3] = { gA, gB, gC };
        #pragma unroll
        for (int j = 0; j < 3; j++) {
            if (gts[j] > 0.f) {
                int slot = atomicAdd(&g_cnt[ids[j]], 1);
                g_tok [ids[j] * NTOK + slot] = tok;
                g_gate[ids[j] * NTOK + slot] = gts[j];
            }
        }
        for (int e = 0; e < NEXP; e++) atomicAdd(&g_sumP[e], p[e]);
    }
}

// ---------------- small utility kernels ----------------
__global__ void zero_small() {
    int t = threadIdx.x;
    if (t < NEXP) { g_cnt[t] = 0; g_sumP[t] = 0.f; }
}
__global__ void aux_kernel(float* __restrict__ out, int out_size) {
    if (out_size <= OUT_MAIN) return;
    float a = 0.f;
    for (int e = 0; e < NEXP; e++)
        a += ((float)g_cnt[e] / (float)NTOK) * (g_sumP[e] / (float)NTOK);
    out[OUT_MAIN] = COEF * (float)NEXP * a;
}

// ---------------- host launcher ----------------
extern "C" void kernel_launch(void* const* d_in, const int* in_sizes, int n_in,
                              void* d_out, int out_size)
{
    const float* query  = (const float*)d_in[0];
    const float* keyval = (const float*)d_in[1];
    const float* Wq = (const float*)d_in[2];  const float* bq = (const float*)d_in[3];
    const float* Wk = (const float*)d_in[4];  const float* bk = (const float*)d_in[5];
    const float* Wv = (const float*)d_in[6];  const float* bv = (const float*)d_in[7];
    const float* W_in  = (const float*)d_in[8];  const float* b_in  = (const float*)d_in[9];
    const float* W_out = (const float*)d_in[10]; const float* b_out = (const float*)d_in[11];
    const float* Wa = (const float*)d_in[12]; const float* ba = (const float*)d_in[13];
    const float* ln1g = (const float*)d_in[14]; const float* ln1b = (const float*)d_in[15];
    const float* Wg = (const float*)d_in[16];
    const float* ew1 = (const float*)d_in[17]; const float* eb1 = (const float*)d_in[18];
    const float* ew2 = (const float*)d_in[19]; const float* eb2 = (const float*)d_in[20];
    const float* ln2g = (const float*)d_in[21]; const float* ln2b = (const float*)d_in[22];
    float* out = (float*)d_out;

    float *q, *k, *v, *qh, *kh, *vh, *qt, *kt, *vt, *sc, *ot, *o, *op, *a, *x, *y;
    cudaGetSymbolAddress((void**)&q,  g_q);
    cudaGetSymbolAddress((void**)&k,  g_k);
    cudaGetSymbolAddress((void**)&v,  g_v);
    cudaGetSymbolAddress((void**)&qh, g_qh);
    cudaGetSymbolAddress((void**)&kh, g_kh);
    cudaGetSymbolAddress((void**)&vh, g_vh);
    cudaGetSymbolAddress((void**)&qt, g_qt);
    cudaGetSymbolAddress((void**)&kt, g_kt);
    cudaGetSymbolAddress((void**)&vt, g_vt);
    cudaGetSymbolAddress((void**)&sc, g_sc);
    cudaGetSymbolAddress((void**)&ot, g_ot);
    cudaGetSymbolAddress((void**)&o,  g_o);
    cudaGetSymbolAddress((void**)&op, g_op);
    cudaGetSymbolAddress((void**)&a,  g_a);
    cudaGetSymbolAddress((void**)&x,  g_x);
    cudaGetSymbolAddress((void**)&y,  g_y);

    const dim3 THR(256);
    const dim3 GLIN(DIM / 64, NTOK / 64, 1);          // 4096x1024 linears

    zero_small<<<1, 32>>>();

    // outer Q/K/V linears: x @ W^T + b
    gemm64<true><<<GLIN, THR>>>(query,  Wq, q, DIM, DIM, DIM, DIM, 0, 0, 0, bq, 1.f);
    gemm64<true><<<GLIN, THR>>>(keyval, Wk, k, DIM, DIM, DIM, DIM, 0, 0, 0, bk, 1.f);
    gemm64<true><<<GLIN, THR>>>(keyval, Wv, v, DIM, DIM, DIM, DIM, 0, 0, 0, bv, 1.f);

    // MHA in-projection
    gemm64<true><<<GLIN, THR>>>(q, W_in,               qh, DIM, DIM, DIM, DIM, 0, 0, 0, b_in,           1.f);
    gemm64<true><<<GLIN, THR>>>(k, W_in + DIM * DIM,   kh, DIM, DIM, DIM, DIM, 0, 0, 0, b_in + DIM,     1.f);
    gemm64<true><<<GLIN, THR>>>(v, W_in + 2 * DIM * DIM, vh, DIM, DIM, DIM, DIM, 0, 0, 0, b_in + 2 * DIM, 1.f);

    // [B,S,H,dh] -> [B,H,S,dh]
    head_split<<<512, 256>>>(qh, qt);
    head_split<<<512, 256>>>(kh, kt);
    head_split<<<512, 256>>>(vh, vt);

    // scores = (Q @ K^T) / 8, batched over B*H
    gemm64<true><<<dim3(SKV / 64, SQL / 64, BH), THR>>>(
        qt, kt, sc, DH, DH, DH, SKV,
        (long long)SQL * DH, (long long)SKV * DH, (long long)SQL * SKV,
        nullptr, 0.125f);

    softmax_rows<<<dim3(SQL, BH), THR>>>();

    // O = attn @ V, batched
    gemm64<false><<<dim3(1, SQL / 64, BH), THR>>>(
        sc, vt, ot, SKV, SKV, DH, DH,
        (long long)SQL * SKV, (long long)SKV * DH, (long long)SQL * DH,
        nullptr, 1.f);

    head_merge<<<512, 256>>>(ot, o);

    // out-projection + adapter
    gemm64<true><<<GLIN, THR>>>(o,  W_out, op, DIM, DIM, DIM, DIM, 0, 0, 0, b_out, 1.f);
    gemm64<true><<<GLIN, THR>>>(op, Wa,    a,  DIM, DIM, DIM, DIM, 0, 0, 0, ba,    1.f);

    // x = LN1(a + query); y = x (residual accumulator for MoE)
    ln_res<<<NTOK, THR>>>(a, query, ln1g, ln1b, x, y);

    // gating -> per-expert token lists + aux accumulators
    gating<<<NTOK, THR>>>(Wg);

    // expert FFNs (gathered rows; grid covers max count, early-exit on cnt)
    moe_gemm1<<<dim3(HDIM / 64, NTOK / 64, NEXP), THR>>>(ew1, eb1);
    moe_gemm2<<<dim3(DIM / 64,  NTOK / 64, NEXP), THR>>>(ew2, eb2);

    // final LN -> output, then aux scalar
    ln_res<<<NTOK, THR>>>(y, nullptr, ln2g, ln2b, out, nullptr);
    aux_kernel<<<1, 1>>>(out, out_size);
}

// round 6
// speedup vs baseline: 1.1744x; 1.1744x over previous
#include <cuda_runtime.h>
#include <math.h>
#include <stddef.h>

// ---------------- problem constants ----------------
#define BATCH 4
#define SQL   1024
#define SKV   1024
#define DIM   1024
#define NH    16
#define DH    64
#define NEXP  8
#define HDIM  4096              // 4*DIM
#define NTOK  (BATCH*SQL)       // 4096
#define BH    (BATCH*NH)        // 64
#define OUT_MAIN (NTOK*DIM)     // 4194304
#define THRESH 0.05f
#define COEF   0.01f

// ---------------- static device scratch ----------------
__device__ float g_q [NTOK*DIM];
__device__ float g_k [NTOK*DIM];
__device__ float g_v [NTOK*DIM];
__device__ float g_qh[NTOK*DIM];
__device__ float g_kh[NTOK*DIM];
__device__ float g_vh[NTOK*DIM];
__device__ float g_qt[NTOK*DIM];
__device__ float g_kt[NTOK*DIM];
__device__ float g_vt[NTOK*DIM];
__device__ float g_sc[(size_t)BH*SQL*SKV];      // 256 MB
__device__ float g_ot[NTOK*DIM];
__device__ float g_o [NTOK*DIM];
__device__ float g_op[NTOK*DIM];
__device__ float g_a [NTOK*DIM];
__device__ float g_x [NTOK*DIM];
__device__ float g_h [(size_t)NEXP*NTOK*HDIM];  // 512 MB
__device__ float g_e2[(size_t)NEXP*NTOK*DIM];   // 128 MB (dense expert outputs)
__device__ int   g_cnt[NEXP];
__device__ int   g_tok[NEXP*NTOK];
__device__ float g_probs[NTOK*NEXP];
__device__ int   g_tcnt[NTOK];
__device__ int   g_te  [NTOK*3];
__device__ int   g_tslot[NTOK*3];
__device__ float g_tgate[NTOK*3];

// ---------------- helpers ----------------
__device__ __forceinline__ float blk_reduce_sum(float v, float* sm) {
    int lane = threadIdx.x & 31, w = threadIdx.x >> 5;
    #pragma unroll
    for (int o = 16; o; o >>= 1) v += __shfl_down_sync(0xffffffffu, v, o);
    if (!lane) sm[w] = v;
    __syncthreads();
    if (threadIdx.x < 32) {
        v = (threadIdx.x < 8) ? sm[threadIdx.x] : 0.f;
        #pragma unroll
        for (int o = 4; o; o >>= 1) v += __shfl_down_sync(0xffffffffu, v, o);
        if (!threadIdx.x) sm[0] = v;
    }
    __syncthreads();
    float r = sm[0];
    __syncthreads();
    return r;
}

__device__ __forceinline__ float blk_reduce_max(float v, float* sm) {
    int lane = threadIdx.x & 31, w = threadIdx.x >> 5;
    #pragma unroll
    for (int o = 16; o; o >>= 1) v = fmaxf(v, __shfl_down_sync(0xffffffffu, v, o));
    if (!lane) sm[w] = v;
    __syncthreads();
    if (threadIdx.x < 32) {
        v = (threadIdx.x < 8) ? sm[threadIdx.x] : -1e30f;
        #pragma unroll
        for (int o = 4; o; o >>= 1) v = fmaxf(v, __shfl_down_sync(0xffffffffu, v, o));
        if (!threadIdx.x) sm[0] = v;
    }
    __syncthreads();
    float r = sm[0];
    __syncthreads();
    return r;
}

__device__ __forceinline__ float gelu_exact(float v) {
    return 0.5f * v * (1.0f + erff(v * 0.70710678118654752f));
}

// ================= 128x(BN)x8 SGEMM, 8x(BN/16) per thread, double-buffered =================
// C[z] = alpha * A[z] @ op(B[z]) + bias    (op = B^T if TRANSB)
// M multiple of 128, N multiple of BN, K multiple of 8.
template<int BN, bool TRANSB>
__global__ __launch_bounds__(256, 2)
void gemm128(const float* __restrict__ A, const float* __restrict__ B,
             float* __restrict__ C, int K, int lda, int ldb, int ldc,
             long long As, long long Bs, long long Cs,
             const float* __restrict__ bias, float alpha)
{
    constexpr int TN = BN / 16;
    A += (long long)blockIdx.z * As;
    B += (long long)blockIdx.z * Bs;
    C += (long long)blockIdx.z * Cs;
    const int m0 = blockIdx.y << 7, n0 = blockIdx.x * BN;
    __shared__ __align__(16) float Asm[2][8][128];
    __shared__ __align__(16) float Bsm[2][8][BN];

    const int t = threadIdx.x, tx = t & 15, ty = t >> 4;
    // A tile loader: 128 rows x 8 k, one float4/thread
    const int arow = t >> 1, acol = (t & 1) << 2;
    const float* gA = A + (size_t)(m0 + arow) * lda + acol;
    // B tile loader
    int bk, bn; bool bact;
    if (TRANSB) { bk = (t & 1) << 2; bn = t >> 1; bact = (bn < BN); }
    else if (BN == 128) { bk = t >> 5; bn = (t & 31) << 2; bact = true; }
    else { bk = t >> 4; bn = (t & 15) << 2; bact = (t < 128); }
    const float* gB = TRANSB ? B + (size_t)(n0 + (bact ? bn : 0)) * ldb + bk
                             : B + (size_t)bk * ldb + n0 + bn;

    float4 aR = *(const float4*)gA;
    float4 bR = bact ? *(const float4*)gB : make_float4(0.f, 0.f, 0.f, 0.f);

    float acc[8][TN];
    #pragma unroll
    for (int i = 0; i < 8; i++)
        #pragma unroll
        for (int j = 0; j < TN; j++) acc[i][j] = 0.f;

    int buf = 0;
    for (int k0 = 0; k0 < K; k0 += 8) {
        Asm[buf][acol + 0][arow] = aR.x;
        Asm[buf][acol + 1][arow] = aR.y;
        Asm[buf][acol + 2][arow] = aR.z;
        Asm[buf][acol + 3][arow] = aR.w;
        if (TRANSB) {
            if (bact) {
                Bsm[buf][bk + 0][bn] = bR.x;
                Bsm[buf][bk + 1][bn] = bR.y;
                Bsm[buf][bk + 2][bn] = bR.z;
                Bsm[buf][bk + 3][bn] = bR.w;
            }
        } else {
            if (bact) *(float4*)&Bsm[buf][bk][bn] = bR;
        }
        __syncthreads();
        if (k0 + 8 < K) {
            gA += 8;
            aR = *(const float4*)gA;
            if (TRANSB) gB += 8; else gB += (size_t)8 * ldb;
            if (bact) bR = *(const float4*)gB;
        }
        #pragma unroll
        for (int kk = 0; kk < 8; kk++) {
            float a8[8], b8[TN];
            *(float4*)(a8)     = *(const float4*)&Asm[buf][kk][ty << 3];
            *(float4*)(a8 + 4) = *(const float4*)&Asm[buf][kk][(ty << 3) + 4];
            *(float4*)(b8)     = *(const float4*)&Bsm[buf][kk][tx * TN];
            if (TN == 8) *(float4*)(b8 + 4) = *(const float4*)&Bsm[buf][kk][tx * TN + 4];
            #pragma unroll
            for (int i = 0; i < 8; i++)
                #pragma unroll
                for (int j = 0; j < TN; j++)
                    acc[i][j] += a8[i] * b8[j];
        }
        buf ^= 1;
    }
    #pragma unroll
    for (int i = 0; i < 8; i++) {
        int mm = m0 + (ty << 3) + i;
        #pragma unroll
        for (int j = 0; j < TN; j++) {
            int nn = n0 + tx * TN + j;
            float v = acc[i][j] * alpha;
            if (bias) v += bias[nn];
            C[(size_t)mm * ldc + nn] = v;
        }
    }
}

// ================= MoE GEMM 1: h = gelu(gather(x) @ ew1[e] + eb1[e]) =================
__global__ __launch_bounds__(256, 2)
void moe_gemm1(const float* __restrict__ ew1, const float* __restrict__ eb1)
{
    const int e = blockIdx.z;
    const int cnt = g_cnt[e];
    const int m0 = blockIdx.y << 7;
    if (m0 >= cnt) return;
    const int n0 = blockIdx.x << 7;
    const float* B = ew1 + (size_t)e * DIM * HDIM;
    __shared__ __align__(16) float Asm[2][8][128];
    __shared__ __align__(16) float Bsm[2][8][128];
    const int t = threadIdx.x, tx = t & 15, ty = t >> 4;
    const int arow = t >> 1, acol = (t & 1) << 2;
    const int gm = m0 + arow;
    const int tok = g_tok[e * NTOK + (gm < cnt ? gm : cnt - 1)];
    const float* gA = g_x + (size_t)tok * DIM + acol;
    const int bk = t >> 5, bn = (t & 31) << 2;
    const float* gB = B + (size_t)bk * HDIM + n0 + bn;

    float4 aR = *(const float4*)gA;
    float4 bR = *(const float4*)gB;
    float acc[8][8];
    #pragma unroll
    for (int i = 0; i < 8; i++)
        #pragma unroll
        for (int j = 0; j < 8; j++) acc[i][j] = 0.f;

    int buf = 0;
    for (int k0 = 0; k0 < DIM; k0 += 8) {
        Asm[buf][acol + 0][arow] = aR.x;
        Asm[buf][acol + 1][arow] = aR.y;
        Asm[buf][acol + 2][arow] = aR.z;
        Asm[buf][acol + 3][arow] = aR.w;
        *(float4*)&Bsm[buf][bk][bn] = bR;
        __syncthreads();
        if (k0 + 8 < DIM) {
            gA += 8;            aR = *(const float4*)gA;
            gB += (size_t)8 * HDIM; bR = *(const float4*)gB;
        }
        #pragma unroll
        for (int kk = 0; kk < 8; kk++) {
            float a8[8], b8[8];
            *(float4*)(a8)     = *(const float4*)&Asm[buf][kk][ty << 3];
            *(float4*)(a8 + 4) = *(const float4*)&Asm[buf][kk][(ty << 3) + 4];
            *(float4*)(b8)     = *(const float4*)&Bsm[buf][kk][tx << 3];
            *(float4*)(b8 + 4) = *(const float4*)&Bsm[buf][kk][(tx << 3) + 4];
            #pragma unroll
            for (int i = 0; i < 8; i++)
                #pragma unroll
                for (int j = 0; j < 8; j++)
                    acc[i][j] += a8[i] * b8[j];
        }
        buf ^= 1;
    }
    #pragma unroll
    for (int i = 0; i < 8; i++) {
        int mm = m0 + (ty << 3) + i;
        #pragma unroll
        for (int j = 0; j < 8; j++) {
            int nn = n0 + (tx << 3) + j;
            g_h[((size_t)e * NTOK + mm) * HDIM + nn] =
                gelu_exact(acc[i][j] + eb1[e * HDIM + nn]);
        }
    }
}

// ================= MoE GEMM 2: e2[e][slot] = h[e][slot] @ ew2[e] + eb2[e] =================
__global__ __launch_bounds__(256, 2)
void moe_gemm2(const float* __restrict__ ew2, const float* __restrict__ eb2)
{
    const int e = blockIdx.z;
    const int cnt = g_cnt[e];
    const int m0 = blockIdx.y << 7;
    if (m0 >= cnt) return;
    const int n0 = blockIdx.x << 7;
    const float* A = g_h + (size_t)e * NTOK * HDIM;
    const float* B = ew2 + (size_t)e * HDIM * DIM;
    __shared__ __align__(16) float Asm[2][8][128];
    __shared__ __align__(16) float Bsm[2][8][128];
    const int t = threadIdx.x, tx = t & 15, ty = t >> 4;
    const int arow = t >> 1, acol = (t & 1) << 2;
    const float* gA = A + (size_t)(m0 + arow) * HDIM + acol;
    const int bk = t >> 5, bn = (t & 31) << 2;
    const float* gB = B + (size_t)bk * DIM + n0 + bn;

    float4 aR = *(const float4*)gA;
    float4 bR = *(const float4*)gB;
    float acc[8][8];
    #pragma unroll
    for (int i = 0; i < 8; i++)
        #pragma unroll
        for (int j = 0; j < 8; j++) acc[i][j] = 0.f;

    int buf = 0;
    for (int k0 = 0; k0 < HDIM; k0 += 8) {
        Asm[buf][acol + 0][arow] = aR.x;
        Asm[buf][acol + 1][arow] = aR.y;
        Asm[buf][acol + 2][arow] = aR.z;
        Asm[buf][acol + 3][arow] = aR.w;
        *(float4*)&Bsm[buf][bk][bn] = bR;
        __syncthreads();
        if (k0 + 8 < HDIM) {
            gA += 8;            aR = *(const float4*)gA;
            gB += (size_t)8 * DIM; bR = *(const float4*)gB;
        }
        #pragma unroll
        for (int kk = 0; kk < 8; kk++) {
            float a8[8], b8[8];
            *(float4*)(a8)     = *(const float4*)&Asm[buf][kk][ty << 3];
            *(float4*)(a8 + 4) = *(const float4*)&Asm[buf][kk][(ty << 3) + 4];
            *(float4*)(b8)     = *(const float4*)&Bsm[buf][kk][tx << 3];
            *(float4*)(b8 + 4) = *(const float4*)&Bsm[buf][kk][(tx << 3) + 4];
            #pragma unroll
            for (int i = 0; i < 8; i++)
                #pragma unroll
                for (int j = 0; j < 8; j++)
                    acc[i][j] += a8[i] * b8[j];
        }
        buf ^= 1;
    }
    #pragma unroll
    for (int i = 0; i < 8; i++) {
        int mm = m0 + (ty << 3) + i;
        if (mm < cnt) {
            #pragma unroll
            for (int j = 0; j < 8; j++) {
                int nn = n0 + (tx << 3) + j;
                g_e2[((size_t)e * NTOK + mm) * DIM + nn] = acc[i][j] + eb2[e * DIM + nn];
            }
        }
    }
}

// ---------------- head split/merge ----------------
__global__ void head_split(const float* __restrict__ in, float* __restrict__ out) {
    for (int i = blockIdx.x * blockDim.x + threadIdx.x; i < NTOK * DIM;
         i += gridDim.x * blockDim.x) {
        int d = i & 63, s = (i >> 6) & 1023, h = (i >> 16) & 15, b = i >> 20;
        out[i] = in[(size_t)((b << 10) + s) * DIM + (h << 6) + d];
    }
}
__global__ void head_merge(const float* __restrict__ in, float* __restrict__ out) {
    for (int i = blockIdx.x * blockDim.x + threadIdx.x; i < NTOK * DIM;
         i += gridDim.x * blockDim.x) {
        int col = i & 1023, h = col >> 6, d = col & 63;
        int s = (i >> 10) & 1023, b = i >> 20;
        out[i] = in[(size_t)(((b << 4) + h) * 1024 + s) * 64 + d];
    }
}

// ---------------- softmax over score rows (in place) ----------------
__global__ void softmax_rows() {
    float* r = g_sc + ((size_t)blockIdx.y * SQL + blockIdx.x) * SKV;
    __shared__ float sm[32];
    int t = threadIdx.x;
    float v[4];
    float mx = -1e30f;
    #pragma unroll
    for (int j = 0; j < 4; j++) { v[j] = r[t + j * 256]; mx = fmaxf(mx, v[j]); }
    mx = blk_reduce_max(mx, sm);
    float s = 0.f;
    #pragma unroll
    for (int j = 0; j < 4; j++) { v[j] = __expf(v[j] - mx); s += v[j]; }
    s = blk_reduce_sum(s, sm);
    float inv = 1.f / s;
    #pragma unroll
    for (int j = 0; j < 4; j++) r[t + j * 256] = v[j] * inv;
}

// ---------------- LayerNorm with residual: out = LN(a + res) ----------------
__global__ void ln_res(const float* __restrict__ a, const float* __restrict__ res,
                       const float* __restrict__ g, const float* __restrict__ b,
                       float* __restrict__ out1)
{
    __shared__ float sm[32];
    const size_t base = (size_t)blockIdx.x * DIM;
    int t = threadIdx.x;
    float v[4];
    float s = 0.f;
    #pragma unroll
    for (int j = 0; j < 4; j++) {
        int c = t + j * 256;
        v[j] = a[base + c] + (res ? res[base + c] : 0.f);
        s += v[j];
    }
    s = blk_reduce_sum(s, sm);
    float mean = s * (1.0f / DIM);
    float s2 = 0.f;
    #pragma unroll
    for (int j = 0; j < 4; j++) { float d = v[j] - mean; s2 += d * d; }
    s2 = blk_reduce_sum(s2, sm);
    float rs = rsqrtf(s2 * (1.0f / DIM) + 1e-5f);
    #pragma unroll
    for (int j = 0; j < 4; j++) {
        int c = t + j * 256;
        out1[base + c] = (v[j] - mean) * rs * g[c] + b[c];
    }
}

// ---------------- fused MoE combine + final LayerNorm ----------------
__global__ void combine_ln(const float* __restrict__ g, const float* __restrict__ b,
                           float* __restrict__ out)
{
    __shared__ float sm[32];
    const int tok = blockIdx.x;
    const size_t base = (size_t)tok * DIM;
    int t = threadIdx.x;
    float v[4];
    #pragma unroll
    for (int j = 0; j < 4; j++) v[j] = g_x[base + t + j * 256];
    const int nl = g_tcnt[tok];
    for (int l = 0; l < nl; l++) {
        int   e    = g_te  [tok * 3 + l];
        int   slot = g_tslot[tok * 3 + l];
        float gt   = g_tgate[tok * 3 + l];
        const float* row = g_e2 + ((size_t)e * NTOK + slot) * DIM;
        #pragma unroll
        for (int j = 0; j < 4; j++) v[j] += gt * row[t + j * 256];
    }
    float s = 0.f;
    #pragma unroll
    for (int j = 0; j < 4; j++) s += v[j];
    s = blk_reduce_sum(s, sm);
    float mean = s * (1.0f / DIM);
    float s2 = 0.f;
    #pragma unroll
    for (int j = 0; j < 4; j++) { float d = v[j] - mean; s2 += d * d; }
    s2 = blk_reduce_sum(s2, sm);
    float rs = rsqrtf(s2 * (1.0f / DIM) + 1e-5f);
    #pragma unroll
    for (int j = 0; j < 4; j++) {
        int c = t + j * 256;
        out[base + c] = (v[j] - mean) * rs * g[c] + b[c];
    }
}

// ---------------- gating: softmax over 8 experts, top-3 + threshold ----------------
__global__ void gating(const float* __restrict__ Wg) {
    __shared__ float logits[NEXP];
    const int tok = blockIdx.x;
    const float* xr = g_x + (size_t)tok * DIM;
    int w = threadIdx.x >> 5, lane = threadIdx.x & 31;
    float s = 0.f;
    for (int i = lane; i < DIM; i += 32) s += xr[i] * Wg[i * NEXP + w];
    #pragma unroll
    for (int o = 16; o; o >>= 1) s += __shfl_down_sync(0xffffffffu, s, o);
    if (!lane) logits[w] = s;
    __syncthreads();
    if (threadIdx.x == 0) {
        float p[NEXP];
        float mx = -1e30f;
        for (int e = 0; e < NEXP; e++) mx = fmaxf(mx, logits[e]);
        float sum = 0.f;
        for (int e = 0; e < NEXP; e++) { p[e] = __expf(logits[e] - mx); sum += p[e]; }
        float inv = 1.f / sum;
        for (int e = 0; e < NEXP; e++) { p[e] *= inv; g_probs[tok * NEXP + e] = p[e]; }
        // top-3 (ties -> lowest index, matching lax.top_k)
        int i0 = 0;
        for (int e = 1; e < NEXP; e++) if (p[e] > p[i0]) i0 = e;
        int i1 = -1;
        for (int e = 0; e < NEXP; e++) if (e != i0 && (i1 < 0 || p[e] > p[i1])) i1 = e;
        int i2 = -1;
        for (int e = 0; e < NEXP; e++) if (e != i0 && e != i1 && (i2 < 0 || p[e] > p[i2])) i2 = e;
        int   ids[3] = { i0, i1, i2 };
        float gts[3] = { p[i0],
                         (p[i1] >= THRESH) ? p[i1] : 0.f,
                         (p[i2] >= THRESH) ? p[i2] : 0.f };
        int nl = 0;
        #pragma unroll
        for (int j = 0; j < 3; j++) {
            if (gts[j] > 0.f) {
                int slot = atomicAdd(&g_cnt[ids[j]], 1);
                g_tok  [ids[j] * NTOK + slot] = tok;
                g_te   [tok * 3 + nl] = ids[j];
                g_tslot[tok * 3 + nl] = slot;
                g_tgate[tok * 3 + nl] = gts[j];
                nl++;
            }
        }
        g_tcnt[tok] = nl;
    }
}

// ---------------- small utility kernels ----------------
__global__ void zero_small() {
    int t = threadIdx.x;
    if (t < NEXP) g_cnt[t] = 0;
}
__global__ void aux_kernel(float* __restrict__ out, int out_size) {
    if (out_size <= OUT_MAIN) return;
    __shared__ float sm[32];
    int t = threadIdx.x;
    float total = 0.f;
    for (int e = 0; e < NEXP; e++) {
        float s = 0.f;
        for (int tok = t; tok < NTOK; tok += 256) s += g_probs[tok * NEXP + e];
        s = blk_reduce_sum(s, sm);
        if (t == 0) total += ((float)g_cnt[e] / (float)NTOK) * (s / (float)NTOK);
    }
    if (t == 0) out[OUT_MAIN] = COEF * (float)NEXP * total;
}

// ---------------- host launcher ----------------
extern "C" void kernel_launch(void* const* d_in, const int* in_sizes, int n_in,
                              void* d_out, int out_size)
{
    const float* query  = (const float*)d_in[0];
    const float* keyval = (const float*)d_in[1];
    const float* Wq = (const float*)d_in[2];  const float* bq = (const float*)d_in[3];
    const float* Wk = (const float*)d_in[4];  const float* bk = (const float*)d_in[5];
    const float* Wv = (const float*)d_in[6];  const float* bv = (const float*)d_in[7];
    const float* W_in  = (const float*)d_in[8];  const float* b_in  = (const float*)d_in[9];
    const float* W_out = (const float*)d_in[10]; const float* b_out = (const float*)d_in[11];
    const float* Wa = (const float*)d_in[12]; const float* ba = (const float*)d_in[13];
    const float* ln1g = (const float*)d_in[14]; const float* ln1b = (const float*)d_in[15];
    const float* Wg = (const float*)d_in[16];
    const float* ew1 = (const float*)d_in[17]; const float* eb1 = (const float*)d_in[18];
    const float* ew2 = (const float*)d_in[19]; const float* eb2 = (const float*)d_in[20];
    const float* ln2g = (const float*)d_in[21]; const float* ln2b = (const float*)d_in[22];
    float* out = (float*)d_out;

    float *q, *k, *v, *qh, *kh, *vh, *qt, *kt, *vt, *sc, *ot, *o, *op, *a, *x;
    cudaGetSymbolAddress((void**)&q,  g_q);
    cudaGetSymbolAddress((void**)&k,  g_k);
    cudaGetSymbolAddress((void**)&v,  g_v);
    cudaGetSymbolAddress((void**)&qh, g_qh);
    cudaGetSymbolAddress((void**)&kh, g_kh);
    cudaGetSymbolAddress((void**)&vh, g_vh);
    cudaGetSymbolAddress((void**)&qt, g_qt);
    cudaGetSymbolAddress((void**)&kt, g_kt);
    cudaGetSymbolAddress((void**)&vt, g_vt);
    cudaGetSymbolAddress((void**)&sc, g_sc);
    cudaGetSymbolAddress((void**)&ot, g_ot);
    cudaGetSymbolAddress((void**)&o,  g_o);
    cudaGetSymbolAddress((void**)&op, g_op);
    cudaGetSymbolAddress((void**)&a,  g_a);
    cudaGetSymbolAddress((void**)&x,  g_x);

    const dim3 THR(256);
    const dim3 GLIN(DIM / 128, NTOK / 128, 1);        // 8 x 32 for 4096x1024 linears

    zero_small<<<1, 32>>>();

    // outer Q/K/V linears: x @ W^T + b
    gemm128<128, true><<<GLIN, THR>>>(query,  Wq, q, DIM, DIM, DIM, DIM, 0, 0, 0, bq, 1.f);
    gemm128<128, true><<<GLIN, THR>>>(keyval, Wk, k, DIM, DIM, DIM, DIM, 0, 0, 0, bk, 1.f);
    gemm128<128, true><<<GLIN, THR>>>(keyval, Wv, v, DIM, DIM, DIM, DIM, 0, 0, 0, bv, 1.f);

    // MHA in-projection
    gemm128<128, true><<<GLIN, THR>>>(q, W_in,                 qh, DIM, DIM, DIM, DIM, 0, 0, 0, b_in,           1.f);
    gemm128<128, true><<<GLIN, THR>>>(k, W_in + DIM * DIM,     kh, DIM, DIM, DIM, DIM, 0, 0, 0, b_in + DIM,     1.f);
    gemm128<128, true><<<GLIN, THR>>>(v, W_in + 2 * DIM * DIM, vh, DIM, DIM, DIM, DIM, 0, 0, 0, b_in + 2 * DIM, 1.f);

    // [B,S,H,dh] -> [B,H,S,dh]
    head_split<<<512, 256>>>(qh, qt);
    head_split<<<512, 256>>>(kh, kt);
    head_split<<<512, 256>>>(vh, vt);

    // scores = (Q @ K^T) / 8, batched over B*H
    gemm128<128, true><<<dim3(SKV / 128, SQL / 128, BH), THR>>>(
        qt, kt, sc, DH, DH, DH, SKV,
        (long long)SQL * DH, (long long)SKV * DH, (long long)SQL * SKV,
        nullptr, 0.125f);

    softmax_rows<<<dim3(SQL, BH), THR>>>();

    // O = attn @ V, batched (N = 64 tile variant)
    gemm128<64, false><<<dim3(1, SQL / 128, BH), THR>>>(
        sc, vt, ot, SKV, SKV, DH, DH,
        (long long)SQL * SKV, (long long)SKV * DH, (long long)SQL * DH,
        nullptr, 1.f);

    head_merge<<<512, 256>>>(ot, o);

    // out-projection + adapter
    gemm128<128, true><<<GLIN, THR>>>(o,  W_out, op, DIM, DIM, DIM, DIM, 0, 0, 0, b_out, 1.f);
    gemm128<128, true><<<GLIN, THR>>>(op, Wa,    a,  DIM, DIM, DIM, DIM, 0, 0, 0, ba,    1.f);

    // x = LN1(a + query)
    ln_res<<<NTOK, THR>>>(a, query, ln1g, ln1b, x);

    // gating -> per-expert token lists + per-token combine lists
    gating<<<NTOK, THR>>>(Wg);

    // expert FFNs (gathered rows; grid covers max count, early-exit on cnt)
    moe_gemm1<<<dim3(HDIM / 128, NTOK / 128, NEXP), THR>>>(ew1, eb1);
    moe_gemm2<<<dim3(DIM / 128,  NTOK / 128, NEXP), THR>>>(ew2, eb2);

    // fused combine + final LN -> output, then aux scalar
    combine_ln<<<NTOK, THR>>>(ln2g, ln2b, out);
    aux_kernel<<<1, 256>>>(out, out_size);
}

// round 8
// speedup vs baseline: 2.2476x; 1.9139x over previous
#include <cuda_runtime.h>
#include <cuda_bf16.h>
#include <math.h>
#include <stddef.h>
#include <stdint.h>

// ---------------- problem constants ----------------
#define BATCH 4
#define SQL   1024
#define SKV   1024
#define DIM   1024
#define NH    16
#define DH    64
#define NEXP  8
#define HDIM  4096
#define NTOK  (BATCH*SQL)       // 4096
#define BH    (BATCH*NH)        // 64
#define OUT_MAIN (NTOK*DIM)
#define THRESH 0.05f
#define COEF   0.01f
#define KCH   64                // K chunk
#define RS    72                // smem row stride in u16 (64 data + 8 pad)

typedef unsigned short u16;
typedef unsigned int   u32;

// ---------------- static device scratch (fp32) ----------------
__device__ float g_qh[NTOK*DIM];
__device__ float g_kh[NTOK*DIM];
__device__ float g_vh[NTOK*DIM];
__device__ float g_sc[(size_t)BH*SQL*SKV];      // 256 MB
__device__ float g_ot[NTOK*DIM];
__device__ float g_a [NTOK*DIM];
__device__ float g_x [NTOK*DIM];
__device__ float g_e2[(size_t)NEXP*NTOK*DIM];   // 128 MB
__device__ int   g_cnt[NEXP];
__device__ int   g_tok[NEXP*NTOK];
__device__ float g_probs[NTOK*NEXP];
__device__ int   g_tcnt[NTOK];
__device__ int   g_te  [NTOK*3];
__device__ int   g_tslot[NTOK*3];
__device__ float g_tgate[NTOK*3];

// ---------------- bf16 hi/lo split buffers ----------------
__device__ u16 s_query_h[NTOK*DIM], s_query_l[NTOK*DIM];
__device__ u16 s_kv_h[NTOK*DIM],    s_kv_l[NTOK*DIM];
__device__ u16 s_q_h[NTOK*DIM],     s_q_l[NTOK*DIM];
__device__ u16 s_k_h[NTOK*DIM],     s_k_l[NTOK*DIM];
__device__ u16 s_v_h[NTOK*DIM],     s_v_l[NTOK*DIM];
__device__ u16 s_qt_h[NTOK*DIM],    s_qt_l[NTOK*DIM];
__device__ u16 s_kt_h[NTOK*DIM],    s_kt_l[NTOK*DIM];
__device__ u16 s_vt_h[NTOK*DIM],    s_vt_l[NTOK*DIM];    // [bh][dh][skv]
__device__ u16 s_o_h[NTOK*DIM],     s_o_l[NTOK*DIM];
__device__ u16 s_op_h[NTOK*DIM],    s_op_l[NTOK*DIM];
__device__ u16 s_x_h[NTOK*DIM],     s_x_l[NTOK*DIM];
__device__ u16 s_p_h[(size_t)BH*SQL*SKV], s_p_l[(size_t)BH*SQL*SKV];
__device__ u16 s_hh [(size_t)NEXP*NTOK*HDIM], s_hl[(size_t)NEXP*NTOK*HDIM];
// weights
__device__ u16 s_wq_h[DIM*DIM],   s_wq_l[DIM*DIM];
__device__ u16 s_wk_h[DIM*DIM],   s_wk_l[DIM*DIM];
__device__ u16 s_wv_h[DIM*DIM],   s_wv_l[DIM*DIM];
__device__ u16 s_win_h[3*DIM*DIM],s_win_l[3*DIM*DIM];
__device__ u16 s_wo_h[DIM*DIM],   s_wo_l[DIM*DIM];
__device__ u16 s_wa_h[DIM*DIM],   s_wa_l[DIM*DIM];
__device__ u16 s_e1_h[(size_t)NEXP*HDIM*DIM], s_e1_l[(size_t)NEXP*HDIM*DIM]; // [e][n=HDIM][k=DIM]
__device__ u16 s_e2_h[(size_t)NEXP*DIM*HDIM], s_e2_l[(size_t)NEXP*DIM*HDIM]; // [e][n=DIM][k=HDIM]

// ---------------- helpers ----------------
__device__ __forceinline__ u16 f2bf(float v) { __nv_bfloat16 b = __float2bfloat16(v); return *(u16*)&b; }
__device__ __forceinline__ float bf2f(u16 u) { __nv_bfloat16 b; *(u16*)&b = u; return __bfloat162float(b); }
__device__ __forceinline__ void split2(float v, u16& h, u16& l) {
    u16 hu = f2bf(v); h = hu; l = f2bf(v - bf2f(hu));
}
__device__ __forceinline__ float gelu_exact(float v) {
    return 0.5f * v * (1.0f + erff(v * 0.70710678118654752f));
}
__device__ __forceinline__ float blk_reduce_sum(float v, float* sm) {
    int lane = threadIdx.x & 31, w = threadIdx.x >> 5;
    #pragma unroll
    for (int o = 16; o; o >>= 1) v += __shfl_down_sync(0xffffffffu, v, o);
    if (!lane) sm[w] = v;
    __syncthreads();
    if (threadIdx.x < 32) {
        v = (threadIdx.x < 8) ? sm[threadIdx.x] : 0.f;
        #pragma unroll
        for (int o = 4; o; o >>= 1) v += __shfl_down_sync(0xffffffffu, v, o);
        if (!threadIdx.x) sm[0] = v;
    }
    __syncthreads();
    float r = sm[0];
    __syncthreads();
    return r;
}
__device__ __forceinline__ float blk_reduce_max(float v, float* sm) {
    int lane = threadIdx.x & 31, w = threadIdx.x >> 5;
    #pragma unroll
    for (int o = 16; o; o >>= 1) v = fmaxf(v, __shfl_down_sync(0xffffffffu, v, o));
    if (!lane) sm[w] = v;
    __syncthreads();
    if (threadIdx.x < 32) {
        v = (threadIdx.x < 8) ? sm[threadIdx.x] : -1e30f;
        #pragma unroll
        for (int o = 4; o; o >>= 1) v = fmaxf(v, __shfl_down_sync(0xffffffffu, v, o));
        if (!threadIdx.x) sm[0] = v;
    }
    __syncthreads();
    float r = sm[0];
    __syncthreads();
    return r;
}

__device__ __forceinline__ void mma_bf16(float* c, const u32* a, const u32* b) {
    asm volatile(
        "mma.sync.aligned.m16n8k16.row.col.f32.bf16.bf16.f32 "
        "{%0,%1,%2,%3}, {%4,%5,%6,%7}, {%8,%9}, {%0,%1,%2,%3};"
        : "+f"(c[0]), "+f"(c[1]), "+f"(c[2]), "+f"(c[3])
        : "r"(a[0]), "r"(a[1]), "r"(a[2]), "r"(a[3]), "r"(b[0]), "r"(b[1]));
}

// =====================================================================
// bf16-split tensor-core GEMM via mma.sync: C[z] = alpha*(A@B^T) + bias.
// A,B are bf16 hi/lo pairs, K-major rows (stride K). M tile 128, N tile BN,
// K chunks of 64. 8 warps (4x2), warp tile 32 x (BN/2). Double-buffered smem.
// =====================================================================
template<int BN, bool GELU_, bool WF32, bool WSPLIT, bool GATHER>
__global__ __launch_bounds__(256, 1)
void gemm_tc(const u16* __restrict__ Ah_, const u16* __restrict__ Al_,
             const u16* __restrict__ Bh_, const u16* __restrict__ Bl_,
             int K, long long As, long long Bs, long long Cs,
             const int* __restrict__ rowmap, const int* __restrict__ cntArr,
             const float* __restrict__ bias, long long biasStride, float alpha,
             float* __restrict__ Cf, u16* __restrict__ Ch, u16* __restrict__ Cl, int ldc)
{
    extern __shared__ __align__(16) u16 smem[];
    const int z = blockIdx.z;
    const int cnt = cntArr ? cntArr[z] : 0x40000000;
    const int m0 = blockIdx.y << 7;
    if (m0 >= cnt) return;
    const int n0 = blockIdx.x * BN;

    const u16* Ah = Ah_ + (size_t)z * As;
    const u16* Al = Al_ + (size_t)z * As;
    const u16* Bh = Bh_ + (size_t)z * Bs;
    const u16* Bl = Bl_ + (size_t)z * Bs;
    if (WF32)   Cf += (size_t)z * Cs;
    if (WSPLIT) { Ch += (size_t)z * Cs; Cl += (size_t)z * Cs; }
    const float* bptr = bias ? bias + (size_t)z * biasStride : nullptr;
    const int* rmap = GATHER ? (rowmap + (size_t)z * NTOK) : nullptr;

    constexpr int ASZ = 128 * RS;            // u16 per A tile
    constexpr int BSZ = BN * RS;
    constexpr int STG = 2 * ASZ + 2 * BSZ;   // per stage
    constexpr int WN  = BN / 2;
    constexpr int NF  = WN / 8;

    const int tid = threadIdx.x;
    const int wid = tid >> 5, lane = tid & 31;
    const int wm = wid & 3, wn = wid >> 1 >> 1;   // wn = wid>>2
    const int gid = lane >> 2, tg = lane & 3;

    float acc[2][NF][4];
    #pragma unroll
    for (int i = 0; i < 2; i++)
        #pragma unroll
        for (int j = 0; j < NF; j++)
            #pragma unroll
            for (int q = 0; q < 4; q++) acc[i][j][q] = 0.f;

    const int nch = K / KCH;
    for (int c = 0; c < nch; c++) {
        const int buf = c & 1;
        const int k0 = c * KCH;
        u16* sA_h = smem + buf * STG;
        u16* sA_l = sA_h + ASZ;
        u16* sB_h = sA_h + 2 * ASZ;
        u16* sB_l = sB_h + BSZ;

        // ---- load A (128 x 64, hi+lo) ----
        #pragma unroll
        for (int it = 0; it < 4; it++) {
            int idx = tid + it * 256;
            int row = idx >> 3, blk = idx & 7;
            int srow;
            if (GATHER) { int gm = m0 + row; if (gm >= cnt) gm = cnt - 1; srow = rmap[gm]; }
            else srow = m0 + row;
            size_t go = (size_t)srow * K + k0 + blk * 8;
            *(uint4*)&sA_h[row * RS + blk * 8] = *(const uint4*)(Ah + go);
            *(uint4*)&sA_l[row * RS + blk * 8] = *(const uint4*)(Al + go);
        }
        // ---- load B (BN x 64, hi+lo) ----
        #pragma unroll
        for (int it = 0; it < BN / 32; it++) {
            int idx = tid + it * 256;
            int row = idx >> 3, blk = idx & 7;
            size_t go = (size_t)(n0 + row) * K + k0 + blk * 8;
            *(uint4*)&sB_h[row * RS + blk * 8] = *(const uint4*)(Bh + go);
            *(uint4*)&sB_l[row * RS + blk * 8] = *(const uint4*)(Bl + go);
        }
        __syncthreads();

        #pragma unroll
        for (int ks = 0; ks < 4; ks++) {
            u32 ah[2][4], al[2][4];
            #pragma unroll
            for (int mi = 0; mi < 2; mi++) {
                const u16* pa = sA_h + (wm * 32 + mi * 16 + gid) * RS + ks * 16 + tg * 2;
                ah[mi][0] = *(const u32*)pa;
                ah[mi][1] = *(const u32*)(pa + 8 * RS);
                ah[mi][2] = *(const u32*)(pa + 8);
                ah[mi][3] = *(const u32*)(pa + 8 * RS + 8);
                const u16* pl = sA_l + (wm * 32 + mi * 16 + gid) * RS + ks * 16 + tg * 2;
                al[mi][0] = *(const u32*)pl;
                al[mi][1] = *(const u32*)(pl + 8 * RS);
                al[mi][2] = *(const u32*)(pl + 8);
                al[mi][3] = *(const u32*)(pl + 8 * RS + 8);
            }
            u32 bh[NF][2], bl[NF][2];
            #pragma unroll
            for (int nf = 0; nf < NF; nf++) {
                const u16* pb = sB_h + (wn * WN + nf * 8 + gid) * RS + ks * 16 + tg * 2;
                bh[nf][0] = *(const u32*)pb;
                bh[nf][1] = *(const u32*)(pb + 8);
                const u16* ql = sB_l + (wn * WN + nf * 8 + gid) * RS + ks * 16 + tg * 2;
                bl[nf][0] = *(const u32*)ql;
                bl[nf][1] = *(const u32*)(ql + 8);
            }
            #pragma unroll
            for (int mi = 0; mi < 2; mi++)
                #pragma unroll
                for (int nf = 0; nf < NF; nf++) {
                    mma_bf16(acc[mi][nf], ah[mi], bh[nf]);
                    mma_bf16(acc[mi][nf], ah[mi], bl[nf]);
                    mma_bf16(acc[mi][nf], al[mi], bh[nf]);
                }
        }
        __syncthreads();
    }

    // ---- epilogue ----
    #pragma unroll
    for (int mi = 0; mi < 2; mi++) {
        #pragma unroll
        for (int nf = 0; nf < NF; nf++) {
            int mA  = m0 + wm * 32 + mi * 16 + gid;
            int col = n0 + wn * WN + nf * 8 + tg * 2;
            #pragma unroll
            for (int half = 0; half < 2; half++) {
                int m = mA + half * 8;
                if (m < cnt) {
                    float v0 = acc[mi][nf][half * 2 + 0] * alpha;
                    float v1 = acc[mi][nf][half * 2 + 1] * alpha;
                    if (bptr) { v0 += bptr[col]; v1 += bptr[col + 1]; }
                    if (GELU_) { v0 = gelu_exact(v0); v1 = gelu_exact(v1); }
                    size_t o = (size_t)m * ldc + col;
                    if (WF32) { Cf[o] = v0; Cf[o + 1] = v1; }
                    if (WSPLIT) {
                        u16 h0, l0, h1, l1;
                        split2(v0, h0, l0); split2(v1, h1, l1);
                        Ch[o] = h0; Ch[o + 1] = h1;
                        Cl[o] = l0; Cl[o + 1] = l1;
                    }
                }
            }
        }
    }
}

// ---------------- conversion kernels ----------------
__global__ void split_f32(const float* __restrict__ s, u16* __restrict__ h, u16* __restrict__ l, int n) {
    for (int i = blockIdx.x * blockDim.x + threadIdx.x; i * 4 < n; i += gridDim.x * blockDim.x) {
        float4 v = ((const float4*)s)[i];
        u16 hh[4], ll[4];
        split2(v.x, hh[0], ll[0]); split2(v.y, hh[1], ll[1]);
        split2(v.z, hh[2], ll[2]); split2(v.w, hh[3], ll[3]);
        *(uint2*)&h[4 * i] = *(uint2*)hh;
        *(uint2*)&l[4 * i] = *(uint2*)ll;
    }
}

__global__ void transpose_split(const float* __restrict__ s, u16* __restrict__ oh, u16* __restrict__ ol,
                                int R, int C) {
    __shared__ float t[32][33];
    size_t zo = (size_t)blockIdx.z * R * C;
    const float* src = s + zo;
    int c0 = blockIdx.x * 32, r0 = blockIdx.y * 32;
    int tx = threadIdx.x & 31, ty = threadIdx.x >> 5;
    #pragma unroll
    for (int dy = 0; dy < 32; dy += 8)
        t[ty + dy][tx] = src[(size_t)(r0 + ty + dy) * C + c0 + tx];
    __syncthreads();
    #pragma unroll
    for (int dy = 0; dy < 32; dy += 8) {
        float v = t[tx][ty + dy];
        size_t o = zo + (size_t)(c0 + ty + dy) * R + r0 + tx;
        u16 hh, ll; split2(v, hh, ll);
        oh[o] = hh; ol[o] = ll;
    }
}

__global__ void headsplit_qk(const float* __restrict__ in, u16* __restrict__ oh, u16* __restrict__ ol) {
    for (int i = blockIdx.x * blockDim.x + threadIdx.x; i < NTOK * DIM; i += gridDim.x * blockDim.x) {
        int d = i & 63, s = (i >> 6) & 1023, h = (i >> 16) & 15, b = i >> 20;
        float v = in[(size_t)((b << 10) + s) * DIM + (h << 6) + d];
        u16 hh, ll; split2(v, hh, ll);
        oh[i] = hh; ol[i] = ll;
    }
}

__global__ void headsplit_vT(const float* __restrict__ in, u16* __restrict__ oh, u16* __restrict__ ol) {
    __shared__ float t[32][33];
    int z = blockIdx.z;
    int b = z >> 4, h = z & 15;
    int s0 = blockIdx.x * 32, d0 = blockIdx.y * 32;
    int tx = threadIdx.x & 31, ty = threadIdx.x >> 5;
    #pragma unroll
    for (int dy = 0; dy < 32; dy += 8)
        t[ty + dy][tx] = in[(size_t)((b << 10) + s0 + ty + dy) * DIM + h * 64 + d0 + tx];
    __syncthreads();
    #pragma unroll
    for (int dy = 0; dy < 32; dy += 8) {
        float v = t[tx][ty + dy];
        size_t o = (size_t)(z * 64 + d0 + ty + dy) * 1024 + s0 + tx;
        u16 hh, ll; split2(v, hh, ll);
        oh[o] = hh; ol[o] = ll;
    }
}

__global__ void softmax_split() {
    const size_t ro = ((size_t)blockIdx.y * SQL + blockIdx.x) * SKV;
    const float* r = g_sc + ro;
    __shared__ float sm[32];
    int t = threadIdx.x;
    float v[4];
    float mx = -1e30f;
    #pragma unroll
    for (int j = 0; j < 4; j++) { v[j] = r[t + j * 256]; mx = fmaxf(mx, v[j]); }
    mx = blk_reduce_max(mx, sm);
    float s = 0.f;
    #pragma unroll
    for (int j = 0; j < 4; j++) { v[j] = __expf(v[j] - mx); s += v[j]; }
    s = blk_reduce_sum(s, sm);
    float inv = 1.f / s;
    #pragma unroll
    for (int j = 0; j < 4; j++) {
        float p = v[j] * inv;
        u16 hh, ll; split2(p, hh, ll);
        s_p_h[ro + t + j * 256] = hh;
        s_p_l[ro + t + j * 256] = ll;
    }
}

__global__ void head_merge_split(const float* __restrict__ in, u16* __restrict__ oh, u16* __restrict__ ol) {
    for (int i = blockIdx.x * blockDim.x + threadIdx.x; i < NTOK * DIM; i += gridDim.x * blockDim.x) {
        int col = i & 1023, h = col >> 6, d = col & 63;
        int s = (i >> 10) & 1023, b = i >> 20;
        float v = in[(size_t)(((b << 4) + h) * 1024 + s) * 64 + d];
        u16 hh, ll; split2(v, hh, ll);
        oh[i] = hh; ol[i] = ll;
    }
}

__global__ void ln_res_split(const float* __restrict__ a, const float* __restrict__ res,
                             const float* __restrict__ g, const float* __restrict__ b,
                             float* __restrict__ of, u16* __restrict__ oh, u16* __restrict__ ol) {
    __shared__ float sm[32];
    const size_t base = (size_t)blockIdx.x * DIM;
    int t = threadIdx.x;
    float v[4];
    float s = 0.f;
    #pragma unroll
    for (int j = 0; j < 4; j++) {
        int c = t + j * 256;
        v[j] = a[base + c] + res[base + c];
        s += v[j];
    }
    s = blk_reduce_sum(s, sm);
    float mean = s * (1.0f / DIM);
    float s2 = 0.f;
    #pragma unroll
    for (int j = 0; j < 4; j++) { float d = v[j] - mean; s2 += d * d; }
    s2 = blk_reduce_sum(s2, sm);
    float rs = rsqrtf(s2 * (1.0f / DIM) + 1e-5f);
    #pragma unroll
    for (int j = 0; j < 4; j++) {
        int c = t + j * 256;
        float o = (v[j] - mean) * rs * g[c] + b[c];
        of[base + c] = o;
        u16 hh, ll; split2(o, hh, ll);
        oh[base + c] = hh; ol[base + c] = ll;
    }
}

__global__ void combine_ln(const float* __restrict__ g, const float* __restrict__ b,
                           float* __restrict__ out) {
    __shared__ float sm[32];
    const int tok = blockIdx.x;
    const size_t base = (size_t)tok * DIM;
    int t = threadIdx.x;
    float v[4];
    #pragma unroll
    for (int j = 0; j < 4; j++) v[j] = g_x[base + t + j * 256];
    const int nl = g_tcnt[tok];
    for (int l = 0; l < nl; l++) {
        int   e    = g_te[tok * 3 + l];
        int   slot = g_tslot[tok * 3 + l];
        float gt   = g_tgate[tok * 3 + l];
        const float* row = g_e2 + ((size_t)e * NTOK + slot) * DIM;
        #pragma unroll
        for (int j = 0; j < 4; j++) v[j] += gt * row[t + j * 256];
    }
    float s = 0.f;
    #pragma unroll
    for (int j = 0; j < 4; j++) s += v[j];
    s = blk_reduce_sum(s, sm);
    float mean = s * (1.0f / DIM);
    float s2 = 0.f;
    #pragma unroll
    for (int j = 0; j < 4; j++) { float d = v[j] - mean; s2 += d * d; }
    s2 = blk_reduce_sum(s2, sm);
    float rs = rsqrtf(s2 * (1.0f / DIM) + 1e-5f);
    #pragma unroll
    for (int j = 0; j < 4; j++) {
        int c = t + j * 256;
        out[base + c] = (v[j] - mean) * rs * g[c] + b[c];
    }
}

__global__ void gating(const float* __restrict__ Wg) {
    __shared__ float logits[NEXP];
    const int tok = blockIdx.x;
    const float* xr = g_x + (size_t)tok * DIM;
    int w = threadIdx.x >> 5, lane = threadIdx.x & 31;
    float s = 0.f;
    for (int i = lane; i < DIM; i += 32) s += xr[i] * Wg[i * NEXP + w];
    #pragma unroll
    for (int o = 16; o; o >>= 1) s += __shfl_down_sync(0xffffffffu, s, o);
    if (!lane) logits[w] = s;
    __syncthreads();
    if (threadIdx.x == 0) {
        float p[NEXP];
        float mx = -1e30f;
        for (int e = 0; e < NEXP; e++) mx = fmaxf(mx, logits[e]);
        float sum = 0.f;
        for (int e = 0; e < NEXP; e++) { p[e] = __expf(logits[e] - mx); sum += p[e]; }
        float inv = 1.f / sum;
        for (int e = 0; e < NEXP; e++) { p[e] *= inv; g_probs[tok * NEXP + e] = p[e]; }
        int i0 = 0;
        for (int e = 1; e < NEXP; e++) if (p[e] > p[i0]) i0 = e;
        int i1 = -1;
        for (int e = 0; e < NEXP; e++) if (e != i0 && (i1 < 0 || p[e] > p[i1])) i1 = e;
        int i2 = -1;
        for (int e = 0; e < NEXP; e++) if (e != i0 && e != i1 && (i2 < 0 || p[e] > p[i2])) i2 = e;
        int   ids[3] = { i0, i1, i2 };
        float gts[3] = { p[i0],
                         (p[i1] >= THRESH) ? p[i1] : 0.f,
                         (p[i2] >= THRESH) ? p[i2] : 0.f };
        int nl = 0;
        #pragma unroll
        for (int j = 0; j < 3; j++) {
            if (gts[j] > 0.f) {
                int slot = atomicAdd(&g_cnt[ids[j]], 1);
                g_tok  [ids[j] * NTOK + slot] = tok;
                g_te   [tok * 3 + nl] = ids[j];
                g_tslot[tok * 3 + nl] = slot;
                g_tgate[tok * 3 + nl] = gts[j];
                nl++;
            }
        }
        g_tcnt[tok] = nl;
    }
}

__global__ void zero_small() {
    int t = threadIdx.x;
    if (t < NEXP) g_cnt[t] = 0;
}
__global__ void aux_kernel(float* __restrict__ out, int out_size) {
    if (out_size <= OUT_MAIN) return;
    __shared__ float sm[32];
    int t = threadIdx.x;
    float total = 0.f;
    for (int e = 0; e < NEXP; e++) {
        float s = 0.f;
        for (int tok = t; tok < NTOK; tok += 256) s += g_probs[tok * NEXP + e];
        s = blk_reduce_sum(s, sm);
        if (t == 0) total += ((float)g_cnt[e] / (float)NTOK) * (s / (float)NTOK);
    }
    if (t == 0) out[OUT_MAIN] = COEF * (float)NEXP * total;
}

// ---------------- host launcher ----------------
#define GETSYM(var, sym) do { cudaGetSymbolAddress((void**)&(var), sym); } while (0)

extern "C" void kernel_launch(void* const* d_in, const int* in_sizes, int n_in,
                              void* d_out, int out_size)
{
    (void)in_sizes; (void)n_in;
    const float* query  = (const float*)d_in[0];
    const float* keyval = (const float*)d_in[1];
    const float* Wq = (const float*)d_in[2];  const float* bq = (const float*)d_in[3];
    const float* Wk = (const float*)d_in[4];  const float* bk = (const float*)d_in[5];
    const float* Wv = (const float*)d_in[6];  const float* bv = (const float*)d_in[7];
    const float* W_in  = (const float*)d_in[8];  const float* b_in  = (const float*)d_in[9];
    const float* W_out = (const float*)d_in[10]; const float* b_out = (const float*)d_in[11];
    const float* Wa = (const float*)d_in[12]; const float* ba = (const float*)d_in[13];
    const float* ln1g = (const float*)d_in[14]; const float* ln1b = (const float*)d_in[15];
    const float* Wg = (const float*)d_in[16];
    const float* ew1 = (const float*)d_in[17]; const float* eb1 = (const float*)d_in[18];
    const float* ew2 = (const float*)d_in[19]; const float* eb2 = (const float*)d_in[20];
    const float* ln2g = (const float*)d_in[21]; const float* ln2b = (const float*)d_in[22];
    float* out = (float*)d_out;

    float *qh, *kh, *vh, *sc, *ot, *a, *x, *e2p;
    GETSYM(qh, g_qh); GETSYM(kh, g_kh); GETSYM(vh, g_vh);
    GETSYM(sc, g_sc); GETSYM(ot, g_ot); GETSYM(a, g_a); GETSYM(x, g_x);
    GETSYM(e2p, g_e2);
    u16 *qyh,*qyl,*kvh,*kvl,*qsh,*qsl,*ksh,*ksl,*vsh,*vsl;
    u16 *qth,*qtl,*kth,*ktl,*vth,*vtl,*oh,*ol,*oph,*opl,*xh,*xl,*pph,*ppl,*hhh,*hhl;
    u16 *wqh,*wql,*wkh,*wkl,*wvh,*wvl,*winh,*winl,*woh,*wol,*wah,*wal,*e1h,*e1l,*e2h,*e2l;
    GETSYM(qyh, s_query_h); GETSYM(qyl, s_query_l);
    GETSYM(kvh, s_kv_h);    GETSYM(kvl, s_kv_l);
    GETSYM(qsh, s_q_h);  GETSYM(qsl, s_q_l);
    GETSYM(ksh, s_k_h);  GETSYM(ksl, s_k_l);
    GETSYM(vsh, s_v_h);  GETSYM(vsl, s_v_l);
    GETSYM(qth, s_qt_h); GETSYM(qtl, s_qt_l);
    GETSYM(kth, s_kt_h); GETSYM(ktl, s_kt_l);
    GETSYM(vth, s_vt_h); GETSYM(vtl, s_vt_l);
    GETSYM(oh,  s_o_h);  GETSYM(ol,  s_o_l);
    GETSYM(oph, s_op_h); GETSYM(opl, s_op_l);
    GETSYM(xh,  s_x_h);  GETSYM(xl,  s_x_l);
    GETSYM(pph, s_p_h);  GETSYM(ppl, s_p_l);
    GETSYM(hhh, s_hh);   GETSYM(hhl, s_hl);
    GETSYM(wqh, s_wq_h); GETSYM(wql, s_wq_l);
    GETSYM(wkh, s_wk_h); GETSYM(wkl, s_wk_l);
    GETSYM(wvh, s_wv_h); GETSYM(wvl, s_wv_l);
    GETSYM(winh, s_win_h); GETSYM(winl, s_win_l);
    GETSYM(woh, s_wo_h); GETSYM(wol, s_wo_l);
    GETSYM(wah, s_wa_h); GETSYM(wal, s_wa_l);
    GETSYM(e1h, s_e1_h); GETSYM(e1l, s_e1_l);
    GETSYM(e2h, s_e2_h); GETSYM(e2l, s_e2_l);
    int *tokp; GETSYM(tokp, g_tok);
    int *cntp; GETSYM(cntp, g_cnt);

    // dynamic smem: 2 stages * (2*A + 2*B) tiles, u16 with RS=72 row stride
    const int SM128 = 2 * (2 * 128 * RS + 2 * 128 * RS) * 2;   // 147456 B
    const int SM64  = 2 * (2 * 128 * RS + 2 * 64  * RS) * 2;   // 110592 B
    cudaFuncSetAttribute((const void*)gemm_tc<128,false,false,true ,false>, cudaFuncAttributeMaxDynamicSharedMemorySize, SM128);
    cudaFuncSetAttribute((const void*)gemm_tc<128,false,true ,false,false>, cudaFuncAttributeMaxDynamicSharedMemorySize, SM128);
    cudaFuncSetAttribute((const void*)gemm_tc<64 ,false,true ,false,false>, cudaFuncAttributeMaxDynamicSharedMemorySize, SM64);
    cudaFuncSetAttribute((const void*)gemm_tc<128,true ,false,true ,true >, cudaFuncAttributeMaxDynamicSharedMemorySize, SM128);

    const dim3 T256(256);

    zero_small<<<1, 32>>>();

    // ---- input / weight conversions ----
    split_f32<<<1024, 256>>>(query,  qyh, qyl, NTOK*DIM);
    split_f32<<<1024, 256>>>(keyval, kvh, kvl, NTOK*DIM);
    split_f32<<<512, 256>>>(Wq, wqh, wql, DIM*DIM);
    split_f32<<<512, 256>>>(Wk, wkh, wkl, DIM*DIM);
    split_f32<<<512, 256>>>(Wv, wvh, wvl, DIM*DIM);
    split_f32<<<1024, 256>>>(W_in, winh, winl, 3*DIM*DIM);
    split_f32<<<512, 256>>>(W_out, woh, wol, DIM*DIM);
    split_f32<<<512, 256>>>(Wa, wah, wal, DIM*DIM);
    transpose_split<<<dim3(HDIM/32, DIM/32, NEXP), T256>>>(ew1, e1h, e1l, DIM, HDIM);   // [D,H] -> [H,D]
    transpose_split<<<dim3(DIM/32, HDIM/32, NEXP), T256>>>(ew2, e2h, e2l, HDIM, DIM);   // [H,D] -> [D,H]

    const dim3 GLIN(DIM/128, NTOK/128, 1);

    // ---- outer Q/K/V linears (split output) ----
    gemm_tc<128,false,false,true,false><<<GLIN, T256, SM128>>>(
        qyh, qyl, wqh, wql, DIM, 0, 0, 0, nullptr, nullptr, bq, 0, 1.f, nullptr, qsh, qsl, DIM);
    gemm_tc<128,false,false,true,false><<<GLIN, T256, SM128>>>(
        kvh, kvl, wkh, wkl, DIM, 0, 0, 0, nullptr, nullptr, bk, 0, 1.f, nullptr, ksh, ksl, DIM);
    gemm_tc<128,false,false,true,false><<<GLIN, T256, SM128>>>(
        kvh, kvl, wvh, wvl, DIM, 0, 0, 0, nullptr, nullptr, bv, 0, 1.f, nullptr, vsh, vsl, DIM);

    // ---- MHA in-projection (fp32 out) ----
    gemm_tc<128,false,true,false,false><<<GLIN, T256, SM128>>>(
        qsh, qsl, winh,              winl,              DIM, 0, 0, 0, nullptr, nullptr, b_in,        0, 1.f, qh, nullptr, nullptr, DIM);
    gemm_tc<128,false,true,false,false><<<GLIN, T256, SM128>>>(
        ksh, ksl, winh + DIM*DIM,    winl + DIM*DIM,    DIM, 0, 0, 0, nullptr, nullptr, b_in + DIM,  0, 1.f, kh, nullptr, nullptr, DIM);
    gemm_tc<128,false,true,false,false><<<GLIN, T256, SM128>>>(
        vsh, vsl, winh + 2*DIM*DIM,  winl + 2*DIM*DIM,  DIM, 0, 0, 0, nullptr, nullptr, b_in + 2*DIM,0, 1.f, vh, nullptr, nullptr, DIM);

    // ---- head reshape ----
    headsplit_qk<<<512, 256>>>(qh, qth, qtl);
    headsplit_qk<<<512, 256>>>(kh, kth, ktl);
    headsplit_vT<<<dim3(SQL/32, 2, BH), T256>>>(vh, vth, vtl);

    // ---- scores = (Q @ K^T)/8 ----
    gemm_tc<128,false,true,false,false><<<dim3(SKV/128, SQL/128, BH), T256, SM128>>>(
        qth, qtl, kth, ktl, DH,
        (long long)SQL*DH, (long long)SKV*DH, (long long)SQL*SKV,
        nullptr, nullptr, nullptr, 0, 0.125f, sc, nullptr, nullptr, SKV);

    softmax_split<<<dim3(SQL, BH), T256>>>();

    // ---- O = attn @ V ----
    gemm_tc<64,false,true,false,false><<<dim3(1, SQL/128, BH), T256, SM64>>>(
        pph, ppl, vth, vtl, SKV,
        (long long)SQL*SKV, (long long)DH*SKV, (long long)SQL*DH,
        nullptr, nullptr, nullptr, 0, 1.f, ot, nullptr, nullptr, DH);

    head_merge_split<<<512, 256>>>(ot, oh, ol);

    // ---- out-projection + adapter ----
    gemm_tc<128,false,false,true,false><<<GLIN, T256, SM128>>>(
        oh, ol, woh, wol, DIM, 0, 0, 0, nullptr, nullptr, b_out, 0, 1.f, nullptr, oph, opl, DIM);
    gemm_tc<128,false,true,false,false><<<GLIN, T256, SM128>>>(
        oph, opl, wah, wal, DIM, 0, 0, 0, nullptr, nullptr, ba, 0, 1.f, a, nullptr, nullptr, DIM);

    // ---- LN1 (+residual) -> x fp32 + split ----
    ln_res_split<<<NTOK, T256>>>(a, query, ln1g, ln1b, x, xh, xl);

    // ---- gating ----
    gating<<<NTOK, T256>>>(Wg);

    // ---- MoE expert FFNs ----
    gemm_tc<128,true,false,true,true><<<dim3(HDIM/128, NTOK/128, NEXP), T256, SM128>>>(
        xh, xl, e1h, e1l, DIM,
        0, (long long)HDIM*DIM, (long long)NTOK*HDIM,
        tokp, cntp, eb1, HDIM, 1.f, nullptr, hhh, hhl, HDIM);
    gemm_tc<128,false,true,false,false><<<dim3(DIM/128, NTOK/128, NEXP), T256, SM128>>>(
        hhh, hhl, e2h, e2l, HDIM,
        (long long)NTOK*HDIM, (long long)DIM*HDIM, (long long)NTOK*DIM,
        nullptr, cntp, eb2, DIM, 1.f, e2p, nullptr, nullptr, DIM);

    // ---- fused combine + final LN -> output, then aux scalar ----
    combine_ln<<<NTOK, T256>>>(ln2g, ln2b, out);
    aux_kernel<<<1, 256>>>(out, out_size);
}

// round 9
// speedup vs baseline: 2.5654x; 1.1414x over previous
#include <cuda_runtime.h>
#include <cuda_bf16.h>
#include <math.h>
#include <stddef.h>
#include <stdint.h>

// ---------------- problem constants ----------------
#define BATCH 4
#define SQL   1024
#define SKV   1024
#define DIM   1024
#define NH    16
#define DH    64
#define NEXP  8
#define HDIM  4096
#define NTOK  (BATCH*SQL)       // 4096
#define BH    (BATCH*NH)        // 64
#define OUT_MAIN (NTOK*DIM)
#define THRESH 0.05f
#define COEF   0.01f
#define KCH   64                // K chunk
#define RS    72                // smem row stride in u16 (64 data + 8 pad)

typedef unsigned short u16;
typedef unsigned int   u32;

// ---------------- static device scratch (fp32) ----------------
__device__ float g_qh[NTOK*DIM];
__device__ float g_kh[NTOK*DIM];
__device__ float g_vh[NTOK*DIM];
__device__ float g_sc[(size_t)BH*SQL*SKV];      // 256 MB
__device__ float g_ot[NTOK*DIM];
__device__ float g_a [NTOK*DIM];
__device__ float g_x [NTOK*DIM];
__device__ float g_e2[(size_t)NEXP*NTOK*DIM];   // 128 MB
__device__ int   g_cnt[NEXP];
__device__ int   g_tok[NEXP*NTOK];
__device__ float g_probs[NTOK*NEXP];
__device__ int   g_tcnt[NTOK];
__device__ int   g_te  [NTOK*3];
__device__ int   g_tslot[NTOK*3];
__device__ float g_tgate[NTOK*3];

// ---------------- bf16 hi/lo split buffers ----------------
__device__ u16 s_query_h[NTOK*DIM], s_query_l[NTOK*DIM];
__device__ u16 s_kv_h[NTOK*DIM],    s_kv_l[NTOK*DIM];
__device__ u16 s_q_h[NTOK*DIM],     s_q_l[NTOK*DIM];
__device__ u16 s_k_h[NTOK*DIM],     s_k_l[NTOK*DIM];
__device__ u16 s_v_h[NTOK*DIM],     s_v_l[NTOK*DIM];
__device__ u16 s_qt_h[NTOK*DIM],    s_qt_l[NTOK*DIM];
__device__ u16 s_kt_h[NTOK*DIM],    s_kt_l[NTOK*DIM];
__device__ u16 s_vt_h[NTOK*DIM],    s_vt_l[NTOK*DIM];    // [bh][dh][skv]
__device__ u16 s_o_h[NTOK*DIM],     s_o_l[NTOK*DIM];
__device__ u16 s_op_h[NTOK*DIM],    s_op_l[NTOK*DIM];
__device__ u16 s_x_h[NTOK*DIM],     s_x_l[NTOK*DIM];
__device__ u16 s_p_h[(size_t)BH*SQL*SKV], s_p_l[(size_t)BH*SQL*SKV];
__device__ u16 s_hh [(size_t)NEXP*NTOK*HDIM], s_hl[(size_t)NEXP*NTOK*HDIM];
// weights
__device__ u16 s_wq_h[DIM*DIM],   s_wq_l[DIM*DIM];
__device__ u16 s_wk_h[DIM*DIM],   s_wk_l[DIM*DIM];
__device__ u16 s_wv_h[DIM*DIM],   s_wv_l[DIM*DIM];
__device__ u16 s_win_h[3*DIM*DIM],s_win_l[3*DIM*DIM];
__device__ u16 s_wo_h[DIM*DIM],   s_wo_l[DIM*DIM];
__device__ u16 s_wa_h[DIM*DIM],   s_wa_l[DIM*DIM];
__device__ u16 s_e1_h[(size_t)NEXP*HDIM*DIM], s_e1_l[(size_t)NEXP*HDIM*DIM]; // [e][n=HDIM][k=DIM]
__device__ u16 s_e2_h[(size_t)NEXP*DIM*HDIM], s_e2_l[(size_t)NEXP*DIM*HDIM]; // [e][n=DIM][k=HDIM]

// ---------------- helpers ----------------
__device__ __forceinline__ u16 f2bf(float v) { __nv_bfloat16 b = __float2bfloat16(v); return *(u16*)&b; }
__device__ __forceinline__ float bf2f(u16 u) { __nv_bfloat16 b; *(u16*)&b = u; return __bfloat162float(b); }
__device__ __forceinline__ void split2(float v, u16& h, u16& l) {
    u16 hu = f2bf(v); h = hu; l = f2bf(v - bf2f(hu));
}
__device__ __forceinline__ float gelu_exact(float v) {
    return 0.5f * v * (1.0f + erff(v * 0.70710678118654752f));
}
__device__ __forceinline__ u32 smem_u32(const void* p) {
    u32 a;
    asm("{ .reg .u64 t; cvta.to.shared.u64 t, %1; cvt.u32.u64 %0, t; }" : "=r"(a) : "l"(p));
    return a;
}
__device__ __forceinline__ float blk_reduce_sum(float v, float* sm) {
    int lane = threadIdx.x & 31, w = threadIdx.x >> 5;
    #pragma unroll
    for (int o = 16; o; o >>= 1) v += __shfl_down_sync(0xffffffffu, v, o);
    if (!lane) sm[w] = v;
    __syncthreads();
    if (threadIdx.x < 32) {
        v = (threadIdx.x < 8) ? sm[threadIdx.x] : 0.f;
        #pragma unroll
        for (int o = 4; o; o >>= 1) v += __shfl_down_sync(0xffffffffu, v, o);
        if (!threadIdx.x) sm[0] = v;
    }
    __syncthreads();
    float r = sm[0];
    __syncthreads();
    return r;
}
__device__ __forceinline__ float blk_reduce_max(float v, float* sm) {
    int lane = threadIdx.x & 31, w = threadIdx.x >> 5;
    #pragma unroll
    for (int o = 16; o; o >>= 1) v = fmaxf(v, __shfl_down_sync(0xffffffffu, v, o));
    if (!lane) sm[w] = v;
    __syncthreads();
    if (threadIdx.x < 32) {
        v = (threadIdx.x < 8) ? sm[threadIdx.x] : -1e30f;
        #pragma unroll
        for (int o = 4; o; o >>= 1) v = fmaxf(v, __shfl_down_sync(0xffffffffu, v, o));
        if (!threadIdx.x) sm[0] = v;
    }
    __syncthreads();
    float r = sm[0];
    __syncthreads();
    return r;
}

__device__ __forceinline__ void mma_bf16(float* c, const u32* a, const u32* b) {
    asm volatile(
        "mma.sync.aligned.m16n8k16.row.col.f32.bf16.bf16.f32 "
        "{%0,%1,%2,%3}, {%4,%5,%6,%7}, {%8,%9}, {%0,%1,%2,%3};"
        : "+f"(c[0]), "+f"(c[1]), "+f"(c[2]), "+f"(c[3])
        : "r"(a[0]), "r"(a[1]), "r"(a[2]), "r"(a[3]), "r"(b[0]), "r"(b[1]));
}

#define CP16(dst, src) \
    asm volatile("cp.async.cg.shared.global [%0], [%1], 16;" :: "r"(dst), "l"(src) : "memory")
#define CP_COMMIT() asm volatile("cp.async.commit_group;" ::: "memory")
#define CP_WAIT1()  asm volatile("cp.async.wait_group 1;" ::: "memory")
#define LDMX4(r, addr) \
    asm volatile("ldmatrix.sync.aligned.m8n8.x4.shared.b16 {%0,%1,%2,%3}, [%4];" \
        : "=r"((r)[0]), "=r"((r)[1]), "=r"((r)[2]), "=r"((r)[3]) : "r"(addr))

// =====================================================================
// bf16-split tensor-core GEMM via mma.sync + cp.async pipeline + ldmatrix.
// C[z] = alpha*(A@B^T) + bias. A,B bf16 hi/lo pairs, K-major rows (stride K).
// M tile 128, N tile BN, K chunks of 64. 8 warps (4x2), warp tile 32 x BN/2.
// =====================================================================
template<int BN, bool GELU_, bool WF32, bool WSPLIT, bool GATHER>
__global__ __launch_bounds__(256, 1)
void gemm_tc(const u16* __restrict__ Ah_, const u16* __restrict__ Al_,
             const u16* __restrict__ Bh_, const u16* __restrict__ Bl_,
             int K, long long As, long long Bs, long long Cs,
             const int* __restrict__ rowmap, const int* __restrict__ cntArr,
             const float* __restrict__ bias, long long biasStride, float alpha,
             float* __restrict__ Cf, u16* __restrict__ Ch, u16* __restrict__ Cl, int ldc)
{
    extern __shared__ __align__(16) u16 smem[];
    const int z = blockIdx.z;
    const int cnt = cntArr ? cntArr[z] : 0x40000000;
    const int m0 = blockIdx.y << 7;
    if (m0 >= cnt) return;
    const int n0 = blockIdx.x * BN;

    const u16* Ah = Ah_ + (size_t)z * As;
    const u16* Al = Al_ + (size_t)z * As;
    const u16* Bh = Bh_ + (size_t)z * Bs;
    const u16* Bl = Bl_ + (size_t)z * Bs;
    if (WF32)   Cf += (size_t)z * Cs;
    if (WSPLIT) { Ch += (size_t)z * Cs; Cl += (size_t)z * Cs; }
    const float* bptr = bias ? bias + (size_t)z * biasStride : nullptr;
    const int* rmap = GATHER ? (rowmap + (size_t)z * NTOK) : nullptr;

    constexpr int ASZ = 128 * RS;            // u16 per A tile
    constexpr int BSZ = BN * RS;
    constexpr int STG = 2 * ASZ + 2 * BSZ;   // u16 per stage
    constexpr int WN  = BN / 2;
    constexpr int NF  = WN / 8;
    constexpr int NBI = BN / 32;             // B loader iterations

    const int tid = threadIdx.x;
    const int wid = tid >> 5, lane = tid & 31;
    const int wm = wid & 3, wn = wid >> 2;
    const u32 sb = smem_u32(smem);

    // ---- per-thread global-load bookkeeping (hoisted out of chunk loop) ----
    const u16* aSrcH[4]; const u16* aSrcL[4]; u32 aDstB[4];
    #pragma unroll
    for (int it = 0; it < 4; it++) {
        int idx = tid + it * 256;
        int row = idx >> 3, blk = idx & 7;
        int srow;
        if (GATHER) { int gm = m0 + row; if (gm >= cnt) gm = cnt - 1; srow = rmap[gm]; }
        else srow = m0 + row;
        aSrcH[it] = Ah + (size_t)srow * K + blk * 8;
        aSrcL[it] = Al + (size_t)srow * K + blk * 8;
        aDstB[it] = (u32)(row * RS + blk * 8) * 2;
    }
    const u16* bSrcH[4]; const u16* bSrcL[4]; u32 bDstB[4];
    #pragma unroll
    for (int it = 0; it < NBI; it++) {
        int idx = tid + it * 256;
        int row = idx >> 3, blk = idx & 7;
        bSrcH[it] = Bh + (size_t)(n0 + row) * K + blk * 8;
        bSrcL[it] = Bl + (size_t)(n0 + row) * K + blk * 8;
        bDstB[it] = (u32)(2 * ASZ + row * RS + blk * 8) * 2;
    }

    auto load_chunk = [&](int c, int s) {
        const int k0 = c * KCH;
        const u32 base = sb + (u32)(s * STG) * 2;
        #pragma unroll
        for (int it = 0; it < 4; it++) {
            CP16(base + aDstB[it],            aSrcH[it] + k0);
            CP16(base + aDstB[it] + ASZ * 2,  aSrcL[it] + k0);
        }
        #pragma unroll
        for (int it = 0; it < NBI; it++) {
            CP16(base + bDstB[it],            bSrcH[it] + k0);
            CP16(base + bDstB[it] + BSZ * 2,  bSrcL[it] + k0);
        }
    };

    // ---- per-lane ldmatrix address components ----
    const int aRowO = ((lane >> 3) & 1) * 8 + (lane & 7);
    const int aKO   = ((lane >> 4) & 1) * 8;
    const int bRowO = ((lane >> 4) & 1) * 8 + (lane & 7);
    const int bKO   = ((lane >> 3) & 1) * 8;

    float acc[2][NF][4];
    #pragma unroll
    for (int i = 0; i < 2; i++)
        #pragma unroll
        for (int j = 0; j < NF; j++)
            #pragma unroll
            for (int q = 0; q < 4; q++) acc[i][j][q] = 0.f;

    const int nch = K / KCH;

    // ---- pipeline prologue: 2 groups always committed ----
    load_chunk(0, 0);
    CP_COMMIT();
    if (nch > 1) load_chunk(1, 1);
    CP_COMMIT();

    for (int c = 0; c < nch; c++) {
        CP_WAIT1();              // exactly 1 newer group pending -> chunk c ready
        __syncthreads();

        const u32 stB = sb + (u32)((c & 1) * STG) * 2;
        #pragma unroll
        for (int ks = 0; ks < 4; ks++) {
            u32 ah[2][4], al[2][4];
            #pragma unroll
            for (int mi = 0; mi < 2; mi++) {
                u32 ad = stB + (u32)((wm * 32 + mi * 16 + aRowO) * RS + ks * 16 + aKO) * 2;
                LDMX4(ah[mi], ad);
                LDMX4(al[mi], ad + ASZ * 2);
            }
            u32 bh[NF][2], bl[NF][2];
            #pragma unroll
            for (int j = 0; j < NF / 2; j++) {
                u32 bd = stB + (u32)(2 * ASZ + (wn * WN + j * 16 + bRowO) * RS + ks * 16 + bKO) * 2;
                u32 t[4];
                LDMX4(t, bd);
                bh[2*j][0] = t[0]; bh[2*j][1] = t[1];
                bh[2*j+1][0] = t[2]; bh[2*j+1][1] = t[3];
                LDMX4(t, bd + BSZ * 2);
                bl[2*j][0] = t[0]; bl[2*j][1] = t[1];
                bl[2*j+1][0] = t[2]; bl[2*j+1][1] = t[3];
            }
            #pragma unroll
            for (int mi = 0; mi < 2; mi++)
                #pragma unroll
                for (int nf = 0; nf < NF; nf++) {
                    mma_bf16(acc[mi][nf], ah[mi], bh[nf]);
                    mma_bf16(acc[mi][nf], ah[mi], bl[nf]);
                    mma_bf16(acc[mi][nf], al[mi], bh[nf]);
                }
        }
        __syncthreads();         // all warps done with stage c&1
        if (c + 2 < nch) load_chunk(c + 2, c & 1);
        CP_COMMIT();             // commit every iter (group accounting stays exact)
    }

    // ---- epilogue ----
    const int gid = lane >> 2, tg = lane & 3;
    #pragma unroll
    for (int mi = 0; mi < 2; mi++) {
        #pragma unroll
        for (int nf = 0; nf < NF; nf++) {
            int mA  = m0 + wm * 32 + mi * 16 + gid;
            int col = n0 + wn * WN + nf * 8 + tg * 2;
            #pragma unroll
            for (int half = 0; half < 2; half++) {
                int m = mA + half * 8;
                if (m < cnt) {
                    float v0 = acc[mi][nf][half * 2 + 0] * alpha;
                    float v1 = acc[mi][nf][half * 2 + 1] * alpha;
                    if (bptr) { v0 += bptr[col]; v1 += bptr[col + 1]; }
                    if (GELU_) { v0 = gelu_exact(v0); v1 = gelu_exact(v1); }
                    size_t o = (size_t)m * ldc + col;
                    if (WF32) { Cf[o] = v0; Cf[o + 1] = v1; }
                    if (WSPLIT) {
                        u16 h0, l0, h1, l1;
                        split2(v0, h0, l0); split2(v1, h1, l1);
                        Ch[o] = h0; Ch[o + 1] = h1;
                        Cl[o] = l0; Cl[o + 1] = l1;
                    }
                }
            }
        }
    }
}

// ---------------- conversion kernels ----------------
__global__ void split_f32(const float* __restrict__ s, u16* __restrict__ h, u16* __restrict__ l, int n) {
    for (int i = blockIdx.x * blockDim.x + threadIdx.x; i * 4 < n; i += gridDim.x * blockDim.x) {
        float4 v = ((const float4*)s)[i];
        u16 hh[4], ll[4];
        split2(v.x, hh[0], ll[0]); split2(v.y, hh[1], ll[1]);
        split2(v.z, hh[2], ll[2]); split2(v.w, hh[3], ll[3]);
        *(uint2*)&h[4 * i] = *(uint2*)hh;
        *(uint2*)&l[4 * i] = *(uint2*)ll;
    }
}

__global__ void transpose_split(const float* __restrict__ s, u16* __restrict__ oh, u16* __restrict__ ol,
                                int R, int C) {
    __shared__ float t[32][33];
    size_t zo = (size_t)blockIdx.z * R * C;
    const float* src = s + zo;
    int c0 = blockIdx.x * 32, r0 = blockIdx.y * 32;
    int tx = threadIdx.x & 31, ty = threadIdx.x >> 5;
    #pragma unroll
    for (int dy = 0; dy < 32; dy += 8)
        t[ty + dy][tx] = src[(size_t)(r0 + ty + dy) * C + c0 + tx];
    __syncthreads();
    #pragma unroll
    for (int dy = 0; dy < 32; dy += 8) {
        float v = t[tx][ty + dy];
        size_t o = zo + (size_t)(c0 + ty + dy) * R + r0 + tx;
        u16 hh, ll; split2(v, hh, ll);
        oh[o] = hh; ol[o] = ll;
    }
}

__global__ void headsplit_qk(const float* __restrict__ in, u16* __restrict__ oh, u16* __restrict__ ol) {
    for (int i = blockIdx.x * blockDim.x + threadIdx.x; i < NTOK * DIM; i += gridDim.x * blockDim.x) {
        int d = i & 63, s = (i >> 6) & 1023, h = (i >> 16) & 15, b = i >> 20;
        float v = in[(size_t)((b << 10) + s) * DIM + (h << 6) + d];
        u16 hh, ll; split2(v, hh, ll);
        oh[i] = hh; ol[i] = ll;
    }
}

__global__ void headsplit_vT(const float* __restrict__ in, u16* __restrict__ oh, u16* __restrict__ ol) {
    __shared__ float t[32][33];
    int z = blockIdx.z;
    int b = z >> 4, h = z & 15;
    int s0 = blockIdx.x * 32, d0 = blockIdx.y * 32;
    int tx = threadIdx.x & 31, ty = threadIdx.x >> 5;
    #pragma unroll
    for (int dy = 0; dy < 32; dy += 8)
        t[ty + dy][tx] = in[(size_t)((b << 10) + s0 + ty + dy) * DIM + h * 64 + d0 + tx];
    __syncthreads();
    #pragma unroll
    for (int dy = 0; dy < 32; dy += 8) {
        float v = t[tx][ty + dy];
        size_t o = (size_t)(z * 64 + d0 + ty + dy) * 1024 + s0 + tx;
        u16 hh, ll; split2(v, hh, ll);
        oh[o] = hh; ol[o] = ll;
    }
}

__global__ void softmax_split() {
    const size_t ro = ((size_t)blockIdx.y * SQL + blockIdx.x) * SKV;
    const float* r = g_sc + ro;
    __shared__ float sm[32];
    int t = threadIdx.x;
    float v[4];
    float mx = -1e30f;
    #pragma unroll
    for (int j = 0; j < 4; j++) { v[j] = r[t + j * 256]; mx = fmaxf(mx, v[j]); }
    mx = blk_reduce_max(mx, sm);
    float s = 0.f;
    #pragma unroll
    for (int j = 0; j < 4; j++) { v[j] = __expf(v[j] - mx); s += v[j]; }
    s = blk_reduce_sum(s, sm);
    float inv = 1.f / s;
    #pragma unroll
    for (int j = 0; j < 4; j++) {
        float p = v[j] * inv;
        u16 hh, ll; split2(p, hh, ll);
        s_p_h[ro + t + j * 256] = hh;
        s_p_l[ro + t + j * 256] = ll;
    }
}

__global__ void head_merge_split(const float* __restrict__ in, u16* __restrict__ oh, u16* __restrict__ ol) {
    for (int i = blockIdx.x * blockDim.x + threadIdx.x; i < NTOK * DIM; i += gridDim.x * blockDim.x) {
        int col = i & 1023, h = col >> 6, d = col & 63;
        int s = (i >> 10) & 1023, b = i >> 20;
        float v = in[(size_t)(((b << 4) + h) * 1024 + s) * 64 + d];
        u16 hh, ll; split2(v, hh, ll);
        oh[i] = hh; ol[i] = ll;
    }
}

__global__ void ln_res_split(const float* __restrict__ a, const float* __restrict__ res,
                             const float* __restrict__ g, const float* __restrict__ b,
                             float* __restrict__ of, u16* __restrict__ oh, u16* __restrict__ ol) {
    __shared__ float sm[32];
    const size_t base = (size_t)blockIdx.x * DIM;
    int t = threadIdx.x;
    float v[4];
    float s = 0.f;
    #pragma unroll
    for (int j = 0; j < 4; j++) {
        int c = t + j * 256;
        v[j] = a[base + c] + res[base + c];
        s += v[j];
    }
    s = blk_reduce_sum(s, sm);
    float mean = s * (1.0f / DIM);
    float s2 = 0.f;
    #pragma unroll
    for (int j = 0; j < 4; j++) { float d = v[j] - mean; s2 += d * d; }
    s2 = blk_reduce_sum(s2, sm);
    float rs = rsqrtf(s2 * (1.0f / DIM) + 1e-5f);
    #pragma unroll
    for (int j = 0; j < 4; j++) {
        int c = t + j * 256;
        float o = (v[j] - mean) * rs * g[c] + b[c];
        of[base + c] = o;
        u16 hh, ll; split2(o, hh, ll);
        oh[base + c] = hh; ol[base + c] = ll;
    }
}

__global__ void combine_ln(const float* __restrict__ g, const float* __restrict__ b,
                           float* __restrict__ out) {
    __shared__ float sm[32];
    const int tok = blockIdx.x;
    const size_t base = (size_t)tok * DIM;
    int t = threadIdx.x;
    float v[4];
    #pragma unroll
    for (int j = 0; j < 4; j++) v[j] = g_x[base + t + j * 256];
    const int nl = g_tcnt[tok];
    for (int l = 0; l < nl; l++) {
        int   e    = g_te[tok * 3 + l];
        int   slot = g_tslot[tok * 3 + l];
        float gt   = g_tgate[tok * 3 + l];
        const float* row = g_e2 + ((size_t)e * NTOK + slot) * DIM;
        #pragma unroll
        for (int j = 0; j < 4; j++) v[j] += gt * row[t + j * 256];
    }
    float s = 0.f;
    #pragma unroll
    for (int j = 0; j < 4; j++) s += v[j];
    s = blk_reduce_sum(s, sm);
    float mean = s * (1.0f / DIM);
    float s2 = 0.f;
    #pragma unroll
    for (int j = 0; j < 4; j++) { float d = v[j] - mean; s2 += d * d; }
    s2 = blk_reduce_sum(s2, sm);
    float rs = rsqrtf(s2 * (1.0f / DIM) + 1e-5f);
    #pragma unroll
    for (int j = 0; j < 4; j++) {
        int c = t + j * 256;
        out[base + c] = (v[j] - mean) * rs * g[c] + b[c];
    }
}

__global__ void gating(const float* __restrict__ Wg) {
    __shared__ float logits[NEXP];
    const int tok = blockIdx.x;
    const float* xr = g_x + (size_t)tok * DIM;
    int w = threadIdx.x >> 5, lane = threadIdx.x & 31;
    float s = 0.f;
    for (int i = lane; i < DIM; i += 32) s += xr[i] * Wg[i * NEXP + w];
    #pragma unroll
    for (int o = 16; o; o >>= 1) s += __shfl_down_sync(0xffffffffu, s, o);
    if (!lane) logits[w] = s;
    __syncthreads();
    if (threadIdx.x == 0) {
        float p[NEXP];
        float mx = -1e30f;
        for (int e = 0; e < NEXP; e++) mx = fmaxf(mx, logits[e]);
        float sum = 0.f;
        for (int e = 0; e < NEXP; e++) { p[e] = __expf(logits[e] - mx); sum += p[e]; }
        float inv = 1.f / sum;
        for (int e = 0; e < NEXP; e++) { p[e] *= inv; g_probs[tok * NEXP + e] = p[e]; }
        int i0 = 0;
        for (int e = 1; e < NEXP; e++) if (p[e] > p[i0]) i0 = e;
        int i1 = -1;
        for (int e = 0; e < NEXP; e++) if (e != i0 && (i1 < 0 || p[e] > p[i1])) i1 = e;
        int i2 = -1;
        for (int e = 0; e < NEXP; e++) if (e != i0 && e != i1 && (i2 < 0 || p[e] > p[i2])) i2 = e;
        int   ids[3] = { i0, i1, i2 };
        float gts[3] = { p[i0],
                         (p[i1] >= THRESH) ? p[i1] : 0.f,
                         (p[i2] >= THRESH) ? p[i2] : 0.f };
        int nl = 0;
        #pragma unroll
        for (int j = 0; j < 3; j++) {
            if (gts[j] > 0.f) {
                int slot = atomicAdd(&g_cnt[ids[j]], 1);
                g_tok  [ids[j] * NTOK + slot] = tok;
                g_te   [tok * 3 + nl] = ids[j];
                g_tslot[tok * 3 + nl] = slot;
                g_tgate[tok * 3 + nl] = gts[j];
                nl++;
            }
        }
        g_tcnt[tok] = nl;
    }
}

__global__ void zero_small() {
    int t = threadIdx.x;
    if (t < NEXP) g_cnt[t] = 0;
}
__global__ void aux_kernel(float* __restrict__ out, int out_size) {
    if (out_size <= OUT_MAIN) return;
    __shared__ float sm[32];
    int t = threadIdx.x;
    float total = 0.f;
    for (int e = 0; e < NEXP; e++) {
        float s = 0.f;
        for (int tok = t; tok < NTOK; tok += 256) s += g_probs[tok * NEXP + e];
        s = blk_reduce_sum(s, sm);
        if (t == 0) total += ((float)g_cnt[e] / (float)NTOK) * (s / (float)NTOK);
    }
    if (t == 0) out[OUT_MAIN] = COEF * (float)NEXP * total;
}

// ---------------- host launcher ----------------
#define GETSYM(var, sym) do { cudaGetSymbolAddress((void**)&(var), sym); } while (0)

extern "C" void kernel_launch(void* const* d_in, const int* in_sizes, int n_in,
                              void* d_out, int out_size)
{
    (void)in_sizes; (void)n_in;
    const float* query  = (const float*)d_in[0];
    const float* keyval = (const float*)d_in[1];
    const float* Wq = (const float*)d_in[2];  const float* bq = (const float*)d_in[3];
    const float* Wk = (const float*)d_in[4];  const float* bk = (const float*)d_in[5];
    const float* Wv = (const float*)d_in[6];  const float* bv = (const float*)d_in[7];
    const float* W_in  = (const float*)d_in[8];  const float* b_in  = (const float*)d_in[9];
    const float* W_out = (const float*)d_in[10]; const float* b_out = (const float*)d_in[11];
    const float* Wa = (const float*)d_in[12]; const float* ba = (const float*)d_in[13];
    const float* ln1g = (const float*)d_in[14]; const float* ln1b = (const float*)d_in[15];
    const float* Wg = (const float*)d_in[16];
    const float* ew1 = (const float*)d_in[17]; const float* eb1 = (const float*)d_in[18];
    const float* ew2 = (const float*)d_in[19]; const float* eb2 = (const float*)d_in[20];
    const float* ln2g = (const float*)d_in[21]; const float* ln2b = (const float*)d_in[22];
    float* out = (float*)d_out;

    float *qh, *kh, *vh, *sc, *ot, *a, *x, *e2p;
    GETSYM(qh, g_qh); GETSYM(kh, g_kh); GETSYM(vh, g_vh);
    GETSYM(sc, g_sc); GETSYM(ot, g_ot); GETSYM(a, g_a); GETSYM(x, g_x);
    GETSYM(e2p, g_e2);
    u16 *qyh,*qyl,*kvh,*kvl,*qsh,*qsl,*ksh,*ksl,*vsh,*vsl;
    u16 *qth,*qtl,*kth,*ktl,*vth,*vtl,*oh,*ol,*oph,*opl,*xh,*xl,*pph,*ppl,*hhh,*hhl;
    u16 *wqh,*wql,*wkh,*wkl,*wvh,*wvl,*winh,*winl,*woh,*wol,*wah,*wal,*e1h,*e1l,*e2h,*e2l;
    GETSYM(qyh, s_query_h); GETSYM(qyl, s_query_l);
    GETSYM(kvh, s_kv_h);    GETSYM(kvl, s_kv_l);
    GETSYM(qsh, s_q_h);  GETSYM(qsl, s_q_l);
    GETSYM(ksh, s_k_h);  GETSYM(ksl, s_k_l);
    GETSYM(vsh, s_v_h);  GETSYM(vsl, s_v_l);
    GETSYM(qth, s_qt_h); GETSYM(qtl, s_qt_l);
    GETSYM(kth, s_kt_h); GETSYM(ktl, s_kt_l);
    GETSYM(vth, s_vt_h); GETSYM(vtl, s_vt_l);
    GETSYM(oh,  s_o_h);  GETSYM(ol,  s_o_l);
    GETSYM(oph, s_op_h); GETSYM(opl, s_op_l);
    GETSYM(xh,  s_x_h);  GETSYM(xl,  s_x_l);
    GETSYM(pph, s_p_h);  GETSYM(ppl, s_p_l);
    GETSYM(hhh, s_hh);   GETSYM(hhl, s_hl);
    GETSYM(wqh, s_wq_h); GETSYM(wql, s_wq_l);
    GETSYM(wkh, s_wk_h); GETSYM(wkl, s_wk_l);
    GETSYM(wvh, s_wv_h); GETSYM(wvl, s_wv_l);
    GETSYM(winh, s_win_h); GETSYM(winl, s_win_l);
    GETSYM(woh, s_wo_h); GETSYM(wol, s_wo_l);
    GETSYM(wah, s_wa_h); GETSYM(wal, s_wa_l);
    GETSYM(e1h, s_e1_h); GETSYM(e1l, s_e1_l);
    GETSYM(e2h, s_e2_h); GETSYM(e2l, s_e2_l);
    int *tokp; GETSYM(tokp, g_tok);
    int *cntp; GETSYM(cntp, g_cnt);

    // dynamic smem: 2 stages * (2*A + 2*B) tiles, u16 with RS=72 row stride
    const int SM128 = 2 * (2 * 128 * RS + 2 * 128 * RS) * 2;   // 147456 B
    const int SM64  = 2 * (2 * 128 * RS + 2 * 64  * RS) * 2;   // 110592 B
    cudaFuncSetAttribute((const void*)gemm_tc<128,false,false,true ,false>, cudaFuncAttributeMaxDynamicSharedMemorySize, SM128);
    cudaFuncSetAttribute((const void*)gemm_tc<128,false,true ,false,false>, cudaFuncAttributeMaxDynamicSharedMemorySize, SM128);
    cudaFuncSetAttribute((const void*)gemm_tc<64 ,false,true ,false,false>, cudaFuncAttributeMaxDynamicSharedMemorySize, SM64);
    cudaFuncSetAttribute((const void*)gemm_tc<128,true ,false,true ,true >, cudaFuncAttributeMaxDynamicSharedMemorySize, SM128);

    const dim3 T256(256);

    zero_small<<<1, 32>>>();

    // ---- input / weight conversions ----
    split_f32<<<1024, 256>>>(query,  qyh, qyl, NTOK*DIM);
    split_f32<<<1024, 256>>>(keyval, kvh, kvl, NTOK*DIM);
    split_f32<<<512, 256>>>(Wq, wqh, wql, DIM*DIM);
    split_f32<<<512, 256>>>(Wk, wkh, wkl, DIM*DIM);
    split_f32<<<512, 256>>>(Wv, wvh, wvl, DIM*DIM);
    split_f32<<<1024, 256>>>(W_in, winh, winl, 3*DIM*DIM);
    split_f32<<<512, 256>>>(W_out, woh, wol, DIM*DIM);
    split_f32<<<512, 256>>>(Wa, wah, wal, DIM*DIM);
    transpose_split<<<dim3(HDIM/32, DIM/32, NEXP), T256>>>(ew1, e1h, e1l, DIM, HDIM);   // [D,H] -> [H,D]
    transpose_split<<<dim3(DIM/32, HDIM/32, NEXP), T256>>>(ew2, e2h, e2l, HDIM, DIM);   // [H,D] -> [D,H]

    const dim3 GLIN(DIM/128, NTOK/128, 1);

    // ---- outer Q/K/V linears (split output) ----
    gemm_tc<128,false,false,true,false><<<GLIN, T256, SM128>>>(
        qyh, qyl, wqh, wql, DIM, 0, 0, 0, nullptr, nullptr, bq, 0, 1.f, nullptr, qsh, qsl, DIM);
    gemm_tc<128,false,false,true,false><<<GLIN, T256, SM128>>>(
        kvh, kvl, wkh, wkl, DIM, 0, 0, 0, nullptr, nullptr, bk, 0, 1.f, nullptr, ksh, ksl, DIM);
    gemm_tc<128,false,false,true,false><<<GLIN, T256, SM128>>>(
        kvh, kvl, wvh, wvl, DIM, 0, 0, 0, nullptr, nullptr, bv, 0, 1.f, nullptr, vsh, vsl, DIM);

    // ---- MHA in-projection (fp32 out) ----
    gemm_tc<128,false,true,false,false><<<GLIN, T256, SM128>>>(
        qsh, qsl, winh,              winl,              DIM, 0, 0, 0, nullptr, nullptr, b_in,        0, 1.f, qh, nullptr, nullptr, DIM);
    gemm_tc<128,false,true,false,false><<<GLIN, T256, SM128>>>(
        ksh, ksl, winh + DIM*DIM,    winl + DIM*DIM,    DIM, 0, 0, 0, nullptr, nullptr, b_in + DIM,  0, 1.f, kh, nullptr, nullptr, DIM);
    gemm_tc<128,false,true,false,false><<<GLIN, T256, SM128>>>(
        vsh, vsl, winh + 2*DIM*DIM,  winl + 2*DIM*DIM,  DIM, 0, 0, 0, nullptr, nullptr, b_in + 2*DIM,0, 1.f, vh, nullptr, nullptr, DIM);

    // ---- head reshape ----
    headsplit_qk<<<512, 256>>>(qh, qth, qtl);
    headsplit_qk<<<512, 256>>>(kh, kth, ktl);
    headsplit_vT<<<dim3(SQL/32, 2, BH), T256>>>(vh, vth, vtl);

    // ---- scores = (Q @ K^T)/8 ----
    gemm_tc<128,false,true,false,false><<<dim3(SKV/128, SQL/128, BH), T256, SM128>>>(
        qth, qtl, kth, ktl, DH,
        (long long)SQL*DH, (long long)SKV*DH, (long long)SQL*SKV,
        nullptr, nullptr, nullptr, 0, 0.125f, sc, nullptr, nullptr, SKV);

    softmax_split<<<dim3(SQL, BH), T256>>>();

    // ---- O = attn @ V ----
    gemm_tc<64,false,true,false,false><<<dim3(1, SQL/128, BH), T256, SM64>>>(
        pph, ppl, vth, vtl, SKV,
        (long long)SQL*SKV, (long long)DH*SKV, (long long)SQL*DH,
        nullptr, nullptr, nullptr, 0, 1.f, ot, nullptr, nullptr, DH);

    head_merge_split<<<512, 256>>>(ot, oh, ol);

    // ---- out-projection + adapter ----
    gemm_tc<128,false,false,true,false><<<GLIN, T256, SM128>>>(
        oh, ol, woh, wol, DIM, 0, 0, 0, nullptr, nullptr, b_out, 0, 1.f, nullptr, oph, opl, DIM);
    gemm_tc<128,false,true,false,false><<<GLIN, T256, SM128>>>(
        oph, opl, wah, wal, DIM, 0, 0, 0, nullptr, nullptr, ba, 0, 1.f, a, nullptr, nullptr, DIM);

    // ---- LN1 (+residual) -> x fp32 + split ----
    ln_res_split<<<NTOK, T256>>>(a, query, ln1g, ln1b, x, xh, xl);

    // ---- gating ----
    gating<<<NTOK, T256>>>(Wg);

    // ---- MoE expert FFNs ----
    gemm_tc<128,true,false,true,true><<<dim3(HDIM/128, NTOK/128, NEXP), T256, SM128>>>(
        xh, xl, e1h, e1l, DIM,
        0, (long long)HDIM*DIM, (long long)NTOK*HDIM,
        tokp, cntp, eb1, HDIM, 1.f, nullptr, hhh, hhl, HDIM);
    gemm_tc<128,false,true,false,false><<<dim3(DIM/128, NTOK/128, NEXP), T256, SM128>>>(
        hhh, hhl, e2h, e2l, HDIM,
        (long long)NTOK*HDIM, (long long)DIM*HDIM, (long long)NTOK*DIM,
        nullptr, cntp, eb2, DIM, 1.f, e2p, nullptr, nullptr, DIM);

    // ---- fused combine + final LN -> output, then aux scalar ----
    combine_ln<<<NTOK, T256>>>(ln2g, ln2b, out);
    aux_kernel<<<1, 256>>>(out, out_size);
}

// round 10
// speedup vs baseline: 2.6758x; 1.0430x over previous
#include <cuda_runtime.h>
#include <cuda_bf16.h>
#include <math.h>
#include <stddef.h>
#include <stdint.h>

// ---------------- problem constants ----------------
#define BATCH 4
#define SQL   1024
#define SKV   1024
#define DIM   1024
#define NH    16
#define DH    64
#define NEXP  8
#define HDIM  4096
#define NTOK  (BATCH*SQL)       // 4096
#define BH    (BATCH*NH)        // 64
#define OUT_MAIN (NTOK*DIM)
#define THRESH 0.05f
#define COEF   0.01f
#define KCH   64                // K chunk
#define RS    72                // smem row stride in u16 (64 data + 8 pad)

typedef unsigned short u16;
typedef unsigned int   u32;

// ---------------- static device scratch (fp32) ----------------
__device__ float g_qh[NTOK*DIM];
__device__ float g_kh[NTOK*DIM];
__device__ float g_vh[NTOK*DIM];
__device__ float g_sc[(size_t)BH*SQL*SKV];      // 256 MB
__device__ float g_ot[NTOK*DIM];
__device__ float g_a [NTOK*DIM];
__device__ float g_x [NTOK*DIM];
__device__ float g_e2[(size_t)NEXP*NTOK*DIM];   // 128 MB
__device__ int   g_cnt[NEXP];
__device__ int   g_tok[NEXP*NTOK];
__device__ float g_probs[NTOK*NEXP];
__device__ int   g_tcnt[NTOK];
__device__ int   g_te  [NTOK*3];
__device__ int   g_tslot[NTOK*3];
__device__ float g_tgate[NTOK*3];

// ---------------- bf16 hi/lo split buffers ----------------
__device__ u16 s_query_h[NTOK*DIM], s_query_l[NTOK*DIM];
__device__ u16 s_kv_h[NTOK*DIM],    s_kv_l[NTOK*DIM];
__device__ u16 s_q_h[NTOK*DIM],     s_q_l[NTOK*DIM];
__device__ u16 s_k_h[NTOK*DIM],     s_k_l[NTOK*DIM];
__device__ u16 s_v_h[NTOK*DIM],     s_v_l[NTOK*DIM];
__device__ u16 s_qt_h[NTOK*DIM],    s_qt_l[NTOK*DIM];
__device__ u16 s_kt_h[NTOK*DIM],    s_kt_l[NTOK*DIM];
__device__ u16 s_vt_h[NTOK*DIM],    s_vt_l[NTOK*DIM];    // [bh][dh][skv]
__device__ u16 s_o_h[NTOK*DIM],     s_o_l[NTOK*DIM];
__device__ u16 s_op_h[NTOK*DIM],    s_op_l[NTOK*DIM];
__device__ u16 s_x_h[NTOK*DIM],     s_x_l[NTOK*DIM];
__device__ u16 s_p_h[(size_t)BH*SQL*SKV], s_p_l[(size_t)BH*SQL*SKV];
__device__ u16 s_hh [(size_t)NEXP*NTOK*HDIM], s_hl[(size_t)NEXP*NTOK*HDIM];
// weights
__device__ u16 s_wq_h[DIM*DIM],   s_wq_l[DIM*DIM];
__device__ u16 s_wk_h[DIM*DIM],   s_wk_l[DIM*DIM];
__device__ u16 s_wv_h[DIM*DIM],   s_wv_l[DIM*DIM];
__device__ u16 s_win_h[3*DIM*DIM],s_win_l[3*DIM*DIM];
__device__ u16 s_wo_h[DIM*DIM],   s_wo_l[DIM*DIM];
__device__ u16 s_wa_h[DIM*DIM],   s_wa_l[DIM*DIM];
__device__ u16 s_e1_h[(size_t)NEXP*HDIM*DIM], s_e1_l[(size_t)NEXP*HDIM*DIM]; // [e][n=HDIM][k=DIM]
__device__ u16 s_e2_h[(size_t)NEXP*DIM*HDIM], s_e2_l[(size_t)NEXP*DIM*HDIM]; // [e][n=DIM][k=HDIM]

// ---------------- helpers ----------------
__device__ __forceinline__ u16 f2bf(float v) { __nv_bfloat16 b = __float2bfloat16(v); return *(u16*)&b; }
__device__ __forceinline__ float bf2f(u16 u) { __nv_bfloat16 b; *(u16*)&b = u; return __bfloat162float(b); }
__device__ __forceinline__ void split2(float v, u16& h, u16& l) {
    u16 hu = f2bf(v); h = hu; l = f2bf(v - bf2f(hu));
}
__device__ __forceinline__ float gelu_exact(float v) {
    return 0.5f * v * (1.0f + erff(v * 0.70710678118654752f));
}
__device__ __forceinline__ u32 smem_u32(const void* p) {
    u32 a;
    asm("{ .reg .u64 t; cvta.to.shared.u64 t, %1; cvt.u32.u64 %0, t; }" : "=r"(a) : "l"(p));
    return a;
}
__device__ __forceinline__ float blk_reduce_sum(float v, float* sm) {
    int lane = threadIdx.x & 31, w = threadIdx.x >> 5;
    #pragma unroll
    for (int o = 16; o; o >>= 1) v += __shfl_down_sync(0xffffffffu, v, o);
    if (!lane) sm[w] = v;
    __syncthreads();
    if (threadIdx.x < 32) {
        v = (threadIdx.x < 8) ? sm[threadIdx.x] : 0.f;
        #pragma unroll
        for (int o = 4; o; o >>= 1) v += __shfl_down_sync(0xffffffffu, v, o);
        if (!threadIdx.x) sm[0] = v;
    }
    __syncthreads();
    float r = sm[0];
    __syncthreads();
    return r;
}
__device__ __forceinline__ float blk_reduce_max(float v, float* sm) {
    int lane = threadIdx.x & 31, w = threadIdx.x >> 5;
    #pragma unroll
    for (int o = 16; o; o >>= 1) v = fmaxf(v, __shfl_down_sync(0xffffffffu, v, o));
    if (!lane) sm[w] = v;
    __syncthreads();
    if (threadIdx.x < 32) {
        v = (threadIdx.x < 8) ? sm[threadIdx.x] : -1e30f;
        #pragma unroll
        for (int o = 4; o; o >>= 1) v = fmaxf(v, __shfl_down_sync(0xffffffffu, v, o));
        if (!threadIdx.x) sm[0] = v;
    }
    __syncthreads();
    float r = sm[0];
    __syncthreads();
    return r;
}

__device__ __forceinline__ void mma_bf16(float* c, const u32* a, const u32* b) {
    asm volatile(
        "mma.sync.aligned.m16n8k16.row.col.f32.bf16.bf16.f32 "
        "{%0,%1,%2,%3}, {%4,%5,%6,%7}, {%8,%9}, {%0,%1,%2,%3};"
        : "+f"(c[0]), "+f"(c[1]), "+f"(c[2]), "+f"(c[3])
        : "r"(a[0]), "r"(a[1]), "r"(a[2]), "r"(a[3]), "r"(b[0]), "r"(b[1]));
}

#define CP16(dst, src) \
    asm volatile("cp.async.cg.shared.global [%0], [%1], 16;" :: "r"(dst), "l"(src) : "memory")
#define CP_COMMIT() asm volatile("cp.async.commit_group;" ::: "memory")
#define CP_WAIT1()  asm volatile("cp.async.wait_group 1;" ::: "memory")
#define LDMX4(r, addr) \
    asm volatile("ldmatrix.sync.aligned.m8n8.x4.shared.b16 {%0,%1,%2,%3}, [%4];" \
        : "=r"((r)[0]), "=r"((r)[1]), "=r"((r)[2]), "=r"((r)[3]) : "r"(addr))

// =====================================================================
// bf16-split tensor-core GEMM: C[z] = alpha*(A@B^T) + bias.
// A,B bf16 hi/lo pairs, K-major rows (stride K). M tile BM (128/256),
// N tile BN. 8 warps as 4(M) x 2(N); warp tile (BM/4) x (BN/2).
// cp.async 2-stage pipeline, ldmatrix fragment loads.
// =====================================================================
template<int BM, int BN, bool GELU_, bool WF32, bool WSPLIT, bool GATHER>
__global__ __launch_bounds__(256, 1)
void gemm_tc(const u16* __restrict__ Ah_, const u16* __restrict__ Al_,
             const u16* __restrict__ Bh_, const u16* __restrict__ Bl_,
             int K, long long As, long long Bs, long long Cs,
             const int* __restrict__ rowmap, const int* __restrict__ cntArr,
             const float* __restrict__ bias, long long biasStride, float alpha,
             float* __restrict__ Cf, u16* __restrict__ Ch, u16* __restrict__ Cl, int ldc)
{
    extern __shared__ __align__(16) u16 smem[];
    const int z = blockIdx.z;
    const int cnt = cntArr ? cntArr[z] : 0x40000000;
    const int m0 = blockIdx.y * BM;
    if (m0 >= cnt) return;
    const int n0 = blockIdx.x * BN;

    const u16* Ah = Ah_ + (size_t)z * As;
    const u16* Al = Al_ + (size_t)z * As;
    const u16* Bh = Bh_ + (size_t)z * Bs;
    const u16* Bl = Bl_ + (size_t)z * Bs;
    if (WF32)   Cf += (size_t)z * Cs;
    if (WSPLIT) { Ch += (size_t)z * Cs; Cl += (size_t)z * Cs; }
    const float* bptr = bias ? bias + (size_t)z * biasStride : nullptr;
    const int* rmap = GATHER ? (rowmap + (size_t)z * NTOK) : nullptr;

    constexpr int ASZ = BM * RS;             // u16 per A tile
    constexpr int BSZ = BN * RS;
    constexpr int STG = 2 * ASZ + 2 * BSZ;   // u16 per stage
    constexpr int WMR = BM / 4;              // warp rows
    constexpr int MI  = WMR / 16;            // m-frags per warp
    constexpr int WN  = BN / 2;
    constexpr int NF  = WN / 8;
    constexpr int AIT = BM / 32;             // A loader iterations
    constexpr int NBI = BN / 32;             // B loader iterations

    const int tid = threadIdx.x;
    const int wid = tid >> 5, lane = tid & 31;
    const int wm = wid & 3, wn = wid >> 2;
    const u32 sb = smem_u32(smem);

    // ---- per-thread global-load bookkeeping (u32 element offsets) ----
    u32 aOff[AIT], aDst[AIT];
    #pragma unroll
    for (int it = 0; it < AIT; it++) {
        int idx = tid + it * 256;
        int row = idx >> 3, blk = idx & 7;
        int srow;
        if (GATHER) { int gm = m0 + row; if (gm >= cnt) gm = cnt - 1; srow = rmap[gm]; }
        else srow = m0 + row;
        aOff[it] = (u32)srow * (u32)K + blk * 8;
        aDst[it] = (u32)(row * RS + blk * 8) * 2;
    }
    u32 bOff[NBI], bDst[NBI];
    #pragma unroll
    for (int it = 0; it < NBI; it++) {
        int idx = tid + it * 256;
        int row = idx >> 3, blk = idx & 7;
        bOff[it] = (u32)(n0 + row) * (u32)K + blk * 8;
        bDst[it] = (u32)(2 * ASZ + row * RS + blk * 8) * 2;
    }

    auto load_chunk = [&](int c, int s) {
        const int k0 = c * KCH;
        const u32 base = sb + (u32)(s * STG) * 2;
        #pragma unroll
        for (int it = 0; it < AIT; it++) {
            CP16(base + aDst[it],           Ah + aOff[it] + k0);
            CP16(base + aDst[it] + ASZ * 2, Al + aOff[it] + k0);
        }
        #pragma unroll
        for (int it = 0; it < NBI; it++) {
            CP16(base + bDst[it],           Bh + bOff[it] + k0);
            CP16(base + bDst[it] + BSZ * 2, Bl + bOff[it] + k0);
        }
    };

    // ---- per-lane ldmatrix address components ----
    const int aRowO = ((lane >> 3) & 1) * 8 + (lane & 7);
    const int aKO   = ((lane >> 4) & 1) * 8;
    const int bRowO = ((lane >> 4) & 1) * 8 + (lane & 7);
    const int bKO   = ((lane >> 3) & 1) * 8;

    float acc[MI][NF][4];
    #pragma unroll
    for (int i = 0; i < MI; i++)
        #pragma unroll
        for (int j = 0; j < NF; j++)
            #pragma unroll
            for (int q = 0; q < 4; q++) acc[i][j][q] = 0.f;

    const int nch = K / KCH;

    load_chunk(0, 0);
    CP_COMMIT();
    if (nch > 1) load_chunk(1, 1);
    CP_COMMIT();

    for (int c = 0; c < nch; c++) {
        CP_WAIT1();
        __syncthreads();

        const u32 stB = sb + (u32)((c & 1) * STG) * 2;
        #pragma unroll
        for (int ks = 0; ks < 4; ks++) {
            u32 ah[MI][4], al[MI][4];
            #pragma unroll
            for (int mi = 0; mi < MI; mi++) {
                u32 ad = stB + (u32)((wm * WMR + mi * 16 + aRowO) * RS + ks * 16 + aKO) * 2;
                LDMX4(ah[mi], ad);
                LDMX4(al[mi], ad + ASZ * 2);
            }
            #pragma unroll
            for (int j = 0; j < NF / 2; j++) {
                u32 bd = stB + (u32)(2 * ASZ + (wn * WN + j * 16 + bRowO) * RS + ks * 16 + bKO) * 2;
                u32 th[4], tl[4];
                LDMX4(th, bd);
                LDMX4(tl, bd + BSZ * 2);
                u32 b0h[2] = { th[0], th[1] }, b1h[2] = { th[2], th[3] };
                u32 b0l[2] = { tl[0], tl[1] }, b1l[2] = { tl[2], tl[3] };
                #pragma unroll
                for (int mi = 0; mi < MI; mi++) {
                    mma_bf16(acc[mi][2*j],   ah[mi], b0h);
                    mma_bf16(acc[mi][2*j],   ah[mi], b0l);
                    mma_bf16(acc[mi][2*j],   al[mi], b0h);
                    mma_bf16(acc[mi][2*j+1], ah[mi], b1h);
                    mma_bf16(acc[mi][2*j+1], ah[mi], b1l);
                    mma_bf16(acc[mi][2*j+1], al[mi], b1h);
                }
            }
        }
        __syncthreads();
        if (c + 2 < nch) load_chunk(c + 2, c & 1);
        CP_COMMIT();
    }

    // ---- epilogue ----
    const int gid = lane >> 2, tg = lane & 3;
    #pragma unroll
    for (int mi = 0; mi < MI; mi++) {
        #pragma unroll
        for (int nf = 0; nf < NF; nf++) {
            int mA  = m0 + wm * WMR + mi * 16 + gid;
            int col = n0 + wn * WN + nf * 8 + tg * 2;
            #pragma unroll
            for (int half = 0; half < 2; half++) {
                int m = mA + half * 8;
                if (m < cnt) {
                    float v0 = acc[mi][nf][half * 2 + 0] * alpha;
                    float v1 = acc[mi][nf][half * 2 + 1] * alpha;
                    if (bptr) { v0 += bptr[col]; v1 += bptr[col + 1]; }
                    if (GELU_) { v0 = gelu_exact(v0); v1 = gelu_exact(v1); }
                    size_t o = (size_t)m * ldc + col;
                    if (WF32) { Cf[o] = v0; Cf[o + 1] = v1; }
                    if (WSPLIT) {
                        u16 h0, l0, h1, l1;
                        split2(v0, h0, l0); split2(v1, h1, l1);
                        Ch[o] = h0; Ch[o + 1] = h1;
                        Cl[o] = l0; Cl[o + 1] = l1;
                    }
                }
            }
        }
    }
}

// ---------------- conversion kernels ----------------
__global__ void split_f32(const float* __restrict__ s, u16* __restrict__ h, u16* __restrict__ l, int n) {
    for (int i = blockIdx.x * blockDim.x + threadIdx.x; i * 4 < n; i += gridDim.x * blockDim.x) {
        float4 v = ((const float4*)s)[i];
        u16 hh[4], ll[4];
        split2(v.x, hh[0], ll[0]); split2(v.y, hh[1], ll[1]);
        split2(v.z, hh[2], ll[2]); split2(v.w, hh[3], ll[3]);
        *(uint2*)&h[4 * i] = *(uint2*)hh;
        *(uint2*)&l[4 * i] = *(uint2*)ll;
    }
}

__global__ void transpose_split(const float* __restrict__ s, u16* __restrict__ oh, u16* __restrict__ ol,
                                int R, int C) {
    __shared__ float t[32][33];
    size_t zo = (size_t)blockIdx.z * R * C;
    const float* src = s + zo;
    int c0 = blockIdx.x * 32, r0 = blockIdx.y * 32;
    int tx = threadIdx.x & 31, ty = threadIdx.x >> 5;
    #pragma unroll
    for (int dy = 0; dy < 32; dy += 8)
        t[ty + dy][tx] = src[(size_t)(r0 + ty + dy) * C + c0 + tx];
    __syncthreads();
    #pragma unroll
    for (int dy = 0; dy < 32; dy += 8) {
        float v = t[tx][ty + dy];
        size_t o = zo + (size_t)(c0 + ty + dy) * R + r0 + tx;
        u16 hh, ll; split2(v, hh, ll);
        oh[o] = hh; ol[o] = ll;
    }
}

__global__ void headsplit_qk(const float* __restrict__ in, u16* __restrict__ oh, u16* __restrict__ ol) {
    for (int i = blockIdx.x * blockDim.x + threadIdx.x; i < NTOK * DIM; i += gridDim.x * blockDim.x) {
        int d = i & 63, s = (i >> 6) & 1023, h = (i >> 16) & 15, b = i >> 20;
        float v = in[(size_t)((b << 10) + s) * DIM + (h << 6) + d];
        u16 hh, ll; split2(v, hh, ll);
        oh[i] = hh; ol[i] = ll;
    }
}

__global__ void headsplit_vT(const float* __restrict__ in, u16* __restrict__ oh, u16* __restrict__ ol) {
    __shared__ float t[32][33];
    int z = blockIdx.z;
    int b = z >> 4, h = z & 15;
    int s0 = blockIdx.x * 32, d0 = blockIdx.y * 32;
    int tx = threadIdx.x & 31, ty = threadIdx.x >> 5;
    #pragma unroll
    for (int dy = 0; dy < 32; dy += 8)
        t[ty + dy][tx] = in[(size_t)((b << 10) + s0 + ty + dy) * DIM + h * 64 + d0 + tx];
    __syncthreads();
    #pragma unroll
    for (int dy = 0; dy < 32; dy += 8) {
        float v = t[tx][ty + dy];
        size_t o = (size_t)(z * 64 + d0 + ty + dy) * 1024 + s0 + tx;
        u16 hh, ll; split2(v, hh, ll);
        oh[o] = hh; ol[o] = ll;
    }
}

__global__ void softmax_split() {
    const size_t ro = ((size_t)blockIdx.y * SQL + blockIdx.x) * SKV;
    const float* r = g_sc + ro;
    __shared__ float sm[32];
    int t = threadIdx.x;
    float v[4];
    float mx = -1e30f;
    #pragma unroll
    for (int j = 0; j < 4; j++) { v[j] = r[t + j * 256]; mx = fmaxf(mx, v[j]); }
    mx = blk_reduce_max(mx, sm);
    float s = 0.f;
    #pragma unroll
    for (int j = 0; j < 4; j++) { v[j] = __expf(v[j] - mx); s += v[j]; }
    s = blk_reduce_sum(s, sm);
    float inv = 1.f / s;
    #pragma unroll
    for (int j = 0; j < 4; j++) {
        float p = v[j] * inv;
        u16 hh, ll; split2(p, hh, ll);
        s_p_h[ro + t + j * 256] = hh;
        s_p_l[ro + t + j * 256] = ll;
    }
}

__global__ void head_merge_split(const float* __restrict__ in, u16* __restrict__ oh, u16* __restrict__ ol) {
    for (int i = blockIdx.x * blockDim.x + threadIdx.x; i < NTOK * DIM; i += gridDim.x * blockDim.x) {
        int col = i & 1023, h = col >> 6, d = col & 63;
        int s = (i >> 10) & 1023, b = i >> 20;
        float v = in[(size_t)(((b << 4) + h) * 1024 + s) * 64 + d];
        u16 hh, ll; split2(v, hh, ll);
        oh[i] = hh; ol[i] = ll;
    }
}

__global__ void ln_res_split(const float* __restrict__ a, const float* __restrict__ res,
                             const float* __restrict__ g, const float* __restrict__ b,
                             float* __restrict__ of, u16* __restrict__ oh, u16* __restrict__ ol) {
    __shared__ float sm[32];
    const size_t base = (size_t)blockIdx.x * DIM;
    int t = threadIdx.x;
    float v[4];
    float s = 0.f;
    #pragma unroll
    for (int j = 0; j < 4; j++) {
        int c = t + j * 256;
        v[j] = a[base + c] + res[base + c];
        s += v[j];
    }
    s = blk_reduce_sum(s, sm);
    float mean = s * (1.0f / DIM);
    float s2 = 0.f;
    #pragma unroll
    for (int j = 0; j < 4; j++) { float d = v[j] - mean; s2 += d * d; }
    s2 = blk_reduce_sum(s2, sm);
    float rs = rsqrtf(s2 * (1.0f / DIM) + 1e-5f);
    #pragma unroll
    for (int j = 0; j < 4; j++) {
        int c = t + j * 256;
        float o = (v[j] - mean) * rs * g[c] + b[c];
        of[base + c] = o;
        u16 hh, ll; split2(o, hh, ll);
        oh[base + c] = hh; ol[base + c] = ll;
    }
}

__global__ void combine_ln(const float* __restrict__ g, const float* __restrict__ b,
                           float* __restrict__ out) {
    __shared__ float sm[32];
    const int tok = blockIdx.x;
    const size_t base = (size_t)tok * DIM;
    int t = threadIdx.x;
    float v[4];
    #pragma unroll
    for (int j = 0; j < 4; j++) v[j] = g_x[base + t + j * 256];
    const int nl = g_tcnt[tok];
    for (int l = 0; l < nl; l++) {
        int   e    = g_te[tok * 3 + l];
        int   slot = g_tslot[tok * 3 + l];
        float gt   = g_tgate[tok * 3 + l];
        const float* row = g_e2 + ((size_t)e * NTOK + slot) * DIM;
        #pragma unroll
        for (int j = 0; j < 4; j++) v[j] += gt * row[t + j * 256];
    }
    float s = 0.f;
    #pragma unroll
    for (int j = 0; j < 4; j++) s += v[j];
    s = blk_reduce_sum(s, sm);
    float mean = s * (1.0f / DIM);
    float s2 = 0.f;
    #pragma unroll
    for (int j = 0; j < 4; j++) { float d = v[j] - mean; s2 += d * d; }
    s2 = blk_reduce_sum(s2, sm);
    float rs = rsqrtf(s2 * (1.0f / DIM) + 1e-5f);
    #pragma unroll
    for (int j = 0; j < 4; j++) {
        int c = t + j * 256;
        out[base + c] = (v[j] - mean) * rs * g[c] + b[c];
    }
}

__global__ void gating(const float* __restrict__ Wg) {
    __shared__ float logits[NEXP];
    const int tok = blockIdx.x;
    const float* xr = g_x + (size_t)tok * DIM;
    int w = threadIdx.x >> 5, lane = threadIdx.x & 31;
    float s = 0.f;
    for (int i = lane; i < DIM; i += 32) s += xr[i] * Wg[i * NEXP + w];
    #pragma unroll
    for (int o = 16; o; o >>= 1) s += __shfl_down_sync(0xffffffffu, s, o);
    if (!lane) logits[w] = s;
    __syncthreads();
    if (threadIdx.x == 0) {
        float p[NEXP];
        float mx = -1e30f;
        for (int e = 0; e < NEXP; e++) mx = fmaxf(mx, logits[e]);
        float sum = 0.f;
        for (int e = 0; e < NEXP; e++) { p[e] = __expf(logits[e] - mx); sum += p[e]; }
        float inv = 1.f / sum;
        for (int e = 0; e < NEXP; e++) { p[e] *= inv; g_probs[tok * NEXP + e] = p[e]; }
        int i0 = 0;
        for (int e = 1; e < NEXP; e++) if (p[e] > p[i0]) i0 = e;
        int i1 = -1;
        for (int e = 0; e < NEXP; e++) if (e != i0 && (i1 < 0 || p[e] > p[i1])) i1 = e;
        int i2 = -1;
        for (int e = 0; e < NEXP; e++) if (e != i0 && e != i1 && (i2 < 0 || p[e] > p[i2])) i2 = e;
        int   ids[3] = { i0, i1, i2 };
        float gts[3] = { p[i0],
                         (p[i1] >= THRESH) ? p[i1] : 0.f,
                         (p[i2] >= THRESH) ? p[i2] : 0.f };
        int nl = 0;
        #pragma unroll
        for (int j = 0; j < 3; j++) {
            if (gts[j] > 0.f) {
                int slot = atomicAdd(&g_cnt[ids[j]], 1);
                g_tok  [ids[j] * NTOK + slot] = tok;
                g_te   [tok * 3 + nl] = ids[j];
                g_tslot[tok * 3 + nl] = slot;
                g_tgate[tok * 3 + nl] = gts[j];
                nl++;
            }
        }
        g_tcnt[tok] = nl;
    }
}

__global__ void zero_small() {
    int t = threadIdx.x;
    if (t < NEXP) g_cnt[t] = 0;
}
__global__ void aux_kernel(float* __restrict__ out, int out_size) {
    if (out_size <= OUT_MAIN) return;
    __shared__ float sm[32];
    int t = threadIdx.x;
    float total = 0.f;
    for (int e = 0; e < NEXP; e++) {
        float s = 0.f;
        for (int tok = t; tok < NTOK; tok += 256) s += g_probs[tok * NEXP + e];
        s = blk_reduce_sum(s, sm);
        if (t == 0) total += ((float)g_cnt[e] / (float)NTOK) * (s / (float)NTOK);
    }
    if (t == 0) out[OUT_MAIN] = COEF * (float)NEXP * total;
}

// ---------------- host launcher ----------------
#define GETSYM(var, sym) do { cudaGetSymbolAddress((void**)&(var), sym); } while (0)

extern "C" void kernel_launch(void* const* d_in, const int* in_sizes, int n_in,
                              void* d_out, int out_size)
{
    (void)in_sizes; (void)n_in;
    const float* query  = (const float*)d_in[0];
    const float* keyval = (const float*)d_in[1];
    const float* Wq = (const float*)d_in[2];  const float* bq = (const float*)d_in[3];
    const float* Wk = (const float*)d_in[4];  const float* bk = (const float*)d_in[5];
    const float* Wv = (const float*)d_in[6];  const float* bv = (const float*)d_in[7];
    const float* W_in  = (const float*)d_in[8];  const float* b_in  = (const float*)d_in[9];
    const float* W_out = (const float*)d_in[10]; const float* b_out = (const float*)d_in[11];
    const float* Wa = (const float*)d_in[12]; const float* ba = (const float*)d_in[13];
    const float* ln1g = (const float*)d_in[14]; const float* ln1b = (const float*)d_in[15];
    const float* Wg = (const float*)d_in[16];
    const float* ew1 = (const float*)d_in[17]; const float* eb1 = (const float*)d_in[18];
    const float* ew2 = (const float*)d_in[19]; const float* eb2 = (const float*)d_in[20];
    const float* ln2g = (const float*)d_in[21]; const float* ln2b = (const float*)d_in[22];
    float* out = (float*)d_out;

    float *qh, *kh, *vh, *sc, *ot, *a, *x, *e2p;
    GETSYM(qh, g_qh); GETSYM(kh, g_kh); GETSYM(vh, g_vh);
    GETSYM(sc, g_sc); GETSYM(ot, g_ot); GETSYM(a, g_a); GETSYM(x, g_x);
    GETSYM(e2p, g_e2);
    u16 *qyh,*qyl,*kvh,*kvl,*qsh,*qsl,*ksh,*ksl,*vsh,*vsl;
    u16 *qth,*qtl,*kth,*ktl,*vth,*vtl,*oh,*ol,*oph,*opl,*xh,*xl,*pph,*ppl,*hhh,*hhl;
    u16 *wqh,*wql,*wkh,*wkl,*wvh,*wvl,*winh,*winl,*woh,*wol,*wah,*wal,*e1h,*e1l,*e2h,*e2l;
    GETSYM(qyh, s_query_h); GETSYM(qyl, s_query_l);
    GETSYM(kvh, s_kv_h);    GETSYM(kvl, s_kv_l);
    GETSYM(qsh, s_q_h);  GETSYM(qsl, s_q_l);
    GETSYM(ksh, s_k_h);  GETSYM(ksl, s_k_l);
    GETSYM(vsh, s_v_h);  GETSYM(vsl, s_v_l);
    GETSYM(qth, s_qt_h); GETSYM(qtl, s_qt_l);
    GETSYM(kth, s_kt_h); GETSYM(ktl, s_kt_l);
    GETSYM(vth, s_vt_h); GETSYM(vtl, s_vt_l);
    GETSYM(oh,  s_o_h);  GETSYM(ol,  s_o_l);
    GETSYM(oph, s_op_h); GETSYM(opl, s_op_l);
    GETSYM(xh,  s_x_h);  GETSYM(xl,  s_x_l);
    GETSYM(pph, s_p_h);  GETSYM(ppl, s_p_l);
    GETSYM(hhh, s_hh);   GETSYM(hhl, s_hl);
    GETSYM(wqh, s_wq_h); GETSYM(wql, s_wq_l);
    GETSYM(wkh, s_wk_h); GETSYM(wkl, s_wk_l);
    GETSYM(wvh, s_wv_h); GETSYM(wvl, s_wv_l);
    GETSYM(winh, s_win_h); GETSYM(winl, s_win_l);
    GETSYM(woh, s_wo_h); GETSYM(wol, s_wo_l);
    GETSYM(wah, s_wa_h); GETSYM(wal, s_wa_l);
    GETSYM(e1h, s_e1_h); GETSYM(e1l, s_e1_l);
    GETSYM(e2h, s_e2_h); GETSYM(e2l, s_e2_l);
    int *tokp; GETSYM(tokp, g_tok);
    int *cntp; GETSYM(cntp, g_cnt);

    // dynamic smem: 2 stages * 2*(BM+BN)*RS u16
    const int S256_128 = 2 * 2 * (256 + 128) * RS * 2;   // 221184 B
    const int S256_64  = 2 * 2 * (256 + 64)  * RS * 2;   // 184320 B
    cudaFuncSetAttribute((const void*)gemm_tc<256,128,false,false,true ,false>, cudaFuncAttributeMaxDynamicSharedMemorySize, S256_128);
    cudaFuncSetAttribute((const void*)gemm_tc<256,128,false,true ,false,false>, cudaFuncAttributeMaxDynamicSharedMemorySize, S256_128);
    cudaFuncSetAttribute((const void*)gemm_tc<256,64 ,false,true ,false,false>, cudaFuncAttributeMaxDynamicSharedMemorySize, S256_64);
    cudaFuncSetAttribute((const void*)gemm_tc<256,128,true ,false,true ,true >, cudaFuncAttributeMaxDynamicSharedMemorySize, S256_128);

    const dim3 T256(256);
    const dim3 GLIN(DIM/128, NTOK/256, 1);   // 8 x 16 = 128 CTAs

    // NOTE launch order: the 6th launch is the Q linear GEMM so ncu (-s 5 -c 1)
    // profiles the main GEMM kernel instead of a conversion kernel.
    zero_small<<<1, 32>>>();                                     // 1
    split_f32<<<1024, 256>>>(query,  qyh, qyl, NTOK*DIM);        // 2
    split_f32<<<1024, 256>>>(keyval, kvh, kvl, NTOK*DIM);        // 3
    split_f32<<<512, 256>>>(Wq, wqh, wql, DIM*DIM);              // 4
    split_f32<<<512, 256>>>(Wk, wkh, wkl, DIM*DIM);              // 5
    gemm_tc<256,128,false,false,true,false><<<GLIN, T256, S256_128>>>(   // 6 <- profiled
        qyh, qyl, wqh, wql, DIM, 0, 0, 0, nullptr, nullptr, bq, 0, 1.f, nullptr, qsh, qsl, DIM);
    split_f32<<<512, 256>>>(Wv, wvh, wvl, DIM*DIM);
    split_f32<<<1024, 256>>>(W_in, winh, winl, 3*DIM*DIM);
    split_f32<<<512, 256>>>(W_out, woh, wol, DIM*DIM);
    split_f32<<<512, 256>>>(Wa, wah, wal, DIM*DIM);
    transpose_split<<<dim3(HDIM/32, DIM/32, NEXP), T256>>>(ew1, e1h, e1l, DIM, HDIM);
    transpose_split<<<dim3(DIM/32, HDIM/32, NEXP), T256>>>(ew2, e2h, e2l, HDIM, DIM);

    // ---- remaining outer K/V linears ----
    gemm_tc<256,128,false,false,true,false><<<GLIN, T256, S256_128>>>(
        kvh, kvl, wkh, wkl, DIM, 0, 0, 0, nullptr, nullptr, bk, 0, 1.f, nullptr, ksh, ksl, DIM);
    gemm_tc<256,128,false,false,true,false><<<GLIN, T256, S256_128>>>(
        kvh, kvl, wvh, wvl, DIM, 0, 0, 0, nullptr, nullptr, bv, 0, 1.f, nullptr, vsh, vsl, DIM);

    // ---- MHA in-projection (fp32 out) ----
    gemm_tc<256,128,false,true,false,false><<<GLIN, T256, S256_128>>>(
        qsh, qsl, winh,              winl,              DIM, 0, 0, 0, nullptr, nullptr, b_in,        0, 1.f, qh, nullptr, nullptr, DIM);
    gemm_tc<256,128,false,true,false,false><<<GLIN, T256, S256_128>>>(
        ksh, ksl, winh + DIM*DIM,    winl + DIM*DIM,    DIM, 0, 0, 0, nullptr, nullptr, b_in + DIM,  0, 1.f, kh, nullptr, nullptr, DIM);
    gemm_tc<256,128,false,true,false,false><<<GLIN, T256, S256_128>>>(
        vsh, vsl, winh + 2*DIM*DIM,  winl + 2*DIM*DIM,  DIM, 0, 0, 0, nullptr, nullptr, b_in + 2*DIM,0, 1.f, vh, nullptr, nullptr, DIM);

    // ---- head reshape ----
    headsplit_qk<<<512, 256>>>(qh, qth, qtl);
    headsplit_qk<<<512, 256>>>(kh, kth, ktl);
    headsplit_vT<<<dim3(SQL/32, 2, BH), T256>>>(vh, vth, vtl);

    // ---- scores = (Q @ K^T)/8 ----
    gemm_tc<256,128,false,true,false,false><<<dim3(SKV/128, SQL/256, BH), T256, S256_128>>>(
        qth, qtl, kth, ktl, DH,
        (long long)SQL*DH, (long long)SKV*DH, (long long)SQL*SKV,
        nullptr, nullptr, nullptr, 0, 0.125f, sc, nullptr, nullptr, SKV);

    softmax_split<<<dim3(SQL, BH), T256>>>();

    // ---- O = attn @ V ----
    gemm_tc<256,64,false,true,false,false><<<dim3(1, SQL/256, BH), T256, S256_64>>>(
        pph, ppl, vth, vtl, SKV,
        (long long)SQL*SKV, (long long)DH*SKV, (long long)SQL*DH,
        nullptr, nullptr, nullptr, 0, 1.f, ot, nullptr, nullptr, DH);

    head_merge_split<<<512, 256>>>(ot, oh, ol);

    // ---- out-projection + adapter ----
    gemm_tc<256,128,false,false,true,false><<<GLIN, T256, S256_128>>>(
        oh, ol, woh, wol, DIM, 0, 0, 0, nullptr, nullptr, b_out, 0, 1.f, nullptr, oph, opl, DIM);
    gemm_tc<256,128,false,true,false,false><<<GLIN, T256, S256_128>>>(
        oph, opl, wah, wal, DIM, 0, 0, 0, nullptr, nullptr, ba, 0, 1.f, a, nullptr, nullptr, DIM);

    // ---- LN1 (+residual) -> x fp32 + split ----
    ln_res_split<<<NTOK, T256>>>(a, query, ln1g, ln1b, x, xh, xl);

    // ---- gating ----
    gating<<<NTOK, T256>>>(Wg);

    // ---- MoE expert FFNs ----
    gemm_tc<256,128,true,false,true,true><<<dim3(HDIM/128, NTOK/256, NEXP), T256, S256_128>>>(
        xh, xl, e1h, e1l, DIM,
        0, (long long)HDIM*DIM, (long long)NTOK*HDIM,
        tokp, cntp, eb1, HDIM, 1.f, nullptr, hhh, hhl, HDIM);
    gemm_tc<256,128,false,true,false,false><<<dim3(DIM/128, NTOK/256, NEXP), T256, S256_128>>>(
        hhh, hhl, e2h, e2l, HDIM,
        (long long)NTOK*HDIM, (long long)DIM*HDIM, (long long)NTOK*DIM,
        nullptr, cntp, eb2, DIM, 1.f, e2p, nullptr, nullptr, DIM);

    // ---- fused combine + final LN -> output, then aux scalar ----
    combine_ln<<<NTOK, T256>>>(ln2g, ln2b, out);
    aux_kernel<<<1, 256>>>(out, out_size);
}

// round 11
// speedup vs baseline: 2.8106x; 1.0504x over previous
#include <cuda_runtime.h>
#include <cuda_bf16.h>
#include <math.h>
#include <stddef.h>
#include <stdint.h>

// ---------------- problem constants ----------------
#define BATCH 4
#define SQL   1024
#define SKV   1024
#define DIM   1024
#define NH    16
#define DH    64
#define NEXP  8
#define HDIM  4096
#define NTOK  (BATCH*SQL)       // 4096
#define BH    (BATCH*NH)        // 64
#define OUT_MAIN (NTOK*DIM)
#define THRESH 0.05f
#define COEF   0.01f
#define KCH   64                // K chunk
#define RS    72                // smem row stride in u16 (64 data + 8 pad)

typedef unsigned short u16;
typedef unsigned int   u32;

// ---------------- static device scratch (fp32) ----------------
__device__ float g_qh[NTOK*DIM];
__device__ float g_kh[NTOK*DIM];
__device__ float g_vh[NTOK*DIM];
__device__ float g_ot[NTOK*DIM];
__device__ float g_a [NTOK*DIM];
__device__ float g_x [NTOK*DIM];
__device__ float g_e2[(size_t)NEXP*NTOK*DIM];   // 128 MB
__device__ int   g_cnt[NEXP];
__device__ int   g_tok[NEXP*NTOK];
__device__ float g_probs[NTOK*NEXP];
__device__ int   g_tcnt[NTOK];
__device__ int   g_te  [NTOK*3];
__device__ int   g_tslot[NTOK*3];
__device__ float g_tgate[NTOK*3];

// ---------------- bf16 hi/lo split buffers ----------------
__device__ u16 s_query_h[NTOK*DIM], s_query_l[NTOK*DIM];
__device__ u16 s_kv_h[NTOK*DIM],    s_kv_l[NTOK*DIM];
__device__ u16 s_q_h[NTOK*DIM],     s_q_l[NTOK*DIM];
__device__ u16 s_k_h[NTOK*DIM],     s_k_l[NTOK*DIM];
__device__ u16 s_v_h[NTOK*DIM],     s_v_l[NTOK*DIM];
__device__ u16 s_qt_h[NTOK*DIM],    s_qt_l[NTOK*DIM];    // [bh][sq][dh]
__device__ u16 s_kt_h[NTOK*DIM],    s_kt_l[NTOK*DIM];    // [bh][skv][dh]
__device__ u16 s_vt_h[NTOK*DIM],    s_vt_l[NTOK*DIM];    // [bh][dh][skv]
__device__ u16 s_o_h[NTOK*DIM],     s_o_l[NTOK*DIM];
__device__ u16 s_op_h[NTOK*DIM],    s_op_l[NTOK*DIM];
__device__ u16 s_x_h[NTOK*DIM],     s_x_l[NTOK*DIM];
__device__ u16 s_hh [(size_t)NEXP*NTOK*HDIM], s_hl[(size_t)NEXP*NTOK*HDIM];
// weights
__device__ u16 s_wq_h[DIM*DIM],   s_wq_l[DIM*DIM];
__device__ u16 s_wk_h[DIM*DIM],   s_wk_l[DIM*DIM];
__device__ u16 s_wv_h[DIM*DIM],   s_wv_l[DIM*DIM];
__device__ u16 s_win_h[3*DIM*DIM],s_win_l[3*DIM*DIM];
__device__ u16 s_wo_h[DIM*DIM],   s_wo_l[DIM*DIM];
__device__ u16 s_wa_h[DIM*DIM],   s_wa_l[DIM*DIM];
__device__ u16 s_e1_h[(size_t)NEXP*HDIM*DIM], s_e1_l[(size_t)NEXP*HDIM*DIM]; // [e][n=HDIM][k=DIM]
__device__ u16 s_e2_h[(size_t)NEXP*DIM*HDIM], s_e2_l[(size_t)NEXP*DIM*HDIM]; // [e][n=DIM][k=HDIM]

// ---------------- helpers ----------------
__device__ __forceinline__ u16 f2bf(float v) { __nv_bfloat16 b = __float2bfloat16(v); return *(u16*)&b; }
__device__ __forceinline__ float bf2f(u16 u) { __nv_bfloat16 b; *(u16*)&b = u; return __bfloat162float(b); }
__device__ __forceinline__ void split2(float v, u16& h, u16& l) {
    u16 hu = f2bf(v); h = hu; l = f2bf(v - bf2f(hu));
}
__device__ __forceinline__ void split_pack2(float v0, float v1, u32& h, u32& l) {
    u16 h0, l0, h1, l1;
    split2(v0, h0, l0); split2(v1, h1, l1);
    h = (u32)h0 | ((u32)h1 << 16);
    l = (u32)l0 | ((u32)l1 << 16);
}
__device__ __forceinline__ float gelu_exact(float v) {
    return 0.5f * v * (1.0f + erff(v * 0.70710678118654752f));
}
__device__ __forceinline__ u32 smem_u32(const void* p) {
    u32 a;
    asm("{ .reg .u64 t; cvta.to.shared.u64 t, %1; cvt.u32.u64 %0, t; }" : "=r"(a) : "l"(p));
    return a;
}
__device__ __forceinline__ float blk_reduce_sum(float v, float* sm) {
    int lane = threadIdx.x & 31, w = threadIdx.x >> 5;
    #pragma unroll
    for (int o = 16; o; o >>= 1) v += __shfl_down_sync(0xffffffffu, v, o);
    if (!lane) sm[w] = v;
    __syncthreads();
    if (threadIdx.x < 32) {
        v = (threadIdx.x < 8) ? sm[threadIdx.x] : 0.f;
        #pragma unroll
        for (int o = 4; o; o >>= 1) v += __shfl_down_sync(0xffffffffu, v, o);
        if (!threadIdx.x) sm[0] = v;
    }
    __syncthreads();
    float r = sm[0];
    __syncthreads();
    return r;
}

__device__ __forceinline__ void mma_bf16(float* c, const u32* a, const u32* b) {
    asm volatile(
        "mma.sync.aligned.m16n8k16.row.col.f32.bf16.bf16.f32 "
        "{%0,%1,%2,%3}, {%4,%5,%6,%7}, {%8,%9}, {%0,%1,%2,%3};"
        : "+f"(c[0]), "+f"(c[1]), "+f"(c[2]), "+f"(c[3])
        : "r"(a[0]), "r"(a[1]), "r"(a[2]), "r"(a[3]), "r"(b[0]), "r"(b[1]));
}

#define CP16(dst, src) \
    asm volatile("cp.async.cg.shared.global [%0], [%1], 16;" :: "r"(dst), "l"(src) : "memory")
#define CP_COMMIT() asm volatile("cp.async.commit_group;" ::: "memory")
#define CP_WAIT1()  asm volatile("cp.async.wait_group 1;" ::: "memory")
#define CP_WAIT2()  asm volatile("cp.async.wait_group 2;" ::: "memory")
#define LDMX4(r, addr) \
    asm volatile("ldmatrix.sync.aligned.m8n8.x4.shared.b16 {%0,%1,%2,%3}, [%4];" \
        : "=r"((r)[0]), "=r"((r)[1]), "=r"((r)[2]), "=r"((r)[3]) : "r"(addr))

// =====================================================================
// bf16-split tensor-core GEMM (unchanged from R10 winner)
// =====================================================================
template<int BM, int BN, bool GELU_, bool WF32, bool WSPLIT, bool GATHER>
__global__ __launch_bounds__(256, 1)
void gemm_tc(const u16* __restrict__ Ah_, const u16* __restrict__ Al_,
             const u16* __restrict__ Bh_, const u16* __restrict__ Bl_,
             int K, long long As, long long Bs, long long Cs,
             const int* __restrict__ rowmap, const int* __restrict__ cntArr,
             const float* __restrict__ bias, long long biasStride, float alpha,
             float* __restrict__ Cf, u16* __restrict__ Ch, u16* __restrict__ Cl, int ldc)
{
    extern __shared__ __align__(16) u16 smem[];
    const int z = blockIdx.z;
    const int cnt = cntArr ? cntArr[z] : 0x40000000;
    const int m0 = blockIdx.y * BM;
    if (m0 >= cnt) return;
    const int n0 = blockIdx.x * BN;

    const u16* Ah = Ah_ + (size_t)z * As;
    const u16* Al = Al_ + (size_t)z * As;
    const u16* Bh = Bh_ + (size_t)z * Bs;
    const u16* Bl = Bl_ + (size_t)z * Bs;
    if (WF32)   Cf += (size_t)z * Cs;
    if (WSPLIT) { Ch += (size_t)z * Cs; Cl += (size_t)z * Cs; }
    const float* bptr = bias ? bias + (size_t)z * biasStride : nullptr;
    const int* rmap = GATHER ? (rowmap + (size_t)z * NTOK) : nullptr;

    constexpr int ASZ = BM * RS;
    constexpr int BSZ = BN * RS;
    constexpr int STG = 2 * ASZ + 2 * BSZ;
    constexpr int WMR = BM / 4;
    constexpr int MI  = WMR / 16;
    constexpr int WN  = BN / 2;
    constexpr int NF  = WN / 8;
    constexpr int AIT = BM / 32;
    constexpr int NBI = BN / 32;

    const int tid = threadIdx.x;
    const int wid = tid >> 5, lane = tid & 31;
    const int wm = wid & 3, wn = wid >> 2;
    const u32 sb = smem_u32(smem);

    u32 aOff[AIT], aDst[AIT];
    #pragma unroll
    for (int it = 0; it < AIT; it++) {
        int idx = tid + it * 256;
        int row = idx >> 3, blk = idx & 7;
        int srow;
        if (GATHER) { int gm = m0 + row; if (gm >= cnt) gm = cnt - 1; srow = rmap[gm]; }
        else srow = m0 + row;
        aOff[it] = (u32)srow * (u32)K + blk * 8;
        aDst[it] = (u32)(row * RS + blk * 8) * 2;
    }
    u32 bOff[NBI], bDst[NBI];
    #pragma unroll
    for (int it = 0; it < NBI; it++) {
        int idx = tid + it * 256;
        int row = idx >> 3, blk = idx & 7;
        bOff[it] = (u32)(n0 + row) * (u32)K + blk * 8;
        bDst[it] = (u32)(2 * ASZ + row * RS + blk * 8) * 2;
    }

    auto load_chunk = [&](int c, int s) {
        const int k0 = c * KCH;
        const u32 base = sb + (u32)(s * STG) * 2;
        #pragma unroll
        for (int it = 0; it < AIT; it++) {
            CP16(base + aDst[it],           Ah + aOff[it] + k0);
            CP16(base + aDst[it] + ASZ * 2, Al + aOff[it] + k0);
        }
        #pragma unroll
        for (int it = 0; it < NBI; it++) {
            CP16(base + bDst[it],           Bh + bOff[it] + k0);
            CP16(base + bDst[it] + BSZ * 2, Bl + bOff[it] + k0);
        }
    };

    const int aRowO = ((lane >> 3) & 1) * 8 + (lane & 7);
    const int aKO   = ((lane >> 4) & 1) * 8;
    const int bRowO = ((lane >> 4) & 1) * 8 + (lane & 7);
    const int bKO   = ((lane >> 3) & 1) * 8;

    float acc[MI][NF][4];
    #pragma unroll
    for (int i = 0; i < MI; i++)
        #pragma unroll
        for (int j = 0; j < NF; j++)
            #pragma unroll
            for (int q = 0; q < 4; q++) acc[i][j][q] = 0.f;

    const int nch = K / KCH;

    load_chunk(0, 0);
    CP_COMMIT();
    if (nch > 1) load_chunk(1, 1);
    CP_COMMIT();

    for (int c = 0; c < nch; c++) {
        CP_WAIT1();
        __syncthreads();

        const u32 stB = sb + (u32)((c & 1) * STG) * 2;
        #pragma unroll
        for (int ks = 0; ks < 4; ks++) {
            u32 ah[MI][4], al[MI][4];
            #pragma unroll
            for (int mi = 0; mi < MI; mi++) {
                u32 ad = stB + (u32)((wm * WMR + mi * 16 + aRowO) * RS + ks * 16 + aKO) * 2;
                LDMX4(ah[mi], ad);
                LDMX4(al[mi], ad + ASZ * 2);
            }
            #pragma unroll
            for (int j = 0; j < NF / 2; j++) {
                u32 bd = stB + (u32)(2 * ASZ + (wn * WN + j * 16 + bRowO) * RS + ks * 16 + bKO) * 2;
                u32 th[4], tl[4];
                LDMX4(th, bd);
                LDMX4(tl, bd + BSZ * 2);
                u32 b0h[2] = { th[0], th[1] }, b1h[2] = { th[2], th[3] };
                u32 b0l[2] = { tl[0], tl[1] }, b1l[2] = { tl[2], tl[3] };
                #pragma unroll
                for (int mi = 0; mi < MI; mi++) {
                    mma_bf16(acc[mi][2*j],   ah[mi], b0h);
                    mma_bf16(acc[mi][2*j],   ah[mi], b0l);
                    mma_bf16(acc[mi][2*j],   al[mi], b0h);
                    mma_bf16(acc[mi][2*j+1], ah[mi], b1h);
                    mma_bf16(acc[mi][2*j+1], ah[mi], b1l);
                    mma_bf16(acc[mi][2*j+1], al[mi], b1h);
                }
            }
        }
        __syncthreads();
        if (c + 2 < nch) load_chunk(c + 2, c & 1);
        CP_COMMIT();
    }

    const int gid = lane >> 2, tg = lane & 3;
    #pragma unroll
    for (int mi = 0; mi < MI; mi++) {
        #pragma unroll
        for (int nf = 0; nf < NF; nf++) {
            int mA  = m0 + wm * WMR + mi * 16 + gid;
            int col = n0 + wn * WN + nf * 8 + tg * 2;
            #pragma unroll
            for (int half = 0; half < 2; half++) {
                int m = mA + half * 8;
                if (m < cnt) {
                    float v0 = acc[mi][nf][half * 2 + 0] * alpha;
                    float v1 = acc[mi][nf][half * 2 + 1] * alpha;
                    if (bptr) { v0 += bptr[col]; v1 += bptr[col + 1]; }
                    if (GELU_) { v0 = gelu_exact(v0); v1 = gelu_exact(v1); }
                    size_t o = (size_t)m * ldc + col;
                    if (WF32) { Cf[o] = v0; Cf[o + 1] = v1; }
                    if (WSPLIT) {
                        u16 h0, l0, h1, l1;
                        split2(v0, h0, l0); split2(v1, h1, l1);
                        Ch[o] = h0; Ch[o + 1] = h1;
                        Cl[o] = l0; Cl[o + 1] = l1;
                    }
                }
            }
        }
    }
}

// =====================================================================
// Flash attention: per CTA = 128 Q rows of one (b,h); loops 16 KV blocks
// of 64. S = QK^T (bf16-split, 3 products), online softmax in regs,
// O += P@V (P re-split in regs; V hi/lo from smem). Writes O fp32 to g_ot.
// 8 warps; warp = 16 q rows. Q frags kept in registers for all blocks.
// =====================================================================
__global__ __launch_bounds__(256, 1)
void flash_attn()
{
    extern __shared__ __align__(16) u16 smem[];
    const int z  = blockIdx.y;            // head index (b*16+h)
    const int q0 = blockIdx.x * 128;
    const int tid = threadIdx.x, wid = tid >> 5, lane = tid & 31;
    const u32 sb = smem_u32(smem);

    constexpr int QSZ = 128 * RS;         // u16 per Q tile
    constexpr int KSZ = 64 * RS;          // u16 per K/V tile
    constexpr int STG = 4 * KSZ;          // Kh,Kl,Vh,Vl per stage
    const u32 kvB = 2 * QSZ;              // u16 offset of stage 0

    // ---- load Q tile (hi+lo) into smem ----
    #pragma unroll
    for (int j = 0; j < 4; j++) {
        int idx = tid + j * 256;          // 0..1023
        int row = idx >> 3, blk = idx & 7;
        size_t src = ((size_t)(z * 1024 + q0 + row)) * 64 + blk * 8;
        u32 dst = sb + (u32)(row * RS + blk * 8) * 2;
        CP16(dst,           s_qt_h + src);
        CP16(dst + QSZ * 2, s_qt_l + src);
    }
    CP_COMMIT();

    auto load_kv = [&](int c, int s) {
        const int kv0 = c * 64;
        const u32 base = sb + (kvB + (u32)s * STG) * 2;
        #pragma unroll
        for (int j = 0; j < 2; j++) {
            int idx = tid + j * 256;      // 0..511
            int row = idx >> 3, blk = idx & 7;
            size_t ksrc = ((size_t)(z * 1024 + kv0 + row)) * 64 + blk * 8;
            size_t vsrc = ((size_t)(z * 64 + row)) * 1024 + kv0 + blk * 8;
            u32 d = (u32)(row * RS + blk * 8) * 2;
            CP16(base + d,               s_kt_h + ksrc);
            CP16(base + d + KSZ * 2,     s_kt_l + ksrc);
            CP16(base + d + 2 * KSZ * 2, s_vt_h + vsrc);
            CP16(base + d + 3 * KSZ * 2, s_vt_l + vsrc);
        }
    };

    load_kv(0, 0); CP_COMMIT();
    load_kv(1, 1); CP_COMMIT();

    // ---- ldmatrix lane mappings (identical to gemm_tc, verified) ----
    const int aRowO = ((lane >> 3) & 1) * 8 + (lane & 7);
    const int aKO   = ((lane >> 4) & 1) * 8;
    const int bRowO = ((lane >> 4) & 1) * 8 + (lane & 7);
    const int bKO   = ((lane >> 3) & 1) * 8;

    // wait for Q, then load Q fragments to registers (kept all blocks)
    CP_WAIT2();
    __syncthreads();
    u32 qhf[4][4], qlf[4][4];
    #pragma unroll
    for (int ks = 0; ks < 4; ks++) {
        u32 ad = sb + (u32)((wid * 16 + aRowO) * RS + ks * 16 + aKO) * 2;
        LDMX4(qhf[ks], ad);
        LDMX4(qlf[ks], ad + QSZ * 2);
    }

    float of[8][4];
    #pragma unroll
    for (int n = 0; n < 8; n++)
        #pragma unroll
        for (int q = 0; q < 4; q++) of[n][q] = 0.f;
    float m0 = -1e30f, m1 = -1e30f, l0 = 0.f, l1 = 0.f;

    for (int c = 0; c < 16; c++) {
        CP_WAIT1();
        __syncthreads();
        const u32 stB = sb + (kvB + (u32)((c & 1) * STG)) * 2;

        // ---- S = (Q @ K^T) ----
        float sacc[8][4];
        #pragma unroll
        for (int n = 0; n < 8; n++)
            #pragma unroll
            for (int q = 0; q < 4; q++) sacc[n][q] = 0.f;

        #pragma unroll
        for (int ks = 0; ks < 4; ks++) {
            #pragma unroll
            for (int j = 0; j < 4; j++) {
                u32 bd = stB + (u32)((j * 16 + bRowO) * RS + ks * 16 + bKO) * 2;
                u32 th[4], tl[4];
                LDMX4(th, bd);
                LDMX4(tl, bd + KSZ * 2);
                u32 b0h[2] = { th[0], th[1] }, b1h[2] = { th[2], th[3] };
                u32 b0l[2] = { tl[0], tl[1] }, b1l[2] = { tl[2], tl[3] };
                mma_bf16(sacc[2*j],   qhf[ks], b0h);
                mma_bf16(sacc[2*j],   qhf[ks], b0l);
                mma_bf16(sacc[2*j],   qlf[ks], b0h);
                mma_bf16(sacc[2*j+1], qhf[ks], b1h);
                mma_bf16(sacc[2*j+1], qhf[ks], b1l);
                mma_bf16(sacc[2*j+1], qlf[ks], b1h);
            }
        }

        // ---- online softmax (rows: gid -> c0,c1 ; gid+8 -> c2,c3) ----
        float mx0 = -1e30f, mx1 = -1e30f;
        #pragma unroll
        for (int n = 0; n < 8; n++) {
            #pragma unroll
            for (int q = 0; q < 4; q++) sacc[n][q] *= 0.125f;
            mx0 = fmaxf(mx0, fmaxf(sacc[n][0], sacc[n][1]));
            mx1 = fmaxf(mx1, fmaxf(sacc[n][2], sacc[n][3]));
        }
        mx0 = fmaxf(mx0, __shfl_xor_sync(0xffffffffu, mx0, 1));
        mx0 = fmaxf(mx0, __shfl_xor_sync(0xffffffffu, mx0, 2));
        mx1 = fmaxf(mx1, __shfl_xor_sync(0xffffffffu, mx1, 1));
        mx1 = fmaxf(mx1, __shfl_xor_sync(0xffffffffu, mx1, 2));
        float mn0 = fmaxf(m0, mx0), mn1 = fmaxf(m1, mx1);
        float sc0 = __expf(m0 - mn0), sc1 = __expf(m1 - mn1);
        m0 = mn0; m1 = mn1;
        float ps0 = 0.f, ps1 = 0.f;
        #pragma unroll
        for (int n = 0; n < 8; n++) {
            sacc[n][0] = __expf(sacc[n][0] - mn0);
            sacc[n][1] = __expf(sacc[n][1] - mn0);
            sacc[n][2] = __expf(sacc[n][2] - mn1);
            sacc[n][3] = __expf(sacc[n][3] - mn1);
            ps0 += sacc[n][0] + sacc[n][1];
            ps1 += sacc[n][2] + sacc[n][3];
        }
        ps0 += __shfl_xor_sync(0xffffffffu, ps0, 1);
        ps0 += __shfl_xor_sync(0xffffffffu, ps0, 2);
        ps1 += __shfl_xor_sync(0xffffffffu, ps1, 1);
        ps1 += __shfl_xor_sync(0xffffffffu, ps1, 2);
        l0 = l0 * sc0 + ps0;
        l1 = l1 * sc1 + ps1;
        #pragma unroll
        for (int n = 0; n < 8; n++) {
            of[n][0] *= sc0; of[n][1] *= sc0;
            of[n][2] *= sc1; of[n][3] *= sc1;
        }

        // ---- O += P @ V  (P frags built directly from sacc) ----
        #pragma unroll
        for (int kk = 0; kk < 4; kk++) {
            u32 ph[4], pl[4];
            split_pack2(sacc[2*kk][0],   sacc[2*kk][1],   ph[0], pl[0]);
            split_pack2(sacc[2*kk][2],   sacc[2*kk][3],   ph[1], pl[1]);
            split_pack2(sacc[2*kk+1][0], sacc[2*kk+1][1], ph[2], pl[2]);
            split_pack2(sacc[2*kk+1][2], sacc[2*kk+1][3], ph[3], pl[3]);
            #pragma unroll
            for (int j2 = 0; j2 < 4; j2++) {
                u32 vd = stB + (u32)(2 * KSZ) * 2
                       + (u32)((j2 * 16 + bRowO) * RS + kk * 16 + bKO) * 2;
                u32 th[4], tl[4];
                LDMX4(th, vd);
                LDMX4(tl, vd + KSZ * 2);
                u32 b0h[2] = { th[0], th[1] }, b1h[2] = { th[2], th[3] };
                u32 b0l[2] = { tl[0], tl[1] }, b1l[2] = { tl[2], tl[3] };
                mma_bf16(of[2*j2],   ph, b0h);
                mma_bf16(of[2*j2],   ph, b0l);
                mma_bf16(of[2*j2],   pl, b0h);
                mma_bf16(of[2*j2+1], ph, b1h);
                mma_bf16(of[2*j2+1], ph, b1l);
                mma_bf16(of[2*j2+1], pl, b1h);
            }
        }
        __syncthreads();
        if (c + 2 < 16) load_kv(c + 2, c & 1);
        CP_COMMIT();
    }

    // ---- write O (fp32) to g_ot [bh][sq][dh] ----
    const int gid = lane >> 2, tg = lane & 3;
    float inv0 = 1.f / l0, inv1 = 1.f / l1;
    int qr = q0 + wid * 16 + gid;
    #pragma unroll
    for (int n = 0; n < 8; n++) {
        int dh = n * 8 + tg * 2;
        float2 v0 = make_float2(of[n][0] * inv0, of[n][1] * inv0);
        float2 v1 = make_float2(of[n][2] * inv1, of[n][3] * inv1);
        *(float2*)&g_ot[((size_t)(z * 1024 + qr)) * 64 + dh]     = v0;
        *(float2*)&g_ot[((size_t)(z * 1024 + qr + 8)) * 64 + dh] = v1;
    }
}

// ---------------- conversion kernels ----------------
__global__ void split_f32(const float* __restrict__ s, u16* __restrict__ h, u16* __restrict__ l, int n) {
    for (int i = blockIdx.x * blockDim.x + threadIdx.x; i * 4 < n; i += gridDim.x * blockDim.x) {
        float4 v = ((const float4*)s)[i];
        u16 hh[4], ll[4];
        split2(v.x, hh[0], ll[0]); split2(v.y, hh[1], ll[1]);
        split2(v.z, hh[2], ll[2]); split2(v.w, hh[3], ll[3]);
        *(uint2*)&h[4 * i] = *(uint2*)hh;
        *(uint2*)&l[4 * i] = *(uint2*)ll;
    }
}

__global__ void transpose_split(const float* __restrict__ s, u16* __restrict__ oh, u16* __restrict__ ol,
                                int R, int C) {
    __shared__ float t[32][33];
    size_t zo = (size_t)blockIdx.z * R * C;
    const float* src = s + zo;
    int c0 = blockIdx.x * 32, r0 = blockIdx.y * 32;
    int tx = threadIdx.x & 31, ty = threadIdx.x >> 5;
    #pragma unroll
    for (int dy = 0; dy < 32; dy += 8)
        t[ty + dy][tx] = src[(size_t)(r0 + ty + dy) * C + c0 + tx];
    __syncthreads();
    #pragma unroll
    for (int dy = 0; dy < 32; dy += 8) {
        float v = t[tx][ty + dy];
        size_t o = zo + (size_t)(c0 + ty + dy) * R + r0 + tx;
        u16 hh, ll; split2(v, hh, ll);
        oh[o] = hh; ol[o] = ll;
    }
}

__global__ void headsplit_qk(const float* __restrict__ in, u16* __restrict__ oh, u16* __restrict__ ol) {
    for (int i = blockIdx.x * blockDim.x + threadIdx.x; i < NTOK * DIM; i += gridDim.x * blockDim.x) {
        int d = i & 63, s = (i >> 6) & 1023, h = (i >> 16) & 15, b = i >> 20;
        float v = in[(size_t)((b << 10) + s) * DIM + (h << 6) + d];
        u16 hh, ll; split2(v, hh, ll);
        oh[i] = hh; ol[i] = ll;
    }
}

__global__ void headsplit_vT(const float* __restrict__ in, u16* __restrict__ oh, u16* __restrict__ ol) {
    __shared__ float t[32][33];
    int z = blockIdx.z;
    int b = z >> 4, h = z & 15;
    int s0 = blockIdx.x * 32, d0 = blockIdx.y * 32;
    int tx = threadIdx.x & 31, ty = threadIdx.x >> 5;
    #pragma unroll
    for (int dy = 0; dy < 32; dy += 8)
        t[ty + dy][tx] = in[(size_t)((b << 10) + s0 + ty + dy) * DIM + h * 64 + d0 + tx];
    __syncthreads();
    #pragma unroll
    for (int dy = 0; dy < 32; dy += 8) {
        float v = t[tx][ty + dy];
        size_t o = (size_t)(z * 64 + d0 + ty + dy) * 1024 + s0 + tx;
        u16 hh, ll; split2(v, hh, ll);
        oh[o] = hh; ol[o] = ll;
    }
}

__global__ void head_merge_split(const float* __restrict__ in, u16* __restrict__ oh, u16* __restrict__ ol) {
    for (int i = blockIdx.x * blockDim.x + threadIdx.x; i < NTOK * DIM; i += gridDim.x * blockDim.x) {
        int col = i & 1023, h = col >> 6, d = col & 63;
        int s = (i >> 10) & 1023, b = i >> 20;
        float v = in[(size_t)(((b << 4) + h) * 1024 + s) * 64 + d];
        u16 hh, ll; split2(v, hh, ll);
        oh[i] = hh; ol[i] = ll;
    }
}

__global__ void ln_res_split(const float* __restrict__ a, const float* __restrict__ res,
                             const float* __restrict__ g, const float* __restrict__ b,
                             float* __restrict__ of, u16* __restrict__ oh, u16* __restrict__ ol) {
    __shared__ float sm[32];
    const size_t base = (size_t)blockIdx.x * DIM;
    int t = threadIdx.x;
    float v[4];
    float s = 0.f;
    #pragma unroll
    for (int j = 0; j < 4; j++) {
        int c = t + j * 256;
        v[j] = a[base + c] + res[base + c];
        s += v[j];
    }
    s = blk_reduce_sum(s, sm);
    float mean = s * (1.0f / DIM);
    float s2 = 0.f;
    #pragma unroll
    for (int j = 0; j < 4; j++) { float d = v[j] - mean; s2 += d * d; }
    s2 = blk_reduce_sum(s2, sm);
    float rs = rsqrtf(s2 * (1.0f / DIM) + 1e-5f);
    #pragma unroll
    for (int j = 0; j < 4; j++) {
        int c = t + j * 256;
        float o = (v[j] - mean) * rs * g[c] + b[c];
        of[base + c] = o;
        u16 hh, ll; split2(o, hh, ll);
        oh[base + c] = hh; ol[base + c] = ll;
    }
}

__global__ void combine_ln(const float* __restrict__ g, const float* __restrict__ b,
                           float* __restrict__ out) {
    __shared__ float sm[32];
    const int tok = blockIdx.x;
    const size_t base = (size_t)tok * DIM;
    int t = threadIdx.x;
    float v[4];
    #pragma unroll
    for (int j = 0; j < 4; j++) v[j] = g_x[base + t + j * 256];
    const int nl = g_tcnt[tok];
    for (int l = 0; l < nl; l++) {
        int   e    = g_te[tok * 3 + l];
        int   slot = g_tslot[tok * 3 + l];
        float gt   = g_tgate[tok * 3 + l];
        const float* row = g_e2 + ((size_t)e * NTOK + slot) * DIM;
        #pragma unroll
        for (int j = 0; j < 4; j++) v[j] += gt * row[t + j * 256];
    }
    float s = 0.f;
    #pragma unroll
    for (int j = 0; j < 4; j++) s += v[j];
    s = blk_reduce_sum(s, sm);
    float mean = s * (1.0f / DIM);
    float s2 = 0.f;
    #pragma unroll
    for (int j = 0; j < 4; j++) { float d = v[j] - mean; s2 += d * d; }
    s2 = blk_reduce_sum(s2, sm);
    float rs = rsqrtf(s2 * (1.0f / DIM) + 1e-5f);
    #pragma unroll
    for (int j = 0; j < 4; j++) {
        int c = t + j * 256;
        out[base + c] = (v[j] - mean) * rs * g[c] + b[c];
    }
}

__global__ void gating(const float* __restrict__ Wg) {
    __shared__ float logits[NEXP];
    const int tok = blockIdx.x;
    const float* xr = g_x + (size_t)tok * DIM;
    int w = threadIdx.x >> 5, lane = threadIdx.x & 31;
    float s = 0.f;
    for (int i = lane; i < DIM; i += 32) s += xr[i] * Wg[i * NEXP + w];
    #pragma unroll
    for (int o = 16; o; o >>= 1) s += __shfl_down_sync(0xffffffffu, s, o);
    if (!lane) logits[w] = s;
    __syncthreads();
    if (threadIdx.x == 0) {
        float p[NEXP];
        float mx = -1e30f;
        for (int e = 0; e < NEXP; e++) mx = fmaxf(mx, logits[e]);
        float sum = 0.f;
        for (int e = 0; e < NEXP; e++) { p[e] = __expf(logits[e] - mx); sum += p[e]; }
        float inv = 1.f / sum;
        for (int e = 0; e < NEXP; e++) { p[e] *= inv; g_probs[tok * NEXP + e] = p[e]; }
        int i0 = 0;
        for (int e = 1; e < NEXP; e++) if (p[e] > p[i0]) i0 = e;
        int i1 = -1;
        for (int e = 0; e < NEXP; e++) if (e != i0 && (i1 < 0 || p[e] > p[i1])) i1 = e;
        int i2 = -1;
        for (int e = 0; e < NEXP; e++) if (e != i0 && e != i1 && (i2 < 0 || p[e] > p[i2])) i2 = e;
        int   ids[3] = { i0, i1, i2 };
        float gts[3] = { p[i0],
                         (p[i1] >= THRESH) ? p[i1] : 0.f,
                         (p[i2] >= THRESH) ? p[i2] : 0.f };
        int nl = 0;
        #pragma unroll
        for (int j = 0; j < 3; j++) {
            if (gts[j] > 0.f) {
                int slot = atomicAdd(&g_cnt[ids[j]], 1);
                g_tok  [ids[j] * NTOK + slot] = tok;
                g_te   [tok * 3 + nl] = ids[j];
                g_tslot[tok * 3 + nl] = slot;
                g_tgate[tok * 3 + nl] = gts[j];
                nl++;
            }
        }
        g_tcnt[tok] = nl;
    }
}

__global__ void zero_small() {
    int t = threadIdx.x;
    if (t < NEXP) g_cnt[t] = 0;
}
__global__ void aux_kernel(float* __restrict__ out, int out_size) {
    if (out_size <= OUT_MAIN) return;
    __shared__ float sm[32];
    int t = threadIdx.x;
    float total = 0.f;
    for (int e = 0; e < NEXP; e++) {
        float s = 0.f;
        for (int tok = t; tok < NTOK; tok += 256) s += g_probs[tok * NEXP + e];
        s = blk_reduce_sum(s, sm);
        if (t == 0) total += ((float)g_cnt[e] / (float)NTOK) * (s / (float)NTOK);
    }
    if (t == 0) out[OUT_MAIN] = COEF * (float)NEXP * total;
}

// ---------------- host launcher ----------------
#define GETSYM(var, sym) do { cudaGetSymbolAddress((void**)&(var), sym); } while (0)

extern "C" void kernel_launch(void* const* d_in, const int* in_sizes, int n_in,
                              void* d_out, int out_size)
{
    (void)in_sizes; (void)n_in;
    const float* query  = (const float*)d_in[0];
    const float* keyval = (const float*)d_in[1];
    const float* Wq = (const float*)d_in[2];  const float* bq = (const float*)d_in[3];
    const float* Wk = (const float*)d_in[4];  const float* bk = (const float*)d_in[5];
    const float* Wv = (const float*)d_in[6];  const float* bv = (const float*)d_in[7];
    const float* W_in  = (const float*)d_in[8];  const float* b_in  = (const float*)d_in[9];
    const float* W_out = (const float*)d_in[10]; const float* b_out = (const float*)d_in[11];
    const float* Wa = (const float*)d_in[12]; const float* ba = (const float*)d_in[13];
    const float* ln1g = (const float*)d_in[14]; const float* ln1b = (const float*)d_in[15];
    const float* Wg = (const float*)d_in[16];
    const float* ew1 = (const float*)d_in[17]; const float* eb1 = (const float*)d_in[18];
    const float* ew2 = (const float*)d_in[19]; const float* eb2 = (const float*)d_in[20];
    const float* ln2g = (const float*)d_in[21]; const float* ln2b = (const float*)d_in[22];
    float* out = (float*)d_out;

    float *qh, *kh, *vh, *ot, *a, *x, *e2p;
    GETSYM(qh, g_qh); GETSYM(kh, g_kh); GETSYM(vh, g_vh);
    GETSYM(ot, g_ot); GETSYM(a, g_a); GETSYM(x, g_x);
    GETSYM(e2p, g_e2);
    u16 *qyh,*qyl,*kvh,*kvl,*qsh,*qsl,*ksh,*ksl,*vsh,*vsl;
    u16 *qth,*qtl,*kth,*ktl,*vth,*vtl,*oh,*ol,*oph,*opl,*xh,*xl,*hhh,*hhl;
    u16 *wqh,*wql,*wkh,*wkl,*wvh,*wvl,*winh,*winl,*woh,*wol,*wah,*wal,*e1h,*e1l,*e2h,*e2l;
    GETSYM(qyh, s_query_h); GETSYM(qyl, s_query_l);
    GETSYM(kvh, s_kv_h);    GETSYM(kvl, s_kv_l);
    GETSYM(qsh, s_q_h);  GETSYM(qsl, s_q_l);
    GETSYM(ksh, s_k_h);  GETSYM(ksl, s_k_l);
    GETSYM(vsh, s_v_h);  GETSYM(vsl, s_v_l);
    GETSYM(qth, s_qt_h); GETSYM(qtl, s_qt_l);
    GETSYM(kth, s_kt_h); GETSYM(ktl, s_kt_l);
    GETSYM(vth, s_vt_h); GETSYM(vtl, s_vt_l);
    GETSYM(oh,  s_o_h);  GETSYM(ol,  s_o_l);
    GETSYM(oph, s_op_h); GETSYM(opl, s_op_l);
    GETSYM(xh,  s_x_h);  GETSYM(xl,  s_x_l);
    GETSYM(hhh, s_hh);   GETSYM(hhl, s_hl);
    GETSYM(wqh, s_wq_h); GETSYM(wql, s_wq_l);
    GETSYM(wkh, s_wk_h); GETSYM(wkl, s_wk_l);
    GETSYM(wvh, s_wv_h); GETSYM(wvl, s_wv_l);
    GETSYM(winh, s_win_h); GETSYM(winl, s_win_l);
    GETSYM(woh, s_wo_h); GETSYM(wol, s_wo_l);
    GETSYM(wah, s_wa_h); GETSYM(wal, s_wa_l);
    GETSYM(e1h, s_e1_h); GETSYM(e1l, s_e1_l);
    GETSYM(e2h, s_e2_h); GETSYM(e2l, s_e2_l);
    int *tokp; GETSYM(tokp, g_tok);
    int *cntp; GETSYM(cntp, g_cnt);

    const int S256_128 = 2 * 2 * (256 + 128) * RS * 2;   // 221184 B
    const int SFLASH   = (2 * 128 * RS + 2 * 4 * 64 * RS) * 2;  // 110592 B
    cudaFuncSetAttribute((const void*)gemm_tc<256,128,false,false,true ,false>, cudaFuncAttributeMaxDynamicSharedMemorySize, S256_128);
    cudaFuncSetAttribute((const void*)gemm_tc<256,128,false,true ,false,false>, cudaFuncAttributeMaxDynamicSharedMemorySize, S256_128);
    cudaFuncSetAttribute((const void*)gemm_tc<256,128,true ,false,true ,true >, cudaFuncAttributeMaxDynamicSharedMemorySize, S256_128);
    cudaFuncSetAttribute((const void*)flash_attn, cudaFuncAttributeMaxDynamicSharedMemorySize, SFLASH);

    const dim3 T256(256);
    const dim3 GLIN(DIM/128, NTOK/256, 1);   // 8 x 16 = 128 CTAs

    // launches 5 AND 6 are main GEMMs so ncu (-s 5 -c 1) captures one.
    split_f32<<<1024, 256>>>(query,  qyh, qyl, NTOK*DIM);        // 1
    split_f32<<<512, 256>>>(Wq, wqh, wql, DIM*DIM);              // 2
    split_f32<<<1024, 256>>>(keyval, kvh, kvl, NTOK*DIM);        // 3
    split_f32<<<512, 256>>>(Wk, wkh, wkl, DIM*DIM);              // 4
    gemm_tc<256,128,false,false,true,false><<<GLIN, T256, S256_128>>>(   // 5
        qyh, qyl, wqh, wql, DIM, 0, 0, 0, nullptr, nullptr, bq, 0, 1.f, nullptr, qsh, qsl, DIM);
    gemm_tc<256,128,false,false,true,false><<<GLIN, T256, S256_128>>>(   // 6
        kvh, kvl, wkh, wkl, DIM, 0, 0, 0, nullptr, nullptr, bk, 0, 1.f, nullptr, ksh, ksl, DIM);
    split_f32<<<512, 256>>>(Wv, wvh, wvl, DIM*DIM);
    gemm_tc<256,128,false,false,true,false><<<GLIN, T256, S256_128>>>(
        kvh, kvl, wvh, wvl, DIM, 0, 0, 0, nullptr, nullptr, bv, 0, 1.f, nullptr, vsh, vsl, DIM);
    split_f32<<<1024, 256>>>(W_in, winh, winl, 3*DIM*DIM);

    // ---- MHA in-projection (fp32 out) ----
    gemm_tc<256,128,false,true,false,false><<<GLIN, T256, S256_128>>>(
        qsh, qsl, winh,              winl,              DIM, 0, 0, 0, nullptr, nullptr, b_in,        0, 1.f, qh, nullptr, nullptr, DIM);
    gemm_tc<256,128,false,true,false,false><<<GLIN, T256, S256_128>>>(
        ksh, ksl, winh + DIM*DIM,    winl + DIM*DIM,    DIM, 0, 0, 0, nullptr, nullptr, b_in + DIM,  0, 1.f, kh, nullptr, nullptr, DIM);
    gemm_tc<256,128,false,true,false,false><<<GLIN, T256, S256_128>>>(
        vsh, vsl, winh + 2*DIM*DIM,  winl + 2*DIM*DIM,  DIM, 0, 0, 0, nullptr, nullptr, b_in + 2*DIM,0, 1.f, vh, nullptr, nullptr, DIM);

    // ---- head reshape ----
    headsplit_qk<<<512, 256>>>(qh, qth, qtl);
    headsplit_qk<<<512, 256>>>(kh, kth, ktl);
    headsplit_vT<<<dim3(SQL/32, 2, BH), T256>>>(vh, vth, vtl);

    // ---- fused flash attention -> g_ot ----
    flash_attn<<<dim3(SQL/128, BH), T256, SFLASH>>>();

    head_merge_split<<<512, 256>>>(ot, oh, ol);

    // ---- out-projection + adapter ----
    split_f32<<<512, 256>>>(W_out, woh, wol, DIM*DIM);
    gemm_tc<256,128,false,false,true,false><<<GLIN, T256, S256_128>>>(
        oh, ol, woh, wol, DIM, 0, 0, 0, nullptr, nullptr, b_out, 0, 1.f, nullptr, oph, opl, DIM);
    split_f32<<<512, 256>>>(Wa, wah, wal, DIM*DIM);
    gemm_tc<256,128,false,true,false,false><<<GLIN, T256, S256_128>>>(
        oph, opl, wah, wal, DIM, 0, 0, 0, nullptr, nullptr, ba, 0, 1.f, a, nullptr, nullptr, DIM);

    // ---- LN1 (+residual) -> x fp32 + split ----
    ln_res_split<<<NTOK, T256>>>(a, query, ln1g, ln1b, x, xh, xl);

    // ---- gating ----
    zero_small<<<1, 32>>>();
    gating<<<NTOK, T256>>>(Wg);

    // ---- MoE expert weights + FFNs ----
    transpose_split<<<dim3(HDIM/32, DIM/32, NEXP), T256>>>(ew1, e1h, e1l, DIM, HDIM);
    transpose_split<<<dim3(DIM/32, HDIM/32, NEXP), T256>>>(ew2, e2h, e2l, HDIM, DIM);
    gemm_tc<256,128,true,false,true,true><<<dim3(HDIM/128, NTOK/256, NEXP), T256, S256_128>>>(
        xh, xl, e1h, e1l, DIM,
        0, (long long)HDIM*DIM, (long long)NTOK*HDIM,
        tokp, cntp, eb1, HDIM, 1.f, nullptr, hhh, hhl, HDIM);
    gemm_tc<256,128,false,true,false,false><<<dim3(DIM/128, NTOK/256, NEXP), T256, S256_128>>>(
        hhh, hhl, e2h, e2l, HDIM,
        (long long)NTOK*HDIM, (long long)DIM*HDIM, (long long)NTOK*DIM,
        nullptr, cntp, eb2, DIM, 1.f, e2p, nullptr, nullptr, DIM);

    // ---- fused combine + final LN -> output, then aux scalar ----
    combine_ln<<<NTOK, T256>>>(ln2g, ln2b, out);
    aux_kernel<<<1, 256>>>(out, out_size);
}

// round 12
// speedup vs baseline: 2.8609x; 1.0179x over previous
#include <cuda_runtime.h>
#include <cuda_bf16.h>
#include <math.h>
#include <stddef.h>
#include <stdint.h>

// ---------------- problem constants ----------------
#define BATCH 4
#define SQL   1024
#define SKV   1024
#define DIM   1024
#define NH    16
#define DH    64
#define NEXP  8
#define HDIM  4096
#define NTOK  (BATCH*SQL)       // 4096
#define BH    (BATCH*NH)        // 64
#define OUT_MAIN (NTOK*DIM)
#define THRESH 0.05f
#define COEF   0.01f
#define KCH   64                // K chunk
#define RS    72                // smem row stride in u16 (64 data + 8 pad)

typedef unsigned short u16;
typedef unsigned int   u32;

// ---------------- static device scratch (fp32) ----------------
__device__ float g_qh[NTOK*DIM];
__device__ float g_kh[NTOK*DIM];
__device__ float g_vh[NTOK*DIM];
__device__ float g_ot[NTOK*DIM];
__device__ float g_a [NTOK*DIM];
__device__ float g_x [NTOK*DIM];
__device__ float g_e2[(size_t)NEXP*NTOK*DIM];   // 128 MB
__device__ int   g_cnt[NEXP];
__device__ int   g_tok[NEXP*NTOK];
__device__ float g_probs[NTOK*NEXP];
__device__ int   g_tcnt[NTOK];
__device__ int   g_te  [NTOK*3];
__device__ int   g_tslot[NTOK*3];
__device__ float g_tgate[NTOK*3];

// ---------------- bf16 hi/lo split buffers ----------------
__device__ u16 s_query_h[NTOK*DIM], s_query_l[NTOK*DIM];
__device__ u16 s_kv_h[NTOK*DIM],    s_kv_l[NTOK*DIM];
__device__ u16 s_q_h[NTOK*DIM],     s_q_l[NTOK*DIM];
__device__ u16 s_k_h[NTOK*DIM],     s_k_l[NTOK*DIM];
__device__ u16 s_v_h[NTOK*DIM],     s_v_l[NTOK*DIM];
__device__ u16 s_qt_h[NTOK*DIM],    s_qt_l[NTOK*DIM];    // [bh][sq][dh]
__device__ u16 s_kt_h[NTOK*DIM],    s_kt_l[NTOK*DIM];    // [bh][skv][dh]
__device__ u16 s_vt_h[NTOK*DIM],    s_vt_l[NTOK*DIM];    // [bh][dh][skv]
__device__ u16 s_o_h[NTOK*DIM],     s_o_l[NTOK*DIM];
__device__ u16 s_op_h[NTOK*DIM],    s_op_l[NTOK*DIM];
__device__ u16 s_x_h[NTOK*DIM],     s_x_l[NTOK*DIM];
__device__ u16 s_hh [(size_t)NEXP*NTOK*HDIM], s_hl[(size_t)NEXP*NTOK*HDIM];
// weights
__device__ u16 s_wq_h[DIM*DIM],   s_wq_l[DIM*DIM];
__device__ u16 s_wk_h[DIM*DIM],   s_wk_l[DIM*DIM];
__device__ u16 s_wv_h[DIM*DIM],   s_wv_l[DIM*DIM];
__device__ u16 s_win_h[3*DIM*DIM],s_win_l[3*DIM*DIM];
__device__ u16 s_wo_h[DIM*DIM],   s_wo_l[DIM*DIM];
__device__ u16 s_wa_h[DIM*DIM],   s_wa_l[DIM*DIM];
__device__ u16 s_e1_h[(size_t)NEXP*HDIM*DIM], s_e1_l[(size_t)NEXP*HDIM*DIM]; // [e][n=HDIM][k=DIM]
__device__ u16 s_e2_h[(size_t)NEXP*DIM*HDIM], s_e2_l[(size_t)NEXP*DIM*HDIM]; // [e][n=DIM][k=HDIM]

// ---------------- helpers ----------------
__device__ __forceinline__ u16 f2bf(float v) { __nv_bfloat16 b = __float2bfloat16(v); return *(u16*)&b; }
__device__ __forceinline__ float bf2f(u16 u) { __nv_bfloat16 b; *(u16*)&b = u; return __bfloat162float(b); }
__device__ __forceinline__ void split2(float v, u16& h, u16& l) {
    u16 hu = f2bf(v); h = hu; l = f2bf(v - bf2f(hu));
}
__device__ __forceinline__ void split_pack2(float v0, float v1, u32& h, u32& l) {
    u16 h0, l0, h1, l1;
    split2(v0, h0, l0); split2(v1, h1, l1);
    h = (u32)h0 | ((u32)h1 << 16);
    l = (u32)l0 | ((u32)l1 << 16);
}
__device__ __forceinline__ float gelu_exact(float v) {
    return 0.5f * v * (1.0f + erff(v * 0.70710678118654752f));
}
__device__ __forceinline__ u32 smem_u32(const void* p) {
    u32 a;
    asm("{ .reg .u64 t; cvta.to.shared.u64 t, %1; cvt.u32.u64 %0, t; }" : "=r"(a) : "l"(p));
    return a;
}
__device__ __forceinline__ float blk_reduce_sum(float v, float* sm) {
    int lane = threadIdx.x & 31, w = threadIdx.x >> 5;
    #pragma unroll
    for (int o = 16; o; o >>= 1) v += __shfl_down_sync(0xffffffffu, v, o);
    if (!lane) sm[w] = v;
    __syncthreads();
    if (threadIdx.x < 32) {
        v = (threadIdx.x < 8) ? sm[threadIdx.x] : 0.f;
        #pragma unroll
        for (int o = 4; o; o >>= 1) v += __shfl_down_sync(0xffffffffu, v, o);
        if (!threadIdx.x) sm[0] = v;
    }
    __syncthreads();
    float r = sm[0];
    __syncthreads();
    return r;
}

__device__ __forceinline__ void mma_bf16(float* c, const u32* a, const u32* b) {
    asm volatile(
        "mma.sync.aligned.m16n8k16.row.col.f32.bf16.bf16.f32 "
        "{%0,%1,%2,%3}, {%4,%5,%6,%7}, {%8,%9}, {%0,%1,%2,%3};"
        : "+f"(c[0]), "+f"(c[1]), "+f"(c[2]), "+f"(c[3])
        : "r"(a[0]), "r"(a[1]), "r"(a[2]), "r"(a[3]), "r"(b[0]), "r"(b[1]));
}

#define CP16(dst, src) \
    asm volatile("cp.async.cg.shared.global [%0], [%1], 16;" :: "r"(dst), "l"(src) : "memory")
#define CP_COMMIT() asm volatile("cp.async.commit_group;" ::: "memory")
#define CP_WAIT1()  asm volatile("cp.async.wait_group 1;" ::: "memory")
#define CP_WAIT2()  asm volatile("cp.async.wait_group 2;" ::: "memory")
#define LDMX4(r, addr) \
    asm volatile("ldmatrix.sync.aligned.m8n8.x4.shared.b16 {%0,%1,%2,%3}, [%4];" \
        : "=r"((r)[0]), "=r"((r)[1]), "=r"((r)[2]), "=r"((r)[3]) : "r"(addr))

// =====================================================================
// bf16-split tensor-core GEMM. Accumulator-interleaved MMA schedule:
// consecutive MMAs always target different accumulators (same-acc
// reissue distance = 8 issues >= HMMA RAW latency).
// =====================================================================
template<int BM, int BN, bool GELU_, bool WF32, bool WSPLIT, bool GATHER>
__global__ __launch_bounds__(256, 1)
void gemm_tc(const u16* __restrict__ Ah_, const u16* __restrict__ Al_,
             const u16* __restrict__ Bh_, const u16* __restrict__ Bl_,
             int K, long long As, long long Bs, long long Cs,
             const int* __restrict__ rowmap, const int* __restrict__ cntArr,
             const float* __restrict__ bias, long long biasStride, float alpha,
             float* __restrict__ Cf, u16* __restrict__ Ch, u16* __restrict__ Cl, int ldc)
{
    extern __shared__ __align__(16) u16 smem[];
    const int z = blockIdx.z;
    const int cnt = cntArr ? cntArr[z] : 0x40000000;
    const int m0 = blockIdx.y * BM;
    if (m0 >= cnt) return;
    const int n0 = blockIdx.x * BN;

    const u16* Ah = Ah_ + (size_t)z * As;
    const u16* Al = Al_ + (size_t)z * As;
    const u16* Bh = Bh_ + (size_t)z * Bs;
    const u16* Bl = Bl_ + (size_t)z * Bs;
    if (WF32)   Cf += (size_t)z * Cs;
    if (WSPLIT) { Ch += (size_t)z * Cs; Cl += (size_t)z * Cs; }
    const float* bptr = bias ? bias + (size_t)z * biasStride : nullptr;
    const int* rmap = GATHER ? (rowmap + (size_t)z * NTOK) : nullptr;

    constexpr int ASZ = BM * RS;
    constexpr int BSZ = BN * RS;
    constexpr int STG = 2 * ASZ + 2 * BSZ;
    constexpr int WMR = BM / 4;
    constexpr int MI  = WMR / 16;
    constexpr int WN  = BN / 2;
    constexpr int NF  = WN / 8;
    constexpr int AIT = BM / 32;
    constexpr int NBI = BN / 32;

    const int tid = threadIdx.x;
    const int wid = tid >> 5, lane = tid & 31;
    const int wm = wid & 3, wn = wid >> 2;
    const u32 sb = smem_u32(smem);

    u32 aOff[AIT], aDst[AIT];
    #pragma unroll
    for (int it = 0; it < AIT; it++) {
        int idx = tid + it * 256;
        int row = idx >> 3, blk = idx & 7;
        int srow;
        if (GATHER) { int gm = m0 + row; if (gm >= cnt) gm = cnt - 1; srow = rmap[gm]; }
        else srow = m0 + row;
        aOff[it] = (u32)srow * (u32)K + blk * 8;
        aDst[it] = (u32)(row * RS + blk * 8) * 2;
    }
    u32 bOff[NBI], bDst[NBI];
    #pragma unroll
    for (int it = 0; it < NBI; it++) {
        int idx = tid + it * 256;
        int row = idx >> 3, blk = idx & 7;
        bOff[it] = (u32)(n0 + row) * (u32)K + blk * 8;
        bDst[it] = (u32)(2 * ASZ + row * RS + blk * 8) * 2;
    }

    auto load_chunk = [&](int c, int s) {
        const int k0 = c * KCH;
        const u32 base = sb + (u32)(s * STG) * 2;
        #pragma unroll
        for (int it = 0; it < AIT; it++) {
            CP16(base + aDst[it],           Ah + aOff[it] + k0);
            CP16(base + aDst[it] + ASZ * 2, Al + aOff[it] + k0);
        }
        #pragma unroll
        for (int it = 0; it < NBI; it++) {
            CP16(base + bDst[it],           Bh + bOff[it] + k0);
            CP16(base + bDst[it] + BSZ * 2, Bl + bOff[it] + k0);
        }
    };

    const int aRowO = ((lane >> 3) & 1) * 8 + (lane & 7);
    const int aKO   = ((lane >> 4) & 1) * 8;
    const int bRowO = ((lane >> 4) & 1) * 8 + (lane & 7);
    const int bKO   = ((lane >> 3) & 1) * 8;

    float acc[MI][NF][4];
    #pragma unroll
    for (int i = 0; i < MI; i++)
        #pragma unroll
        for (int j = 0; j < NF; j++)
            #pragma unroll
            for (int q = 0; q < 4; q++) acc[i][j][q] = 0.f;

    const int nch = K / KCH;

    load_chunk(0, 0);
    CP_COMMIT();
    if (nch > 1) load_chunk(1, 1);
    CP_COMMIT();

    for (int c = 0; c < nch; c++) {
        CP_WAIT1();
        __syncthreads();

        const u32 stB = sb + (u32)((c & 1) * STG) * 2;
        #pragma unroll
        for (int ks = 0; ks < 4; ks++) {
            u32 ah[MI][4], al[MI][4];
            #pragma unroll
            for (int mi = 0; mi < MI; mi++) {
                u32 ad = stB + (u32)((wm * WMR + mi * 16 + aRowO) * RS + ks * 16 + aKO) * 2;
                LDMX4(ah[mi], ad);
                LDMX4(al[mi], ad + ASZ * 2);
            }
            #pragma unroll
            for (int j = 0; j < NF / 2; j++) {
                u32 bd = stB + (u32)(2 * ASZ + (wn * WN + j * 16 + bRowO) * RS + ks * 16 + bKO) * 2;
                u32 th[4], tl[4];
                LDMX4(th, bd);
                LDMX4(tl, bd + BSZ * 2);
                u32 b0h[2] = { th[0], th[1] }, b1h[2] = { th[2], th[3] };
                u32 b0l[2] = { tl[0], tl[1] }, b1l[2] = { tl[2], tl[3] };
                // accumulator-interleaved: same-acc distance = 2*MI issues
                #pragma unroll
                for (int mi = 0; mi < MI; mi++) {
                    mma_bf16(acc[mi][2*j],   ah[mi], b0h);
                    mma_bf16(acc[mi][2*j+1], ah[mi], b1h);
                }
                #pragma unroll
                for (int mi = 0; mi < MI; mi++) {
                    mma_bf16(acc[mi][2*j],   al[mi], b0h);
                    mma_bf16(acc[mi][2*j+1], al[mi], b1h);
                }
                #pragma unroll
                for (int mi = 0; mi < MI; mi++) {
                    mma_bf16(acc[mi][2*j],   ah[mi], b0l);
                    mma_bf16(acc[mi][2*j+1], ah[mi], b1l);
                }
            }
        }
        __syncthreads();
        if (c + 2 < nch) load_chunk(c + 2, c & 1);
        CP_COMMIT();
    }

    const int gid = lane >> 2, tg = lane & 3;
    #pragma unroll
    for (int mi = 0; mi < MI; mi++) {
        #pragma unroll
        for (int nf = 0; nf < NF; nf++) {
            int mA  = m0 + wm * WMR + mi * 16 + gid;
            int col = n0 + wn * WN + nf * 8 + tg * 2;
            #pragma unroll
            for (int half = 0; half < 2; half++) {
                int m = mA + half * 8;
                if (m < cnt) {
                    float v0 = acc[mi][nf][half * 2 + 0] * alpha;
                    float v1 = acc[mi][nf][half * 2 + 1] * alpha;
                    if (bptr) { v0 += bptr[col]; v1 += bptr[col + 1]; }
                    if (GELU_) { v0 = gelu_exact(v0); v1 = gelu_exact(v1); }
                    size_t o = (size_t)m * ldc + col;
                    if (WF32) { Cf[o] = v0; Cf[o + 1] = v1; }
                    if (WSPLIT) {
                        u16 h0, l0, h1, l1;
                        split2(v0, h0, l0); split2(v1, h1, l1);
                        Ch[o] = h0; Ch[o + 1] = h1;
                        Cl[o] = l0; Cl[o + 1] = l1;
                    }
                }
            }
        }
    }
}

// =====================================================================
// Flash attention (accumulator-interleaved MMA schedules)
// =====================================================================
__global__ __launch_bounds__(256, 1)
void flash_attn()
{
    extern __shared__ __align__(16) u16 smem[];
    const int z  = blockIdx.y;
    const int q0 = blockIdx.x * 128;
    const int tid = threadIdx.x, wid = tid >> 5, lane = tid & 31;
    const u32 sb = smem_u32(smem);

    constexpr int QSZ = 128 * RS;
    constexpr int KSZ = 64 * RS;
    constexpr int STG = 4 * KSZ;
    const u32 kvB = 2 * QSZ;

    #pragma unroll
    for (int j = 0; j < 4; j++) {
        int idx = tid + j * 256;
        int row = idx >> 3, blk = idx & 7;
        size_t src = ((size_t)(z * 1024 + q0 + row)) * 64 + blk * 8;
        u32 dst = sb + (u32)(row * RS + blk * 8) * 2;
        CP16(dst,           s_qt_h + src);
        CP16(dst + QSZ * 2, s_qt_l + src);
    }
    CP_COMMIT();

    auto load_kv = [&](int c, int s) {
        const int kv0 = c * 64;
        const u32 base = sb + (kvB + (u32)s * STG) * 2;
        #pragma unroll
        for (int j = 0; j < 2; j++) {
            int idx = tid + j * 256;
            int row = idx >> 3, blk = idx & 7;
            size_t ksrc = ((size_t)(z * 1024 + kv0 + row)) * 64 + blk * 8;
            size_t vsrc = ((size_t)(z * 64 + row)) * 1024 + kv0 + blk * 8;
            u32 d = (u32)(row * RS + blk * 8) * 2;
            CP16(base + d,               s_kt_h + ksrc);
            CP16(base + d + KSZ * 2,     s_kt_l + ksrc);
            CP16(base + d + 2 * KSZ * 2, s_vt_h + vsrc);
            CP16(base + d + 3 * KSZ * 2, s_vt_l + vsrc);
        }
    };

    load_kv(0, 0); CP_COMMIT();
    load_kv(1, 1); CP_COMMIT();

    const int aRowO = ((lane >> 3) & 1) * 8 + (lane & 7);
    const int aKO   = ((lane >> 4) & 1) * 8;
    const int bRowO = ((lane >> 4) & 1) * 8 + (lane & 7);
    const int bKO   = ((lane >> 3) & 1) * 8;

    CP_WAIT2();
    __syncthreads();
    u32 qhf[4][4], qlf[4][4];
    #pragma unroll
    for (int ks = 0; ks < 4; ks++) {
        u32 ad = sb + (u32)((wid * 16 + aRowO) * RS + ks * 16 + aKO) * 2;
        LDMX4(qhf[ks], ad);
        LDMX4(qlf[ks], ad + QSZ * 2);
    }

    float of[8][4];
    #pragma unroll
    for (int n = 0; n < 8; n++)
        #pragma unroll
        for (int q = 0; q < 4; q++) of[n][q] = 0.f;
    float m0 = -1e30f, m1 = -1e30f, l0 = 0.f, l1 = 0.f;

    for (int c = 0; c < 16; c++) {
        CP_WAIT1();
        __syncthreads();
        const u32 stB = sb + (kvB + (u32)((c & 1) * STG)) * 2;

        // ---- S = Q K^T, interleaved across 8 accumulators ----
        float sacc[8][4];
        #pragma unroll
        for (int n = 0; n < 8; n++)
            #pragma unroll
            for (int q = 0; q < 4; q++) sacc[n][q] = 0.f;

        #pragma unroll
        for (int ks = 0; ks < 4; ks++) {
            u32 b0h[4][2], b1h[4][2], b0l[4][2], b1l[4][2];
            #pragma unroll
            for (int j = 0; j < 4; j++) {
                u32 bd = stB + (u32)((j * 16 + bRowO) * RS + ks * 16 + bKO) * 2;
                u32 th[4], tl[4];
                LDMX4(th, bd);
                LDMX4(tl, bd + KSZ * 2);
                b0h[j][0] = th[0]; b0h[j][1] = th[1];
                b1h[j][0] = th[2]; b1h[j][1] = th[3];
                b0l[j][0] = tl[0]; b0l[j][1] = tl[1];
                b1l[j][0] = tl[2]; b1l[j][1] = tl[3];
            }
            #pragma unroll
            for (int j = 0; j < 4; j++) {
                mma_bf16(sacc[2*j],   qhf[ks], b0h[j]);
                mma_bf16(sacc[2*j+1], qhf[ks], b1h[j]);
            }
            #pragma unroll
            for (int j = 0; j < 4; j++) {
                mma_bf16(sacc[2*j],   qlf[ks], b0h[j]);
                mma_bf16(sacc[2*j+1], qlf[ks], b1h[j]);
            }
            #pragma unroll
            for (int j = 0; j < 4; j++) {
                mma_bf16(sacc[2*j],   qhf[ks], b0l[j]);
                mma_bf16(sacc[2*j+1], qhf[ks], b1l[j]);
            }
        }

        // ---- online softmax ----
        float mx0 = -1e30f, mx1 = -1e30f;
        #pragma unroll
        for (int n = 0; n < 8; n++) {
            #pragma unroll
            for (int q = 0; q < 4; q++) sacc[n][q] *= 0.125f;
            mx0 = fmaxf(mx0, fmaxf(sacc[n][0], sacc[n][1]));
            mx1 = fmaxf(mx1, fmaxf(sacc[n][2], sacc[n][3]));
        }
        mx0 = fmaxf(mx0, __shfl_xor_sync(0xffffffffu, mx0, 1));
        mx0 = fmaxf(mx0, __shfl_xor_sync(0xffffffffu, mx0, 2));
        mx1 = fmaxf(mx1, __shfl_xor_sync(0xffffffffu, mx1, 1));
        mx1 = fmaxf(mx1, __shfl_xor_sync(0xffffffffu, mx1, 2));
        float mn0 = fmaxf(m0, mx0), mn1 = fmaxf(m1, mx1);
        float sc0 = __expf(m0 - mn0), sc1 = __expf(m1 - mn1);
        m0 = mn0; m1 = mn1;
        float ps0 = 0.f, ps1 = 0.f;
        #pragma unroll
        for (int n = 0; n < 8; n++) {
            sacc[n][0] = __expf(sacc[n][0] - mn0);
            sacc[n][1] = __expf(sacc[n][1] - mn0);
            sacc[n][2] = __expf(sacc[n][2] - mn1);
            sacc[n][3] = __expf(sacc[n][3] - mn1);
            ps0 += sacc[n][0] + sacc[n][1];
            ps1 += sacc[n][2] + sacc[n][3];
        }
        ps0 += __shfl_xor_sync(0xffffffffu, ps0, 1);
        ps0 += __shfl_xor_sync(0xffffffffu, ps0, 2);
        ps1 += __shfl_xor_sync(0xffffffffu, ps1, 1);
        ps1 += __shfl_xor_sync(0xffffffffu, ps1, 2);
        l0 = l0 * sc0 + ps0;
        l1 = l1 * sc1 + ps1;
        #pragma unroll
        for (int n = 0; n < 8; n++) {
            of[n][0] *= sc0; of[n][1] *= sc0;
            of[n][2] *= sc1; of[n][3] *= sc1;
        }

        // ---- O += P V, interleaved across 8 accumulators ----
        #pragma unroll
        for (int kk = 0; kk < 4; kk++) {
            u32 ph[4], pl[4];
            split_pack2(sacc[2*kk][0],   sacc[2*kk][1],   ph[0], pl[0]);
            split_pack2(sacc[2*kk][2],   sacc[2*kk][3],   ph[1], pl[1]);
            split_pack2(sacc[2*kk+1][0], sacc[2*kk+1][1], ph[2], pl[2]);
            split_pack2(sacc[2*kk+1][2], sacc[2*kk+1][3], ph[3], pl[3]);
            u32 b0h[4][2], b1h[4][2], b0l[4][2], b1l[4][2];
            #pragma unroll
            for (int j2 = 0; j2 < 4; j2++) {
                u32 vd = stB + (u32)(2 * KSZ) * 2
                       + (u32)((j2 * 16 + bRowO) * RS + kk * 16 + bKO) * 2;
                u32 th[4], tl[4];
                LDMX4(th, vd);
                LDMX4(tl, vd + KSZ * 2);
                b0h[j2][0] = th[0]; b0h[j2][1] = th[1];
                b1h[j2][0] = th[2]; b1h[j2][1] = th[3];
                b0l[j2][0] = tl[0]; b0l[j2][1] = tl[1];
                b1l[j2][0] = tl[2]; b1l[j2][1] = tl[3];
            }
            #pragma unroll
            for (int j2 = 0; j2 < 4; j2++) {
                mma_bf16(of[2*j2],   ph, b0h[j2]);
                mma_bf16(of[2*j2+1], ph, b1h[j2]);
            }
            #pragma unroll
            for (int j2 = 0; j2 < 4; j2++) {
                mma_bf16(of[2*j2],   pl, b0h[j2]);
                mma_bf16(of[2*j2+1], pl, b1h[j2]);
            }
            #pragma unroll
            for (int j2 = 0; j2 < 4; j2++) {
                mma_bf16(of[2*j2],   ph, b0l[j2]);
                mma_bf16(of[2*j2+1], ph, b1l[j2]);
            }
        }
        __syncthreads();
        if (c + 2 < 16) load_kv(c + 2, c & 1);
        CP_COMMIT();
    }

    const int gid = lane >> 2, tg = lane & 3;
    float inv0 = 1.f / l0, inv1 = 1.f / l1;
    int qr = q0 + wid * 16 + gid;
    #pragma unroll
    for (int n = 0; n < 8; n++) {
        int dh = n * 8 + tg * 2;
        float2 v0 = make_float2(of[n][0] * inv0, of[n][1] * inv0);
        float2 v1 = make_float2(of[n][2] * inv1, of[n][3] * inv1);
        *(float2*)&g_ot[((size_t)(z * 1024 + qr)) * 64 + dh]     = v0;
        *(float2*)&g_ot[((size_t)(z * 1024 + qr + 8)) * 64 + dh] = v1;
    }
}

// ---------------- fused conversion: split all inputs/weights in ONE launch ----------------
struct SplitSegs {
    const float4* s[8];
    uint2* h[8];
    uint2* l[8];
    int end4[8];      // cumulative (in float4 units)
};
__global__ void split_all(SplitSegs g) {
    const int total = g.end4[7];
    for (int i = blockIdx.x * blockDim.x + threadIdx.x; i < total; i += gridDim.x * blockDim.x) {
        int k = 0;
        #pragma unroll
        for (int t = 0; t < 7; t++) k += (i >= g.end4[t]) ? 1 : 0;
        int j = i - (k ? g.end4[k - 1] : 0);
        float4 v = g.s[k][j];
        u16 hh[4], ll[4];
        split2(v.x, hh[0], ll[0]); split2(v.y, hh[1], ll[1]);
        split2(v.z, hh[2], ll[2]); split2(v.w, hh[3], ll[3]);
        g.h[k][j] = *(uint2*)hh;
        g.l[k][j] = *(uint2*)ll;
    }
}

__global__ void transpose_split(const float* __restrict__ s, u16* __restrict__ oh, u16* __restrict__ ol,
                                int R, int C) {
    __shared__ float t[32][33];
    size_t zo = (size_t)blockIdx.z * R * C;
    const float* src = s + zo;
    int c0 = blockIdx.x * 32, r0 = blockIdx.y * 32;
    int tx = threadIdx.x & 31, ty = threadIdx.x >> 5;
    #pragma unroll
    for (int dy = 0; dy < 32; dy += 8)
        t[ty + dy][tx] = src[(size_t)(r0 + ty + dy) * C + c0 + tx];
    __syncthreads();
    #pragma unroll
    for (int dy = 0; dy < 32; dy += 8) {
        float v = t[tx][ty + dy];
        size_t o = zo + (size_t)(c0 + ty + dy) * R + r0 + tx;
        u16 hh, ll; split2(v, hh, ll);
        oh[o] = hh; ol[o] = ll;
    }
}

__global__ void headsplit_qk(const float* __restrict__ in, u16* __restrict__ oh, u16* __restrict__ ol) {
    for (int i = blockIdx.x * blockDim.x + threadIdx.x; i < NTOK * DIM; i += gridDim.x * blockDim.x) {
        int d = i & 63, s = (i >> 6) & 1023, h = (i >> 16) & 15, b = i >> 20;
        float v = in[(size_t)((b << 10) + s) * DIM + (h << 6) + d];
        u16 hh, ll; split2(v, hh, ll);
        oh[i] = hh; ol[i] = ll;
    }
}

__global__ void headsplit_vT(const float* __restrict__ in, u16* __restrict__ oh, u16* __restrict__ ol) {
    __shared__ float t[32][33];
    int z = blockIdx.z;
    int b = z >> 4, h = z & 15;
    int s0 = blockIdx.x * 32, d0 = blockIdx.y * 32;
    int tx = threadIdx.x & 31, ty = threadIdx.x >> 5;
    #pragma unroll
    for (int dy = 0; dy < 32; dy += 8)
        t[ty + dy][tx] = in[(size_t)((b << 10) + s0 + ty + dy) * DIM + h * 64 + d0 + tx];
    __syncthreads();
    #pragma unroll
    for (int dy = 0; dy < 32; dy += 8) {
        float v = t[tx][ty + dy];
        size_t o = (size_t)(z * 64 + d0 + ty + dy) * 1024 + s0 + tx;
        u16 hh, ll; split2(v, hh, ll);
        oh[o] = hh; ol[o] = ll;
    }
}

__global__ void head_merge_split(const float* __restrict__ in, u16* __restrict__ oh, u16* __restrict__ ol) {
    for (int i = blockIdx.x * blockDim.x + threadIdx.x; i < NTOK * DIM; i += gridDim.x * blockDim.x) {
        int col = i & 1023, h = col >> 6, d = col & 63;
        int s = (i >> 10) & 1023, b = i >> 20;
        float v = in[(size_t)(((b << 4) + h) * 1024 + s) * 64 + d];
        u16 hh, ll; split2(v, hh, ll);
        oh[i] = hh; ol[i] = ll;
    }
}

__global__ void ln_res_split(const float* __restrict__ a, const float* __restrict__ res,
                             const float* __restrict__ g, const float* __restrict__ b,
                             float* __restrict__ of, u16* __restrict__ oh, u16* __restrict__ ol) {
    __shared__ float sm[32];
    const size_t base = (size_t)blockIdx.x * DIM;
    int t = threadIdx.x;
    float v[4];
    float s = 0.f;
    #pragma unroll
    for (int j = 0; j < 4; j++) {
        int c = t + j * 256;
        v[j] = a[base + c] + res[base + c];
        s += v[j];
    }
    s = blk_reduce_sum(s, sm);
    float mean = s * (1.0f / DIM);
    float s2 = 0.f;
    #pragma unroll
    for (int j = 0; j < 4; j++) { float d = v[j] - mean; s2 += d * d; }
    s2 = blk_reduce_sum(s2, sm);
    float rs = rsqrtf(s2 * (1.0f / DIM) + 1e-5f);
    #pragma unroll
    for (int j = 0; j < 4; j++) {
        int c = t + j * 256;
        float o = (v[j] - mean) * rs * g[c] + b[c];
        of[base + c] = o;
        u16 hh, ll; split2(o, hh, ll);
        oh[base + c] = hh; ol[base + c] = ll;
    }
}

__global__ void combine_ln(const float* __restrict__ g, const float* __restrict__ b,
                           float* __restrict__ out) {
    __shared__ float sm[32];
    const int tok = blockIdx.x;
    const size_t base = (size_t)tok * DIM;
    int t = threadIdx.x;
    float v[4];
    #pragma unroll
    for (int j = 0; j < 4; j++) v[j] = g_x[base + t + j * 256];
    const int nl = g_tcnt[tok];
    for (int l = 0; l < nl; l++) {
        int   e    = g_te[tok * 3 + l];
        int   slot = g_tslot[tok * 3 + l];
        float gt   = g_tgate[tok * 3 + l];
        const float* row = g_e2 + ((size_t)e * NTOK + slot) * DIM;
        #pragma unroll
        for (int j = 0; j < 4; j++) v[j] += gt * row[t + j * 256];
    }
    float s = 0.f;
    #pragma unroll
    for (int j = 0; j < 4; j++) s += v[j];
    s = blk_reduce_sum(s, sm);
    float mean = s * (1.0f / DIM);
    float s2 = 0.f;
    #pragma unroll
    for (int j = 0; j < 4; j++) { float d = v[j] - mean; s2 += d * d; }
    s2 = blk_reduce_sum(s2, sm);
    float rs = rsqrtf(s2 * (1.0f / DIM) + 1e-5f);
    #pragma unroll
    for (int j = 0; j < 4; j++) {
        int c = t + j * 256;
        out[base + c] = (v[j] - mean) * rs * g[c] + b[c];
    }
}

__global__ void gating(const float* __restrict__ Wg) {
    __shared__ float logits[NEXP];
    const int tok = blockIdx.x;
    const float* xr = g_x + (size_t)tok * DIM;
    int w = threadIdx.x >> 5, lane = threadIdx.x & 31;
    float s = 0.f;
    for (int i = lane; i < DIM; i += 32) s += xr[i] * Wg[i * NEXP + w];
    #pragma unroll
    for (int o = 16; o; o >>= 1) s += __shfl_down_sync(0xffffffffu, s, o);
    if (!lane) logits[w] = s;
    __syncthreads();
    if (threadIdx.x == 0) {
        float p[NEXP];
        float mx = -1e30f;
        for (int e = 0; e < NEXP; e++) mx = fmaxf(mx, logits[e]);
        float sum = 0.f;
        for (int e = 0; e < NEXP; e++) { p[e] = __expf(logits[e] - mx); sum += p[e]; }
        float inv = 1.f / sum;
        for (int e = 0; e < NEXP; e++) { p[e] *= inv; g_probs[tok * NEXP + e] = p[e]; }
        int i0 = 0;
        for (int e = 1; e < NEXP; e++) if (p[e] > p[i0]) i0 = e;
        int i1 = -1;
        for (int e = 0; e < NEXP; e++) if (e != i0 && (i1 < 0 || p[e] > p[i1])) i1 = e;
        int i2 = -1;
        for (int e = 0; e < NEXP; e++) if (e != i0 && e != i1 && (i2 < 0 || p[e] > p[i2])) i2 = e;
        int   ids[3] = { i0, i1, i2 };
        float gts[3] = { p[i0],
                         (p[i1] >= THRESH) ? p[i1] : 0.f,
                         (p[i2] >= THRESH) ? p[i2] : 0.f };
        int nl = 0;
        #pragma unroll
        for (int j = 0; j < 3; j++) {
            if (gts[j] > 0.f) {
                int slot = atomicAdd(&g_cnt[ids[j]], 1);
                g_tok  [ids[j] * NTOK + slot] = tok;
                g_te   [tok * 3 + nl] = ids[j];
                g_tslot[tok * 3 + nl] = slot;
                g_tgate[tok * 3 + nl] = gts[j];
                nl++;
            }
        }
        g_tcnt[tok] = nl;
    }
}

__global__ void zero_small() {
    int t = threadIdx.x;
    if (t < NEXP) g_cnt[t] = 0;
}
__global__ void aux_kernel(float* __restrict__ out, int out_size) {
    if (out_size <= OUT_MAIN) return;
    __shared__ float sm[32];
    int t = threadIdx.x;
    float total = 0.f;
    for (int e = 0; e < NEXP; e++) {
        float s = 0.f;
        for (int tok = t; tok < NTOK; tok += 256) s += g_probs[tok * NEXP + e];
        s = blk_reduce_sum(s, sm);
        if (t == 0) total += ((float)g_cnt[e] / (float)NTOK) * (s / (float)NTOK);
    }
    if (t == 0) out[OUT_MAIN] = COEF * (float)NEXP * total;
}

// ---------------- host launcher ----------------
#define GETSYM(var, sym) do { cudaGetSymbolAddress((void**)&(var), sym); } while (0)

extern "C" void kernel_launch(void* const* d_in, const int* in_sizes, int n_in,
                              void* d_out, int out_size)
{
    (void)in_sizes; (void)n_in;
    const float* query  = (const float*)d_in[0];
    const float* keyval = (const float*)d_in[1];
    const float* Wq = (const float*)d_in[2];  const float* bq = (const float*)d_in[3];
    const float* Wk = (const float*)d_in[4];  const float* bk = (const float*)d_in[5];
    const float* Wv = (const float*)d_in[6];  const float* bv = (const float*)d_in[7];
    const float* W_in  = (const float*)d_in[8];  const float* b_in  = (const float*)d_in[9];
    const float* W_out = (const float*)d_in[10]; const float* b_out = (const float*)d_in[11];
    const float* Wa = (const float*)d_in[12]; const float* ba = (const float*)d_in[13];
    const float* ln1g = (const float*)d_in[14]; const float* ln1b = (const float*)d_in[15];
    const float* Wg = (const float*)d_in[16];
    const float* ew1 = (const float*)d_in[17]; const float* eb1 = (const float*)d_in[18];
    const float* ew2 = (const float*)d_in[19]; const float* eb2 = (const float*)d_in[20];
    const float* ln2g = (const float*)d_in[21]; const float* ln2b = (const float*)d_in[22];
    float* out = (float*)d_out;

    float *qh, *kh, *vh, *ot, *a, *x, *e2p;
    GETSYM(qh, g_qh); GETSYM(kh, g_kh); GETSYM(vh, g_vh);
    GETSYM(ot, g_ot); GETSYM(a, g_a); GETSYM(x, g_x);
    GETSYM(e2p, g_e2);
    u16 *qyh,*qyl,*kvh,*kvl,*qsh,*qsl,*ksh,*ksl,*vsh,*vsl;
    u16 *qth,*qtl,*kth,*ktl,*vth,*vtl,*oh,*ol,*oph,*opl,*xh,*xl,*hhh,*hhl;
    u16 *wqh,*wql,*wkh,*wkl,*wvh,*wvl,*winh,*winl,*woh,*wol,*wah,*wal,*e1h,*e1l,*e2h,*e2l;
    GETSYM(qyh, s_query_h); GETSYM(qyl, s_query_l);
    GETSYM(kvh, s_kv_h);    GETSYM(kvl, s_kv_l);
    GETSYM(qsh, s_q_h);  GETSYM(qsl, s_q_l);
    GETSYM(ksh, s_k_h);  GETSYM(ksl, s_k_l);
    GETSYM(vsh, s_v_h);  GETSYM(vsl, s_v_l);
    GETSYM(qth, s_qt_h); GETSYM(qtl, s_qt_l);
    GETSYM(kth, s_kt_h); GETSYM(ktl, s_kt_l);
    GETSYM(vth, s_vt_h); GETSYM(vtl, s_vt_l);
    GETSYM(oh,  s_o_h);  GETSYM(ol,  s_o_l);
    GETSYM(oph, s_op_h); GETSYM(opl, s_op_l);
    GETSYM(xh,  s_x_h);  GETSYM(xl,  s_x_l);
    GETSYM(hhh, s_hh);   GETSYM(hhl, s_hl);
    GETSYM(wqh, s_wq_h); GETSYM(wql, s_wq_l);
    GETSYM(wkh, s_wk_h); GETSYM(wkl, s_wk_l);
    GETSYM(wvh, s_wv_h); GETSYM(wvl, s_wv_l);
    GETSYM(winh, s_win_h); GETSYM(winl, s_win_l);
    GETSYM(woh, s_wo_h); GETSYM(wol, s_wo_l);
    GETSYM(wah, s_wa_h); GETSYM(wal, s_wa_l);
    GETSYM(e1h, s_e1_h); GETSYM(e1l, s_e1_l);
    GETSYM(e2h, s_e2_h); GETSYM(e2l, s_e2_l);
    int *tokp; GETSYM(tokp, g_tok);
    int *cntp; GETSYM(cntp, g_cnt);

    const int S256_128 = 2 * 2 * (256 + 128) * RS * 2;          // 221184 B
    const int SFLASH   = (2 * 128 * RS + 2 * 4 * 64 * RS) * 2;  // 110592 B
    cudaFuncSetAttribute((const void*)gemm_tc<256,128,false,false,true ,false>, cudaFuncAttributeMaxDynamicSharedMemorySize, S256_128);
    cudaFuncSetAttribute((const void*)gemm_tc<256,128,false,true ,false,false>, cudaFuncAttributeMaxDynamicSharedMemorySize, S256_128);
    cudaFuncSetAttribute((const void*)gemm_tc<256,128,true ,false,true ,true >, cudaFuncAttributeMaxDynamicSharedMemorySize, S256_128);
    cudaFuncSetAttribute((const void*)flash_attn, cudaFuncAttributeMaxDynamicSharedMemorySize, SFLASH);

    const dim3 T256(256);
    const dim3 GLIN(DIM/128, NTOK/256, 1);

    // ---- ONE fused split for all fp32->bf16hi/lo conversions ----
    SplitSegs sg;
    const float* srcs[8] = { query, keyval, Wq, Wk, Wv, W_in, W_out, Wa };
    u16* dh[8] = { qyh, kvh, wqh, wkh, wvh, winh, woh, wah };
    u16* dl[8] = { qyl, kvl, wql, wkl, wvl, winl, wol, wal };
    int  ns[8] = { NTOK*DIM, NTOK*DIM, DIM*DIM, DIM*DIM, DIM*DIM, 3*DIM*DIM, DIM*DIM, DIM*DIM };
    int cum = 0;
    for (int i = 0; i < 8; i++) {
        sg.s[i] = (const float4*)srcs[i];
        sg.h[i] = (uint2*)dh[i];
        sg.l[i] = (uint2*)dl[i];
        cum += ns[i] / 4;
        sg.end4[i] = cum;
    }

    // launch 1: all conversions; launches 2..7: GEMMs (ncu capture lands on a GEMM)
    split_all<<<2048, 256>>>(sg);
    gemm_tc<256,128,false,false,true,false><<<GLIN, T256, S256_128>>>(
        qyh, qyl, wqh, wql, DIM, 0, 0, 0, nullptr, nullptr, bq, 0, 1.f, nullptr, qsh, qsl, DIM);
    gemm_tc<256,128,false,false,true,false><<<GLIN, T256, S256_128>>>(
        kvh, kvl, wkh, wkl, DIM, 0, 0, 0, nullptr, nullptr, bk, 0, 1.f, nullptr, ksh, ksl, DIM);
    gemm_tc<256,128,false,false,true,false><<<GLIN, T256, S256_128>>>(
        kvh, kvl, wvh, wvl, DIM, 0, 0, 0, nullptr, nullptr, bv, 0, 1.f, nullptr, vsh, vsl, DIM);
    gemm_tc<256,128,false,true,false,false><<<GLIN, T256, S256_128>>>(
        qsh, qsl, winh,              winl,              DIM, 0, 0, 0, nullptr, nullptr, b_in,        0, 1.f, qh, nullptr, nullptr, DIM);
    gemm_tc<256,128,false,true,false,false><<<GLIN, T256, S256_128>>>(
        ksh, ksl, winh + DIM*DIM,    winl + DIM*DIM,    DIM, 0, 0, 0, nullptr, nullptr, b_in + DIM,  0, 1.f, kh, nullptr, nullptr, DIM);
    gemm_tc<256,128,false,true,false,false><<<GLIN, T256, S256_128>>>(
        vsh, vsl, winh + 2*DIM*DIM,  winl + 2*DIM*DIM,  DIM, 0, 0, 0, nullptr, nullptr, b_in + 2*DIM,0, 1.f, vh, nullptr, nullptr, DIM);

    // ---- head reshape ----
    headsplit_qk<<<512, 256>>>(qh, qth, qtl);
    headsplit_qk<<<512, 256>>>(kh, kth, ktl);
    headsplit_vT<<<dim3(SQL/32, 2, BH), T256>>>(vh, vth, vtl);

    // ---- fused flash attention -> g_ot ----
    flash_attn<<<dim3(SQL/128, BH), T256, SFLASH>>>();

    head_merge_split<<<512, 256>>>(ot, oh, ol);

    // ---- out-projection + adapter ----
    gemm_tc<256,128,false,false,true,false><<<GLIN, T256, S256_128>>>(
        oh, ol, woh, wol, DIM, 0, 0, 0, nullptr, nullptr, b_out, 0, 1.f, nullptr, oph, opl, DIM);
    gemm_tc<256,128,false,true,false,false><<<GLIN, T256, S256_128>>>(
        oph, opl, wah, wal, DIM, 0, 0, 0, nullptr, nullptr, ba, 0, 1.f, a, nullptr, nullptr, DIM);

    // ---- LN1 (+residual) -> x fp32 + split ----
    ln_res_split<<<NTOK, T256>>>(a, query, ln1g, ln1b, x, xh, xl);

    // ---- gating ----
    zero_small<<<1, 32>>>();
    gating<<<NTOK, T256>>>(Wg);

    // ---- MoE expert weights + FFNs ----
    transpose_split<<<dim3(HDIM/32, DIM/32, NEXP), T256>>>(ew1, e1h, e1l, DIM, HDIM);
    transpose_split<<<dim3(DIM/32, HDIM/32, NEXP), T256>>>(ew2, e2h, e2l, HDIM, DIM);
    gemm_tc<256,128,true,false,true,true><<<dim3(HDIM/128, NTOK/256, NEXP), T256, S256_128>>>(
        xh, xl, e1h, e1l, DIM,
        0, (long long)HDIM*DIM, (long long)NTOK*HDIM,
        tokp, cntp, eb1, HDIM, 1.f, nullptr, hhh, hhl, HDIM);
    gemm_tc<256,128,false,true,false,false><<<dim3(DIM/128, NTOK/256, NEXP), T256, S256_128>>>(
        hhh, hhl, e2h, e2l, HDIM,
        (long long)NTOK*HDIM, (long long)DIM*HDIM, (long long)NTOK*DIM,
        nullptr, cntp, eb2, DIM, 1.f, e2p, nullptr, nullptr, DIM);

    // ---- fused combine + final LN -> output, then aux scalar ----
    combine_ln<<<NTOK, T256>>>(ln2g, ln2b, out);
    aux_kernel<<<1, 256>>>(out, out_size);
}